// round 8
// baseline (speedup 1.0000x reference)
#include <cuda_runtime.h>
#include <cuda_bf16.h>
#include <math.h>
#include <stdint.h>

// ---------------- problem constants ----------------
#define Bz 2
#define Dz 8
#define Cz 256
#define Wz 84
#define Hz 84
#define HEADS 8
#define HD 32
#define NT 98            // tokens per window (2*7*7)
#define NTP 112          // padded to 7 x 16
#define NW 576           // windows per batch (4*12*12)
#define BW (Bz*NW)       // 1152 window-batches
#define TOK (BW*NT)      // 112896 tokens
#define HID 1024

// ---------------- scratch (device globals; allocation-free) ----------------
__device__ __align__(256) float g_xp  [(size_t)TOK*Cz];   // shortcut (B,D,H,W,C)
__device__ __align__(256) float g_po  [(size_t)TOK*Cz];   // proj output (windowed order)
__device__ __align__(256) float g_xres[(size_t)TOK*Cz];   // (B,D,H,W,C)
__device__ __align__(256) float g_y   [(size_t)TOK*Cz];
__device__ __align__(256) float g_bias[8 * HEADS * NTP * NTP];  // [cls][head][r][c]
// split bf16 activation planes
__device__ __align__(256) __nv_bfloat16 g_xwh[(size_t)TOK*Cz],   g_xwl[(size_t)TOK*Cz];
__device__ __align__(256) __nv_bfloat16 g_qkvh[(size_t)TOK*3*Cz], g_qkvl[(size_t)TOK*3*Cz];
__device__ __align__(256) __nv_bfloat16 g_aoh[(size_t)TOK*Cz];
__device__ __align__(256) __nv_bfloat16 g_l2h[(size_t)TOK*Cz];
__device__ __align__(256) __nv_bfloat16 g_hih[(size_t)TOK*HID];
// split bf16 weights
__device__ __align__(256) __nv_bfloat16 g_wqh[3*Cz*Cz], g_wql[3*Cz*Cz];
__device__ __align__(256) __nv_bfloat16 g_wph[Cz*Cz],   g_wpl[Cz*Cz];
__device__ __align__(256) __nv_bfloat16 g_w1h[HID*Cz],  g_w1l[HID*Cz];
__device__ __align__(256) __nv_bfloat16 g_w2h[Cz*HID],  g_w2l[Cz*HID];

// ---------------- helpers ----------------
__device__ __forceinline__ uint32_t smem_u32(const void* p) {
    uint32_t a;
    asm("{ .reg .u64 t; cvta.to.shared.u64 t, %1; cvt.u32.u64 %0, t; }" : "=r"(a) : "l"(p));
    return a;
}
__device__ __forceinline__ uint32_t pack2bf(float x, float y) {
    __nv_bfloat162 t = __floats2bfloat162_rn(x, y);
    return *(uint32_t*)&t;
}
__device__ __forceinline__ float bf_hi(float x) {
    return __bfloat162float(__float2bfloat16(x));
}
__device__ __forceinline__ void ldsm4(uint32_t addr, uint32_t& r0, uint32_t& r1,
                                      uint32_t& r2, uint32_t& r3) {
    asm volatile("ldmatrix.sync.aligned.m8n8.x4.shared.b16 {%0,%1,%2,%3}, [%4];"
                 : "=r"(r0), "=r"(r1), "=r"(r2), "=r"(r3) : "r"(addr));
}
__device__ __forceinline__ void ldsm4t(uint32_t addr, uint32_t& r0, uint32_t& r1,
                                       uint32_t& r2, uint32_t& r3) {
    asm volatile("ldmatrix.sync.aligned.m8n8.x4.trans.shared.b16 {%0,%1,%2,%3}, [%4];"
                 : "=r"(r0), "=r"(r1), "=r"(r2), "=r"(r3) : "r"(addr));
}
__device__ __forceinline__ void mma_bf16(float* d, const uint32_t* a, const uint32_t* b) {
    asm volatile(
        "mma.sync.aligned.m16n8k16.row.col.f32.bf16.bf16.f32 "
        "{%0,%1,%2,%3}, {%4,%5,%6,%7}, {%8,%9}, {%0,%1,%2,%3};"
        : "+f"(d[0]), "+f"(d[1]), "+f"(d[2]), "+f"(d[3])
        : "r"(a[0]), "r"(a[1]), "r"(a[2]), "r"(a[3]), "r"(b[0]), "r"(b[1]));
}
__device__ __forceinline__ void cpasync16(uint32_t dst, const void* src) {
    asm volatile("cp.async.cg.shared.global [%0], [%1], 16;" :: "r"(dst), "l"(src));
}

// ---------------- 0a: weight split ----------------
__global__ void k_wsplit(const float* __restrict__ src, __nv_bfloat16* __restrict__ hi,
                         __nv_bfloat16* __restrict__ lo, int n) {
    int i = blockIdx.x * 256 + threadIdx.x;
    if (i < n) {
        float v = src[i];
        float h = bf_hi(v);
        hi[i] = __float2bfloat16(v);
        lo[i] = __float2bfloat16(v - h);
    }
}

// ---------------- 0b: precompute bias+mask per (class, head) ----------------
__global__ void k_bias(const float* __restrict__ rpb) {
    int blk = blockIdx.x;          // cls*8 + head
    int cls = blk >> 3, head = blk & 7;
    float* outp = g_bias + (size_t)blk * NTP * NTP;
    for (int i = threadIdx.x; i < NTP * NTP; i += 256) {
        int r = i / NTP, c = i % NTP;
        float v;
        if (r < NT && c < NT) {
            int dr = r / 49, hr = (r % 49) / 7, wr = r % 7;
            int dc = c / 49, hc = (c % 49) / 7, wc = c % 7;
            int idx = (dr - dc + 1) * 169 + (hr - hc + 6) * 13 + (wr - wc + 6);
            int rgr = ((cls & 4) ? (dr == 0 ? 1 : 2) : 0) * 9
                    + ((cls & 2) ? (hr < 4 ? 1 : 2) : 0) * 3
                    + ((cls & 1) ? (wr < 4 ? 1 : 2) : 0);
            int rgc = ((cls & 4) ? (dc == 0 ? 1 : 2) : 0) * 9
                    + ((cls & 2) ? (hc < 4 ? 1 : 2) : 0) * 3
                    + ((cls & 1) ? (wc < 4 ? 1 : 2) : 0);
            v = rpb[idx * HEADS + head] + (rgr != rgc ? -100.f : 0.f);
        } else {
            v = -30000.f;
        }
        outp[i] = v;
    }
}

// ---------------- 1: transpose in (B,D,C,W,H) -> (B,D,H,W,C) ----------------
__global__ void k_transpose_in(const float* __restrict__ x) {
    __shared__ float tile[32][33];
    int bz = blockIdx.z;
    int bd = bz / Wz, w = bz % Wz;
    int h0 = blockIdx.x * 32, c0 = blockIdx.y * 32;
    #pragma unroll
    for (int j = 0; j < 32; j += 8) {
        int c = c0 + threadIdx.y + j;
        int h = h0 + threadIdx.x;
        if (h < Hz)
            tile[threadIdx.y + j][threadIdx.x] =
                x[(((size_t)bd * Cz + c) * Wz + w) * Hz + h];
    }
    __syncthreads();
    #pragma unroll
    for (int j = 0; j < 32; j += 8) {
        int c = c0 + threadIdx.x;
        int h = h0 + threadIdx.y + j;
        if (h < Hz)
            g_xp[(((size_t)bd * Hz + h) * Wz + w) * Cz + c] =
                tile[threadIdx.x][threadIdx.y + j];
    }
}

__device__ __forceinline__ int map_token(int t) {
    int b   = t / (NW * NT);
    int rem = t % (NW * NT);
    int wi = rem / NT, n = rem % NT;
    int d2 = wi / 144, h2 = (wi / 12) % 12, w2 = wi % 12;
    int dd = n / 49, r = n % 49, hh = r / 7, ww = r % 7;
    int d = d2 * 2 + dd, h = h2 * 7 + hh, w = w2 * 7 + ww;
    int ds = (d + 1) & 7;
    int hs = h + 3; if (hs >= Hz) hs -= Hz;
    int ws = w + 3; if (ws >= Wz) ws -= Wz;
    return ((b * Dz + ds) * Hz + hs) * Wz + ws;
}

__device__ __forceinline__ void blockMeanVar(float v, float& mean, float& invstd) {
    __shared__ float sbuf[16];
    float s1 = v, s2 = v * v;
    #pragma unroll
    for (int o = 16; o; o >>= 1) {
        s1 += __shfl_down_sync(0xffffffffu, s1, o);
        s2 += __shfl_down_sync(0xffffffffu, s2, o);
    }
    int wp = threadIdx.x >> 5, ln = threadIdx.x & 31;
    if (!ln) { sbuf[wp] = s1; sbuf[8 + wp] = s2; }
    __syncthreads();
    float m = 0.f, q = 0.f;
    #pragma unroll
    for (int i = 0; i < 8; i++) { m += sbuf[i]; q += sbuf[8 + i]; }
    m *= (1.f / Cz);
    q = q * (1.f / Cz) - m * m;
    mean = m;
    invstd = rsqrtf(q + 1e-5f);
}

// ---------------- 2: LN1 + shift + partition -> split bf16 ----------------
__global__ void k_ln_part(const float* __restrict__ g, const float* __restrict__ bta) {
    int t = blockIdx.x;
    int srct = map_token(t);
    int c = threadIdx.x;
    float v = g_xp[(size_t)srct * Cz + c];
    float m, inv;
    blockMeanVar(v, m, inv);
    float o = (v - m) * inv * g[c] + bta[c];
    float oh = bf_hi(o);
    g_xwh[(size_t)t * Cz + c] = __float2bfloat16(o);
    g_xwl[(size_t)t * Cz + c] = __float2bfloat16(o - oh);
}

// ---------------- GEMM A (3-pass, 128x128 tile) — qkv only --------------
#define PADK 40
#define PLANE_B (128 * PADK * 2)       // 10240 bytes
template <int PASSES, int ACT, bool HAS_BIAS, bool HAS_RES, int OSPLIT>
__global__ __launch_bounds__(256, 2) void k_gemm_bf(
    const __nv_bfloat16* __restrict__ Ah, const __nv_bfloat16* __restrict__ Al,
    const __nv_bfloat16* __restrict__ Bh, const __nv_bfloat16* __restrict__ Bl,
    const float* __restrict__ bias, const float* __restrict__ res,
    float* __restrict__ out,
    __nv_bfloat16* __restrict__ outh, __nv_bfloat16* __restrict__ outl,
    int M, int N, int K) {
    extern __shared__ __align__(16) unsigned char dsm[];
    constexpr int NPL = (PASSES == 3) ? 4 : 2;
    constexpr int STB = NPL * PLANE_B;
    uint32_t sbase = smem_u32(dsm);
    int tid = threadIdx.x, lane = tid & 31, wid = tid >> 5;
    int bm = blockIdx.y * 128, bn = blockIdx.x * 128;
    int wm = (wid & 1) * 64, wn = (wid >> 1) * 32;

    int aRow = wm + (lane & 15);
    int aCol = (lane >> 4) * 8;
    int bRow = wn + ((lane >> 4) << 3) + (lane & 7);
    int bCol = ((lane >> 3) & 1) * 8;

    float acc[4][4][4];
    #pragma unroll
    for (int i = 0; i < 4; i++)
        #pragma unroll
        for (int j = 0; j < 4; j++)
            #pragma unroll
            for (int c = 0; c < 4; c++) acc[i][j][c] = 0.f;

    const int nChunks = K >> 5;

    #define ISSUE(ch, s) do {                                                   \
        int k0_ = (ch) << 5;                                                    \
        uint32_t sb_ = sbase + (s) * STB;                                       \
        _Pragma("unroll")                                                       \
        for (int q_ = 0; q_ < 2; q_++) {                                        \
            int j_ = q_ * 256 + tid;                                            \
            int row_ = j_ >> 2, c8_ = (j_ & 3) * 8;                             \
            uint32_t so_ = (uint32_t)((row_ * PADK + c8_) * 2);                 \
            size_t ga_ = (size_t)(bm + row_) * K + k0_ + c8_;                   \
            size_t gb_ = (size_t)(bn + row_) * K + k0_ + c8_;                   \
            cpasync16(sb_ + 0 * PLANE_B + so_, Ah + ga_);                       \
            if (PASSES == 3) cpasync16(sb_ + 1 * PLANE_B + so_, Al + ga_);      \
            cpasync16(sb_ + (PASSES == 3 ? 2 : 1) * PLANE_B + so_, Bh + gb_);   \
            if (PASSES == 3) cpasync16(sb_ + 3 * PLANE_B + so_, Bl + gb_);      \
        }                                                                       \
        asm volatile("cp.async.commit_group;");                                 \
    } while (0)

    ISSUE(0, 0);
    for (int ch = 0; ch < nChunks; ch++) {
        int s = ch & 1;
        if (ch + 1 < nChunks) {
            ISSUE(ch + 1, (ch + 1) & 1);
            asm volatile("cp.async.wait_group 1;");
        } else {
            asm volatile("cp.async.wait_group 0;");
        }
        __syncthreads();

        uint32_t baseAH = sbase + s * STB;
        uint32_t baseAL = baseAH + PLANE_B;
        uint32_t baseBH = baseAH + (PASSES == 3 ? 2 : 1) * PLANE_B;
        uint32_t baseBL = baseAH + 3 * PLANE_B;

        #pragma unroll
        for (int kk = 0; kk < 2; kk++) {
            int k0 = kk * 16;
            uint32_t aH[4][4], aL[4][4], bb[8];
            #pragma unroll
            for (int mi = 0; mi < 4; mi++) {
                uint32_t off = (uint32_t)(((aRow + mi * 16) * PADK + k0 + aCol) * 2);
                ldsm4(baseAH + off, aH[mi][0], aH[mi][1], aH[mi][2], aH[mi][3]);
                if (PASSES == 3)
                    ldsm4(baseAL + off, aL[mi][0], aL[mi][1], aL[mi][2], aL[mi][3]);
            }
            #pragma unroll
            for (int p = 0; p < 2; p++) {
                uint32_t off = (uint32_t)(((bRow + p * 16) * PADK + k0 + bCol) * 2);
                ldsm4(baseBH + off, bb[p * 4 + 0], bb[p * 4 + 1], bb[p * 4 + 2], bb[p * 4 + 3]);
            }
            #pragma unroll
            for (int mi = 0; mi < 4; mi++)
                #pragma unroll
                for (int ni = 0; ni < 4; ni++)
                    mma_bf16(acc[mi][ni], aH[mi], &bb[ni * 2]);
            if (PASSES == 3) {
                #pragma unroll
                for (int mi = 0; mi < 4; mi++)
                    #pragma unroll
                    for (int ni = 0; ni < 4; ni++)
                        mma_bf16(acc[mi][ni], aL[mi], &bb[ni * 2]);
                #pragma unroll
                for (int p = 0; p < 2; p++) {
                    uint32_t off = (uint32_t)(((bRow + p * 16) * PADK + k0 + bCol) * 2);
                    ldsm4(baseBL + off, bb[p * 4 + 0], bb[p * 4 + 1], bb[p * 4 + 2], bb[p * 4 + 3]);
                }
                #pragma unroll
                for (int mi = 0; mi < 4; mi++)
                    #pragma unroll
                    for (int ni = 0; ni < 4; ni++)
                        mma_bf16(acc[mi][ni], aH[mi], &bb[ni * 2]);
            }
        }
        __syncthreads();
    }
    #undef ISSUE

    int orow = lane >> 2, ocol = (lane & 3) * 2;
    #pragma unroll
    for (int mi = 0; mi < 4; mi++) {
        int m0 = bm + wm + mi * 16;
        #pragma unroll
        for (int ni = 0; ni < 4; ni++) {
            int n = bn + wn + ni * 8 + ocol;
            float bi0 = 0.f, bi1 = 0.f;
            if (HAS_BIAS) { bi0 = bias[n]; bi1 = bias[n + 1]; }
            #pragma unroll
            for (int half = 0; half < 2; half++) {
                int m = m0 + orow + half * 8;
                float v0 = acc[mi][ni][half * 2 + 0] + bi0;
                float v1 = acc[mi][ni][half * 2 + 1] + bi1;
                if (ACT == 1) {
                    v0 = 0.5f * v0 * (1.f + erff(v0 * 0.70710678118654752f));
                    v1 = 0.5f * v1 * (1.f + erff(v1 * 0.70710678118654752f));
                }
                if (HAS_RES) {
                    const float2 r2 = *(const float2*)(res + (size_t)m * N + n);
                    v0 += r2.x; v1 += r2.y;
                }
                if (OSPLIT == 1) {
                    *(uint32_t*)(outh + (size_t)m * N + n) = pack2bf(v0, v1);
                    *(uint32_t*)(outl + (size_t)m * N + n) =
                        pack2bf(v0 - bf_hi(v0), v1 - bf_hi(v1));
                } else if (OSPLIT == 2) {
                    *(uint32_t*)(outh + (size_t)m * N + n) = pack2bf(v0, v1);
                } else {
                    *(float2*)(out + (size_t)m * N + n) = make_float2(v0, v1);
                }
            }
        }
    }
}

// ---------------- GEMM B (1-pass, 128x256 CTA, 64x64 warp tile) ----------
// smem per stage: A 128xPADK + B 256xPADK halves = 30720 B; 2 stages.
#define APLANE_B (128 * PADK * 2)      // 10240
#define BPLANE_B (256 * PADK * 2)      // 20480
#define STAGE2_B (APLANE_B + BPLANE_B) // 30720
template <int ACT, bool HAS_BIAS, bool HAS_RES, int OSPLIT>
__global__ __launch_bounds__(256, 1) void k_gemm2(
    const __nv_bfloat16* __restrict__ Ah, const __nv_bfloat16* __restrict__ Bh,
    const float* __restrict__ bias, const float* __restrict__ res,
    float* __restrict__ out, __nv_bfloat16* __restrict__ outh,
    int M, int N, int K) {
    extern __shared__ __align__(16) unsigned char dsm[];
    uint32_t sbase = smem_u32(dsm);
    int tid = threadIdx.x, lane = tid & 31, wid = tid >> 5;
    int bm = blockIdx.y * 128, bn = blockIdx.x * 256;
    int wm = (wid & 1) * 64, wn = (wid >> 1) * 64;

    int aRow = wm + (lane & 15);
    int aCol = (lane >> 4) * 8;
    int bRow = wn + ((lane >> 4) << 3) + (lane & 7);
    int bCol = ((lane >> 3) & 1) * 8;

    float acc[4][8][4];
    #pragma unroll
    for (int i = 0; i < 4; i++)
        #pragma unroll
        for (int j = 0; j < 8; j++)
            #pragma unroll
            for (int c = 0; c < 4; c++) acc[i][j][c] = 0.f;

    const int nChunks = K >> 5;

    #define ISSUE2(ch, s) do {                                                  \
        int k0_ = (ch) << 5;                                                    \
        uint32_t sb_ = sbase + (s) * STAGE2_B;                                  \
        _Pragma("unroll")                                                       \
        for (int q_ = 0; q_ < 6; q_++) {                                        \
            int i_ = q_ * 256 + tid;                                            \
            if (i_ < 512) {                                                     \
                int row_ = i_ >> 2, c8_ = (i_ & 3) * 8;                         \
                cpasync16(sb_ + (uint32_t)((row_ * PADK + c8_) * 2),            \
                          Ah + (size_t)(bm + row_) * K + k0_ + c8_);            \
            } else {                                                            \
                int j_ = i_ - 512;                                              \
                int row_ = j_ >> 2, c8_ = (j_ & 3) * 8;                         \
                cpasync16(sb_ + APLANE_B + (uint32_t)((row_ * PADK + c8_) * 2), \
                          Bh + (size_t)(bn + row_) * K + k0_ + c8_);            \
            }                                                                   \
        }                                                                       \
        asm volatile("cp.async.commit_group;");                                 \
    } while (0)

    ISSUE2(0, 0);
    for (int ch = 0; ch < nChunks; ch++) {
        int s = ch & 1;
        if (ch + 1 < nChunks) {
            ISSUE2(ch + 1, (ch + 1) & 1);
            asm volatile("cp.async.wait_group 1;");
        } else {
            asm volatile("cp.async.wait_group 0;");
        }
        __syncthreads();

        uint32_t baseA = sbase + s * STAGE2_B;
        uint32_t baseB = baseA + APLANE_B;

        #pragma unroll
        for (int kk = 0; kk < 2; kk++) {
            int k0 = kk * 16;
            uint32_t aH[4][4], bb[4][4];
            #pragma unroll
            for (int mi = 0; mi < 4; mi++) {
                uint32_t off = (uint32_t)(((aRow + mi * 16) * PADK + k0 + aCol) * 2);
                ldsm4(baseA + off, aH[mi][0], aH[mi][1], aH[mi][2], aH[mi][3]);
            }
            #pragma unroll
            for (int p = 0; p < 4; p++) {
                uint32_t off = (uint32_t)(((bRow + p * 16) * PADK + k0 + bCol) * 2);
                ldsm4(baseB + off, bb[p][0], bb[p][1], bb[p][2], bb[p][3]);
            }
            #pragma unroll
            for (int mi = 0; mi < 4; mi++)
                #pragma unroll
                for (int ni = 0; ni < 8; ni++)
                    mma_bf16(acc[mi][ni], aH[mi], &bb[ni >> 1][(ni & 1) * 2]);
        }
        __syncthreads();
    }
    #undef ISSUE2

    int orow = lane >> 2, ocol = (lane & 3) * 2;
    #pragma unroll
    for (int mi = 0; mi < 4; mi++) {
        int m0 = bm + wm + mi * 16;
        #pragma unroll
        for (int ni = 0; ni < 8; ni++) {
            int n = bn + wn + ni * 8 + ocol;
            float bi0 = 0.f, bi1 = 0.f;
            if (HAS_BIAS) { bi0 = bias[n]; bi1 = bias[n + 1]; }
            #pragma unroll
            for (int half = 0; half < 2; half++) {
                int m = m0 + orow + half * 8;
                float v0 = acc[mi][ni][half * 2 + 0] + bi0;
                float v1 = acc[mi][ni][half * 2 + 1] + bi1;
                if (ACT == 1) {
                    v0 = 0.5f * v0 * (1.f + erff(v0 * 0.70710678118654752f));
                    v1 = 0.5f * v1 * (1.f + erff(v1 * 0.70710678118654752f));
                }
                if (HAS_RES) {
                    const float2 r2 = *(const float2*)(res + (size_t)m * N + n);
                    v0 += r2.x; v1 += r2.y;
                }
                if (OSPLIT == 2) {
                    *(uint32_t*)(outh + (size_t)m * N + n) = pack2bf(v0, v1);
                } else {
                    *(float2*)(out + (size_t)m * N + n) = make_float2(v0, v1);
                }
            }
        }
    }
}

// ---------------- 4: tensor-core attention per (head, window) ----------------
#define APL (NTP * 40)                 // 4480 halves per plane
#define ATTN_SMEM_TC (6 * APL * 2)     // 53760 bytes
__global__ __launch_bounds__(224, 2) void k_attn_tc() {
    extern __shared__ __nv_bfloat16 asm_[];
    int head = blockIdx.x, bwin = blockIdx.y;
    int tid = threadIdx.x, lane = tid & 31, wid = tid >> 5;
    const float scale = 0.17677669529663687f;
    uint32_t sbase = smem_u32(asm_);

    // zero pad rows 98..111 of all 6 planes
    for (int i = tid; i < 6 * 280; i += 224) {
        int p = i / 280, r = i % 280;
        ((uint32_t*)(asm_ + p * APL + NT * 40))[r] = 0u;
    }

    // fill: 98 tokens x {q,k,v} x {hi,lo} x 4 x 16B cp.async copies
    for (int i = tid; i < 98 * 6 * 4; i += 224) {
        int chunk = i & 3;
        int idx = i >> 2;
        int n = idx / 6, which = idx % 6;
        int sel = which >> 1, pl = which & 1;
        const __nv_bfloat16* src = (pl ? g_qkvl : g_qkvh)
            + (size_t)(bwin * NT + n) * (3 * Cz) + sel * Cz + head * HD + chunk * 8;
        uint32_t dst = sbase + (uint32_t)(((sel * 2 + pl) * APL + n * 40 + chunk * 8) * 2);
        cpasync16(dst, src);
    }
    asm volatile("cp.async.commit_group;");
    asm volatile("cp.async.wait_group 0;");
    __syncthreads();

    // window boundary class -> precomputed bias+mask slab
    int wi = bwin % NW;
    int cls = ((wi / 144) == 3 ? 4 : 0) | (((wi / 12) % 12) == 11 ? 2 : 0)
            | ((wi % 12) == 11 ? 1 : 0);
    const float* Bm = g_bias + (size_t)(cls * HEADS + head) * NTP * NTP;

    uint32_t bQh = sbase,            bQl = sbase + APL * 2;
    uint32_t bKh = sbase + 2*APL*2,  bKl = sbase + 3*APL*2;
    uint32_t bVh = sbase + 4*APL*2,  bVl = sbase + 5*APL*2;

    int wm = wid * 16;
    int aRow = wm + (lane & 15);
    int aCol = (lane >> 4) * 8;
    int bR = ((lane >> 4) << 3) + (lane & 7);
    int bCol = ((lane >> 3) & 1) * 8;
    int vR = ((lane >> 3) & 1) * 8 + (lane & 7);
    int vCol = (lane >> 4) * 8;

    float sacc[14][4];
    #pragma unroll
    for (int t = 0; t < 14; t++)
        #pragma unroll
        for (int e = 0; e < 4; e++) sacc[t][e] = 0.f;

    #pragma unroll
    for (int kk = 0; kk < 2; kk++) {
        int k0 = kk * 16;
        uint32_t aH[4], aL[4], bbH[4], bbL[4];
        uint32_t aoff = (uint32_t)((aRow * 40 + k0 + aCol) * 2);
        ldsm4(bQh + aoff, aH[0], aH[1], aH[2], aH[3]);
        ldsm4(bQl + aoff, aL[0], aL[1], aL[2], aL[3]);
        #pragma unroll
        for (int nt = 0; nt < 7; nt++) {
            uint32_t boff = (uint32_t)(((nt * 16 + bR) * 40 + k0 + bCol) * 2);
            ldsm4(bKh + boff, bbH[0], bbH[1], bbH[2], bbH[3]);
            ldsm4(bKl + boff, bbL[0], bbL[1], bbL[2], bbL[3]);
            mma_bf16(sacc[nt * 2 + 0], aH, &bbH[0]);
            mma_bf16(sacc[nt * 2 + 1], aH, &bbH[2]);
            mma_bf16(sacc[nt * 2 + 0], aH, &bbL[0]);
            mma_bf16(sacc[nt * 2 + 1], aH, &bbL[2]);
            mma_bf16(sacc[nt * 2 + 0], aL, &bbH[0]);
            mma_bf16(sacc[nt * 2 + 1], aL, &bbH[2]);
        }
    }

    // scale + precomputed bias/mask (coalesced float2 loads)
    int r0 = wm + (lane >> 2);
    int cbase = (lane & 3) * 2;
    #pragma unroll
    for (int h = 0; h < 2; h++) {
        int r = r0 + h * 8;
        const float2* brow = (const float2*)(Bm + (size_t)r * NTP);
        #pragma unroll
        for (int t = 0; t < 14; t++) {
            float2 bb = brow[t * 4 + (lane & 3)];
            sacc[t][h * 2 + 0] = sacc[t][h * 2 + 0] * scale + bb.x;
            sacc[t][h * 2 + 1] = sacc[t][h * 2 + 1] * scale + bb.y;
        }
    }

    // softmax in regs (row = quad of lanes)
    #pragma unroll
    for (int h = 0; h < 2; h++) {
        float mx = -1e30f;
        #pragma unroll
        for (int t = 0; t < 14; t++) {
            mx = fmaxf(mx, sacc[t][h * 2 + 0]);
            mx = fmaxf(mx, sacc[t][h * 2 + 1]);
        }
        mx = fmaxf(mx, __shfl_xor_sync(0xffffffffu, mx, 1));
        mx = fmaxf(mx, __shfl_xor_sync(0xffffffffu, mx, 2));
        float sum = 0.f;
        #pragma unroll
        for (int t = 0; t < 14; t++) {
            #pragma unroll
            for (int e = 0; e < 2; e++) {
                float v = __expf(sacc[t][h * 2 + e] - mx);
                sacc[t][h * 2 + e] = v;
                sum += v;
            }
        }
        sum += __shfl_xor_sync(0xffffffffu, sum, 1);
        sum += __shfl_xor_sync(0xffffffffu, sum, 2);
        float inv = 1.f / sum;
        #pragma unroll
        for (int t = 0; t < 14; t++) {
            sacc[t][h * 2 + 0] *= inv;
            sacc[t][h * 2 + 1] *= inv;
        }
    }

    // P @ V (3-pass; V via trans-ldmatrix)
    float oacc[4][4];
    #pragma unroll
    for (int i = 0; i < 4; i++)
        #pragma unroll
        for (int e = 0; e < 4; e++) oacc[i][e] = 0.f;

    #pragma unroll
    for (int j = 0; j < 7; j++) {
        uint32_t aH[4], aL[4];
        #pragma unroll
        for (int q = 0; q < 2; q++) {
            float p0 = sacc[2 * j + q][0], p1 = sacc[2 * j + q][1];
            float p2 = sacc[2 * j + q][2], p3 = sacc[2 * j + q][3];
            aH[q * 2 + 0] = pack2bf(p0, p1);
            aH[q * 2 + 1] = pack2bf(p2, p3);
            aL[q * 2 + 0] = pack2bf(p0 - bf_hi(p0), p1 - bf_hi(p1));
            aL[q * 2 + 1] = pack2bf(p2 - bf_hi(p2), p3 - bf_hi(p3));
        }
        #pragma unroll
        for (int dg = 0; dg < 2; dg++) {
            uint32_t bbH[4], bbL[4];
            uint32_t boff = (uint32_t)(((j * 16 + vR) * 40 + vCol + dg * 16) * 2);
            ldsm4t(bVh + boff, bbH[0], bbH[1], bbH[2], bbH[3]);
            ldsm4t(bVl + boff, bbL[0], bbL[1], bbL[2], bbL[3]);
            mma_bf16(oacc[dg * 2 + 0], aH, &bbH[0]);
            mma_bf16(oacc[dg * 2 + 1], aH, &bbH[2]);
            mma_bf16(oacc[dg * 2 + 0], aH, &bbL[0]);
            mma_bf16(oacc[dg * 2 + 1], aH, &bbL[2]);
            mma_bf16(oacc[dg * 2 + 0], aL, &bbH[0]);
            mma_bf16(oacc[dg * 2 + 1], aL, &bbH[2]);
        }
    }

    #pragma unroll
    for (int h = 0; h < 2; h++) {
        int r = r0 + h * 8;
        if (r < NT) {
            size_t ob = ((size_t)bwin * NT + r) * Cz + head * HD;
            #pragma unroll
            for (int nt = 0; nt < 4; nt++) {
                int c = nt * 8 + cbase;
                *(uint32_t*)(g_aoh + ob + c) =
                    pack2bf(oacc[nt][h * 2 + 0], oacc[nt][h * 2 + 1]);
            }
        }
    }
}

// ---------------- 6: window reverse + unshift + residual + LN2 ----------------
__global__ void k_rev_res_ln2(const float* __restrict__ g2, const float* __restrict__ b2) {
    int t = blockIdx.x;
    int ft = map_token(t);
    int c = threadIdx.x;
    float v = g_po[(size_t)t * Cz + c] + g_xp[(size_t)ft * Cz + c];
    g_xres[(size_t)ft * Cz + c] = v;
    float m, inv;
    blockMeanVar(v, m, inv);
    float o = (v - m) * inv * g2[c] + b2[c];
    g_l2h[(size_t)ft * Cz + c] = __float2bfloat16(o);
}

// ---------------- 9: transpose out (B,D,H,W,C) -> (B,D,C,W,H) ----------------
__global__ void k_transpose_out(float* __restrict__ out) {
    __shared__ float tile[32][33];
    int bz = blockIdx.z;
    int bd = bz / Wz, w = bz % Wz;
    int h0 = blockIdx.x * 32, c0 = blockIdx.y * 32;
    #pragma unroll
    for (int j = 0; j < 32; j += 8) {
        int c = c0 + threadIdx.x;
        int h = h0 + threadIdx.y + j;
        if (h < Hz)
            tile[threadIdx.y + j][threadIdx.x] =
                g_y[(((size_t)bd * Hz + h) * Wz + w) * Cz + c];
    }
    __syncthreads();
    #pragma unroll
    for (int j = 0; j < 32; j += 8) {
        int h = h0 + threadIdx.x;
        int c = c0 + threadIdx.y + j;
        if (h < Hz)
            out[(((size_t)bd * Cz + c) * Wz + w) * Hz + h] =
                tile[threadIdx.x][threadIdx.y + j];
    }
}

// ---------------- launch ----------------
extern "C" void kernel_launch(void* const* d_in, const int* in_sizes, int n_in,
                              void* d_out, int out_size) {
    const float* x      = (const float*)d_in[0];
    const float* n1g    = (const float*)d_in[1];
    const float* n1b    = (const float*)d_in[2];
    const float* qkv_w  = (const float*)d_in[3];
    const float* rpb    = (const float*)d_in[4];
    const float* proj_w = (const float*)d_in[5];
    const float* proj_b = (const float*)d_in[6];
    const float* n2g    = (const float*)d_in[7];
    const float* n2b    = (const float*)d_in[8];
    const float* fc1_w  = (const float*)d_in[9];
    const float* fc1_b  = (const float*)d_in[10];
    const float* fc2_w  = (const float*)d_in[11];
    const float* fc2_b  = (const float*)d_in[12];
    float* out = (float*)d_out;

    void* p;
    cudaGetSymbolAddress(&p, g_po);   float* po   = (float*)p;
    cudaGetSymbolAddress(&p, g_xres); float* xres = (float*)p;
    cudaGetSymbolAddress(&p, g_y);    float* y    = (float*)p;
    cudaGetSymbolAddress(&p, g_xwh);  __nv_bfloat16* xwh = (__nv_bfloat16*)p;
    cudaGetSymbolAddress(&p, g_xwl);  __nv_bfloat16* xwl = (__nv_bfloat16*)p;
    cudaGetSymbolAddress(&p, g_qkvh); __nv_bfloat16* qkvh = (__nv_bfloat16*)p;
    cudaGetSymbolAddress(&p, g_qkvl); __nv_bfloat16* qkvl = (__nv_bfloat16*)p;
    cudaGetSymbolAddress(&p, g_aoh);  __nv_bfloat16* aoh = (__nv_bfloat16*)p;
    cudaGetSymbolAddress(&p, g_l2h);  __nv_bfloat16* l2h = (__nv_bfloat16*)p;
    cudaGetSymbolAddress(&p, g_hih);  __nv_bfloat16* hih = (__nv_bfloat16*)p;
    cudaGetSymbolAddress(&p, g_wqh);  __nv_bfloat16* wqh = (__nv_bfloat16*)p;
    cudaGetSymbolAddress(&p, g_wql);  __nv_bfloat16* wql = (__nv_bfloat16*)p;
    cudaGetSymbolAddress(&p, g_wph);  __nv_bfloat16* wph = (__nv_bfloat16*)p;
    cudaGetSymbolAddress(&p, g_w1h);  __nv_bfloat16* w1h = (__nv_bfloat16*)p;
    cudaGetSymbolAddress(&p, g_w2h);  __nv_bfloat16* w2h = (__nv_bfloat16*)p;
    cudaGetSymbolAddress(&p, g_wpl);  __nv_bfloat16* wpl = (__nv_bfloat16*)p;
    cudaGetSymbolAddress(&p, g_w1l);  __nv_bfloat16* w1l = (__nv_bfloat16*)p;
    cudaGetSymbolAddress(&p, g_w2l);  __nv_bfloat16* w2l = (__nv_bfloat16*)p;

    cudaFuncSetAttribute(k_attn_tc, cudaFuncAttributeMaxDynamicSharedMemorySize, ATTN_SMEM_TC);
    cudaFuncSetAttribute(k_gemm_bf<3, 0, false, false, 1>, cudaFuncAttributeMaxDynamicSharedMemorySize, 8 * PLANE_B);
    cudaFuncSetAttribute(k_gemm2<0, true, false, 0>, cudaFuncAttributeMaxDynamicSharedMemorySize, 2 * STAGE2_B);
    cudaFuncSetAttribute(k_gemm2<1, true, false, 2>, cudaFuncAttributeMaxDynamicSharedMemorySize, 2 * STAGE2_B);
    cudaFuncSetAttribute(k_gemm2<0, true, true, 0>,  cudaFuncAttributeMaxDynamicSharedMemorySize, 2 * STAGE2_B);

    dim3 tb(32, 8);
    dim3 tg(3, 8, Bz * Dz * Wz);

    // 0. weight splits + bias table (tiny)
    k_wsplit<<<(3 * Cz * Cz + 255) / 256, 256>>>(qkv_w, wqh, wql, 3 * Cz * Cz);
    k_wsplit<<<(Cz * Cz + 255) / 256, 256>>>(proj_w, wph, wpl, Cz * Cz);
    k_wsplit<<<(HID * Cz + 255) / 256, 256>>>(fc1_w, w1h, w1l, HID * Cz);
    k_wsplit<<<(Cz * HID + 255) / 256, 256>>>(fc2_w, w2h, w2l, Cz * HID);
    k_bias<<<64, 256>>>(rpb);
    // 1. transpose in
    k_transpose_in<<<tg, tb>>>(x);
    // 2. LN1 + shift + partition (split bf16 out)
    k_ln_part<<<TOK, 256>>>(n1g, n1b);
    // 3. qkv GEMM (3-pass, split bf16 out)
    k_gemm_bf<3, 0, false, false, 1><<<dim3((3 * Cz) / 128, TOK / 128), 256, 8 * PLANE_B>>>(
        xwh, xwl, wqh, wql, nullptr, nullptr, nullptr, qkvh, qkvl, TOK, 3 * Cz, Cz);
    // 4. attention (tensor cores, precomputed bias)
    k_attn_tc<<<dim3(HEADS, BW), 224, ATTN_SMEM_TC>>>();
    // 5. proj GEMM (1-pass wide tile) -> g_po fp32
    k_gemm2<0, true, false, 0><<<dim3(Cz / 256, TOK / 128), 256, 2 * STAGE2_B>>>(
        aoh, wph, proj_b, nullptr, po, nullptr, TOK, Cz, Cz);
    // 6. reverse + residual + LN2 (hi plane out)
    k_rev_res_ln2<<<TOK, 256>>>(n2g, n2b);
    // 7. fc1 GEMM (1-pass wide tile) + GELU -> hi plane
    k_gemm2<1, true, false, 2><<<dim3(HID / 256, TOK / 128), 256, 2 * STAGE2_B>>>(
        l2h, w1h, fc1_b, nullptr, nullptr, hih, TOK, HID, Cz);
    // 8. fc2 GEMM (1-pass wide tile) + bias + residual -> y fp32
    k_gemm2<0, true, true, 0><<<dim3(Cz / 256, TOK / 128), 256, 2 * STAGE2_B>>>(
        hih, w2h, fc2_b, xres, y, nullptr, TOK, Cz, HID);
    // 9. transpose out
    k_transpose_out<<<tg, tb>>>(out);
}

// round 9
// speedup vs baseline: 1.0499x; 1.0499x over previous
#include <cuda_runtime.h>
#include <cuda_bf16.h>
#include <math.h>
#include <stdint.h>

// ---------------- problem constants ----------------
#define Bz 2
#define Dz 8
#define Cz 256
#define Wz 84
#define Hz 84
#define HEADS 8
#define HD 32
#define NT 98            // tokens per window (2*7*7)
#define NTP 112          // padded to 7 x 16
#define NW 576           // windows per batch (4*12*12)
#define BW (Bz*NW)       // 1152 window-batches
#define TOK (BW*NT)      // 112896 tokens
#define HID 1024

// ---------------- scratch (device globals; allocation-free) ----------------
__device__ __align__(256) float g_xp  [(size_t)TOK*Cz];   // shortcut (B,D,H,W,C)
__device__ __align__(256) float g_po  [(size_t)TOK*Cz];   // proj output (windowed order)
__device__ __align__(256) float g_xres[(size_t)TOK*Cz];   // (B,D,H,W,C)
__device__ __align__(256) float g_y   [(size_t)TOK*Cz];
__device__ __align__(256) float g_bias[8 * HEADS * NTP * NTP];  // [cls][head][r][c]
// split bf16 activation planes
__device__ __align__(256) __nv_bfloat16 g_xwh[(size_t)TOK*Cz],   g_xwl[(size_t)TOK*Cz];
__device__ __align__(256) __nv_bfloat16 g_qkvh[(size_t)TOK*3*Cz], g_qkvl[(size_t)TOK*3*Cz];
__device__ __align__(256) __nv_bfloat16 g_aoh[(size_t)TOK*Cz];
__device__ __align__(256) __nv_bfloat16 g_l2h[(size_t)TOK*Cz];
__device__ __align__(256) __nv_bfloat16 g_hih[(size_t)TOK*HID];
// split bf16 weights
__device__ __align__(256) __nv_bfloat16 g_wqh[3*Cz*Cz], g_wql[3*Cz*Cz];
__device__ __align__(256) __nv_bfloat16 g_wph[Cz*Cz],   g_wpl[Cz*Cz];
__device__ __align__(256) __nv_bfloat16 g_w1h[HID*Cz],  g_w1l[HID*Cz];
__device__ __align__(256) __nv_bfloat16 g_w2h[Cz*HID],  g_w2l[Cz*HID];

// ---------------- helpers ----------------
__device__ __forceinline__ uint32_t smem_u32(const void* p) {
    uint32_t a;
    asm("{ .reg .u64 t; cvta.to.shared.u64 t, %1; cvt.u32.u64 %0, t; }" : "=r"(a) : "l"(p));
    return a;
}
__device__ __forceinline__ uint32_t pack2bf(float x, float y) {
    __nv_bfloat162 t = __floats2bfloat162_rn(x, y);
    return *(uint32_t*)&t;
}
__device__ __forceinline__ float bf_hi(float x) {
    return __bfloat162float(__float2bfloat16(x));
}
__device__ __forceinline__ void ldsm4(uint32_t addr, uint32_t& r0, uint32_t& r1,
                                      uint32_t& r2, uint32_t& r3) {
    asm volatile("ldmatrix.sync.aligned.m8n8.x4.shared.b16 {%0,%1,%2,%3}, [%4];"
                 : "=r"(r0), "=r"(r1), "=r"(r2), "=r"(r3) : "r"(addr));
}
__device__ __forceinline__ void ldsm4t(uint32_t addr, uint32_t& r0, uint32_t& r1,
                                       uint32_t& r2, uint32_t& r3) {
    asm volatile("ldmatrix.sync.aligned.m8n8.x4.trans.shared.b16 {%0,%1,%2,%3}, [%4];"
                 : "=r"(r0), "=r"(r1), "=r"(r2), "=r"(r3) : "r"(addr));
}
__device__ __forceinline__ void mma_bf16(float* d, const uint32_t* a, const uint32_t* b) {
    asm volatile(
        "mma.sync.aligned.m16n8k16.row.col.f32.bf16.bf16.f32 "
        "{%0,%1,%2,%3}, {%4,%5,%6,%7}, {%8,%9}, {%0,%1,%2,%3};"
        : "+f"(d[0]), "+f"(d[1]), "+f"(d[2]), "+f"(d[3])
        : "r"(a[0]), "r"(a[1]), "r"(a[2]), "r"(a[3]), "r"(b[0]), "r"(b[1]));
}
__device__ __forceinline__ void cpasync16(uint32_t dst, const void* src) {
    asm volatile("cp.async.cg.shared.global [%0], [%1], 16;" :: "r"(dst), "l"(src));
}

// ---------------- 0a: weight split ----------------
__global__ void k_wsplit(const float* __restrict__ src, __nv_bfloat16* __restrict__ hi,
                         __nv_bfloat16* __restrict__ lo, int n) {
    int i = blockIdx.x * 256 + threadIdx.x;
    if (i < n) {
        float v = src[i];
        float h = bf_hi(v);
        hi[i] = __float2bfloat16(v);
        lo[i] = __float2bfloat16(v - h);
    }
}

// ---------------- 0b: precompute bias+mask per (class, head) ----------------
__global__ void k_bias(const float* __restrict__ rpb) {
    int blk = blockIdx.x;          // cls*8 + head
    int cls = blk >> 3, head = blk & 7;
    float* outp = g_bias + (size_t)blk * NTP * NTP;
    for (int i = threadIdx.x; i < NTP * NTP; i += 256) {
        int r = i / NTP, c = i % NTP;
        float v;
        if (r < NT && c < NT) {
            int dr = r / 49, hr = (r % 49) / 7, wr = r % 7;
            int dc = c / 49, hc = (c % 49) / 7, wc = c % 7;
            int idx = (dr - dc + 1) * 169 + (hr - hc + 6) * 13 + (wr - wc + 6);
            int rgr = ((cls & 4) ? (dr == 0 ? 1 : 2) : 0) * 9
                    + ((cls & 2) ? (hr < 4 ? 1 : 2) : 0) * 3
                    + ((cls & 1) ? (wr < 4 ? 1 : 2) : 0);
            int rgc = ((cls & 4) ? (dc == 0 ? 1 : 2) : 0) * 9
                    + ((cls & 2) ? (hc < 4 ? 1 : 2) : 0) * 3
                    + ((cls & 1) ? (wc < 4 ? 1 : 2) : 0);
            v = rpb[idx * HEADS + head] + (rgr != rgc ? -100.f : 0.f);
        } else {
            v = -30000.f;
        }
        outp[i] = v;
    }
}

// ---------------- 1: transpose in (B,D,C,W,H) -> (B,D,H,W,C) ----------------
__global__ void k_transpose_in(const float* __restrict__ x) {
    __shared__ float tile[32][33];
    int bz = blockIdx.z;
    int bd = bz / Wz, w = bz % Wz;
    int h0 = blockIdx.x * 32, c0 = blockIdx.y * 32;
    #pragma unroll
    for (int j = 0; j < 32; j += 8) {
        int c = c0 + threadIdx.y + j;
        int h = h0 + threadIdx.x;
        if (h < Hz)
            tile[threadIdx.y + j][threadIdx.x] =
                x[(((size_t)bd * Cz + c) * Wz + w) * Hz + h];
    }
    __syncthreads();
    #pragma unroll
    for (int j = 0; j < 32; j += 8) {
        int c = c0 + threadIdx.x;
        int h = h0 + threadIdx.y + j;
        if (h < Hz)
            g_xp[(((size_t)bd * Hz + h) * Wz + w) * Cz + c] =
                tile[threadIdx.x][threadIdx.y + j];
    }
}

__device__ __forceinline__ int map_token(int t) {
    int b   = t / (NW * NT);
    int rem = t % (NW * NT);
    int wi = rem / NT, n = rem % NT;
    int d2 = wi / 144, h2 = (wi / 12) % 12, w2 = wi % 12;
    int dd = n / 49, r = n % 49, hh = r / 7, ww = r % 7;
    int d = d2 * 2 + dd, h = h2 * 7 + hh, w = w2 * 7 + ww;
    int ds = (d + 1) & 7;
    int hs = h + 3; if (hs >= Hz) hs -= Hz;
    int ws = w + 3; if (ws >= Wz) ws -= Wz;
    return ((b * Dz + ds) * Hz + hs) * Wz + ws;
}

__device__ __forceinline__ void blockMeanVar(float v, float& mean, float& invstd) {
    __shared__ float sbuf[16];
    float s1 = v, s2 = v * v;
    #pragma unroll
    for (int o = 16; o; o >>= 1) {
        s1 += __shfl_down_sync(0xffffffffu, s1, o);
        s2 += __shfl_down_sync(0xffffffffu, s2, o);
    }
    int wp = threadIdx.x >> 5, ln = threadIdx.x & 31;
    if (!ln) { sbuf[wp] = s1; sbuf[8 + wp] = s2; }
    __syncthreads();
    float m = 0.f, q = 0.f;
    #pragma unroll
    for (int i = 0; i < 8; i++) { m += sbuf[i]; q += sbuf[8 + i]; }
    m *= (1.f / Cz);
    q = q * (1.f / Cz) - m * m;
    mean = m;
    invstd = rsqrtf(q + 1e-5f);
}

// ---------------- 2: LN1 + shift + partition -> split bf16 ----------------
__global__ void k_ln_part(const float* __restrict__ g, const float* __restrict__ bta) {
    int t = blockIdx.x;
    int srct = map_token(t);
    int c = threadIdx.x;
    float v = g_xp[(size_t)srct * Cz + c];
    float m, inv;
    blockMeanVar(v, m, inv);
    float o = (v - m) * inv * g[c] + bta[c];
    float oh = bf_hi(o);
    g_xwh[(size_t)t * Cz + c] = __float2bfloat16(o);
    g_xwl[(size_t)t * Cz + c] = __float2bfloat16(o - oh);
}

// ---------------- GEMM: out[M,N] = A[M,K] @ Wt[N,K]^T --------------------
// PASSES=3: split-bf16 hi/lo, 3 mma passes. PASSES=1: hi only.
// OSPLIT: 0 = fp32 out, 1 = bf16 hi+lo planes, 2 = bf16 hi plane only.
// QSCALE: multiply outputs in columns n < Cz by 1/sqrt(HD) (qkv: scales Q).
#define PADK 40
#define PLANE_B (128 * PADK * 2)       // 10240 bytes
template <int PASSES, int ACT, bool HAS_BIAS, bool HAS_RES, int OSPLIT, bool QSCALE>
__global__ __launch_bounds__(256, 2) void k_gemm_bf(
    const __nv_bfloat16* __restrict__ Ah, const __nv_bfloat16* __restrict__ Al,
    const __nv_bfloat16* __restrict__ Bh, const __nv_bfloat16* __restrict__ Bl,
    const float* __restrict__ bias, const float* __restrict__ res,
    float* __restrict__ out,
    __nv_bfloat16* __restrict__ outh, __nv_bfloat16* __restrict__ outl,
    int M, int N, int K) {
    extern __shared__ __align__(16) unsigned char dsm[];
    constexpr int NPL = (PASSES == 3) ? 4 : 2;
    constexpr int STB = NPL * PLANE_B;
    uint32_t sbase = smem_u32(dsm);
    int tid = threadIdx.x, lane = tid & 31, wid = tid >> 5;
    int bm = blockIdx.y * 128, bn = blockIdx.x * 128;
    int wm = (wid & 1) * 64, wn = (wid >> 1) * 32;

    int aRow = wm + (lane & 15);
    int aCol = (lane >> 4) * 8;
    int bRow = wn + ((lane >> 4) << 3) + (lane & 7);
    int bCol = ((lane >> 3) & 1) * 8;

    float acc[4][4][4];
    #pragma unroll
    for (int i = 0; i < 4; i++)
        #pragma unroll
        for (int j = 0; j < 4; j++)
            #pragma unroll
            for (int c = 0; c < 4; c++) acc[i][j][c] = 0.f;

    const int nChunks = K >> 5;

    #define ISSUE(ch, s) do {                                                   \
        int k0_ = (ch) << 5;                                                    \
        uint32_t sb_ = sbase + (s) * STB;                                       \
        _Pragma("unroll")                                                       \
        for (int q_ = 0; q_ < 2; q_++) {                                        \
            int j_ = q_ * 256 + tid;                                            \
            int row_ = j_ >> 2, c8_ = (j_ & 3) * 8;                             \
            uint32_t so_ = (uint32_t)((row_ * PADK + c8_) * 2);                 \
            size_t ga_ = (size_t)(bm + row_) * K + k0_ + c8_;                   \
            size_t gb_ = (size_t)(bn + row_) * K + k0_ + c8_;                   \
            cpasync16(sb_ + 0 * PLANE_B + so_, Ah + ga_);                       \
            if (PASSES == 3) cpasync16(sb_ + 1 * PLANE_B + so_, Al + ga_);      \
            cpasync16(sb_ + (PASSES == 3 ? 2 : 1) * PLANE_B + so_, Bh + gb_);   \
            if (PASSES == 3) cpasync16(sb_ + 3 * PLANE_B + so_, Bl + gb_);      \
        }                                                                       \
        asm volatile("cp.async.commit_group;");                                 \
    } while (0)

    ISSUE(0, 0);
    for (int ch = 0; ch < nChunks; ch++) {
        int s = ch & 1;
        if (ch + 1 < nChunks) {
            ISSUE(ch + 1, (ch + 1) & 1);
            asm volatile("cp.async.wait_group 1;");
        } else {
            asm volatile("cp.async.wait_group 0;");
        }
        __syncthreads();

        uint32_t baseAH = sbase + s * STB;
        uint32_t baseAL = baseAH + PLANE_B;
        uint32_t baseBH = baseAH + (PASSES == 3 ? 2 : 1) * PLANE_B;
        uint32_t baseBL = baseAH + 3 * PLANE_B;

        #pragma unroll
        for (int kk = 0; kk < 2; kk++) {
            int k0 = kk * 16;
            uint32_t aH[4][4], aL[4][4], bb[8];
            #pragma unroll
            for (int mi = 0; mi < 4; mi++) {
                uint32_t off = (uint32_t)(((aRow + mi * 16) * PADK + k0 + aCol) * 2);
                ldsm4(baseAH + off, aH[mi][0], aH[mi][1], aH[mi][2], aH[mi][3]);
                if (PASSES == 3)
                    ldsm4(baseAL + off, aL[mi][0], aL[mi][1], aL[mi][2], aL[mi][3]);
            }
            #pragma unroll
            for (int p = 0; p < 2; p++) {
                uint32_t off = (uint32_t)(((bRow + p * 16) * PADK + k0 + bCol) * 2);
                ldsm4(baseBH + off, bb[p * 4 + 0], bb[p * 4 + 1], bb[p * 4 + 2], bb[p * 4 + 3]);
            }
            #pragma unroll
            for (int mi = 0; mi < 4; mi++)
                #pragma unroll
                for (int ni = 0; ni < 4; ni++)
                    mma_bf16(acc[mi][ni], aH[mi], &bb[ni * 2]);
            if (PASSES == 3) {
                #pragma unroll
                for (int mi = 0; mi < 4; mi++)
                    #pragma unroll
                    for (int ni = 0; ni < 4; ni++)
                        mma_bf16(acc[mi][ni], aL[mi], &bb[ni * 2]);
                #pragma unroll
                for (int p = 0; p < 2; p++) {
                    uint32_t off = (uint32_t)(((bRow + p * 16) * PADK + k0 + bCol) * 2);
                    ldsm4(baseBL + off, bb[p * 4 + 0], bb[p * 4 + 1], bb[p * 4 + 2], bb[p * 4 + 3]);
                }
                #pragma unroll
                for (int mi = 0; mi < 4; mi++)
                    #pragma unroll
                    for (int ni = 0; ni < 4; ni++)
                        mma_bf16(acc[mi][ni], aH[mi], &bb[ni * 2]);
            }
        }
        __syncthreads();
    }
    #undef ISSUE

    int orow = lane >> 2, ocol = (lane & 3) * 2;
    #pragma unroll
    for (int mi = 0; mi < 4; mi++) {
        int m0 = bm + wm + mi * 16;
        #pragma unroll
        for (int ni = 0; ni < 4; ni++) {
            int n = bn + wn + ni * 8 + ocol;
            float bi0 = 0.f, bi1 = 0.f;
            if (HAS_BIAS) { bi0 = bias[n]; bi1 = bias[n + 1]; }
            float sc = (QSCALE && n < Cz) ? 0.17677669529663687f : 1.f;
            #pragma unroll
            for (int half = 0; half < 2; half++) {
                int m = m0 + orow + half * 8;
                float v0 = acc[mi][ni][half * 2 + 0] + bi0;
                float v1 = acc[mi][ni][half * 2 + 1] + bi1;
                if (QSCALE) { v0 *= sc; v1 *= sc; }
                if (ACT == 1) {
                    v0 = 0.5f * v0 * (1.f + erff(v0 * 0.70710678118654752f));
                    v1 = 0.5f * v1 * (1.f + erff(v1 * 0.70710678118654752f));
                }
                if (HAS_RES) {
                    const float2 r2 = *(const float2*)(res + (size_t)m * N + n);
                    v0 += r2.x; v1 += r2.y;
                }
                if (OSPLIT == 1) {
                    *(uint32_t*)(outh + (size_t)m * N + n) = pack2bf(v0, v1);
                    *(uint32_t*)(outl + (size_t)m * N + n) =
                        pack2bf(v0 - bf_hi(v0), v1 - bf_hi(v1));
                } else if (OSPLIT == 2) {
                    *(uint32_t*)(outh + (size_t)m * N + n) = pack2bf(v0, v1);
                } else {
                    *(float2*)(out + (size_t)m * N + n) = make_float2(v0, v1);
                }
            }
        }
    }
}

// ---------------- 4: tensor-core attention per (head, window) ----------------
#define APL (NTP * 40)                 // 4480 halves per plane
#define ATTN_SMEM_TC (6 * APL * 2)     // 53760 bytes
__global__ __launch_bounds__(224, 2) void k_attn_tc() {
    extern __shared__ __nv_bfloat16 asm_[];
    int head = blockIdx.x, bwin = blockIdx.y;
    int tid = threadIdx.x, lane = tid & 31, wid = tid >> 5;
    uint32_t sbase = smem_u32(asm_);

    // zero pad rows 98..111 of all 6 planes
    for (int i = tid; i < 6 * 280; i += 224) {
        int p = i / 280, r = i % 280;
        ((uint32_t*)(asm_ + p * APL + NT * 40))[r] = 0u;
    }

    // fill: 98 tokens x {q,k,v} x {hi,lo} x 4 x 16B cp.async copies
    for (int i = tid; i < 98 * 6 * 4; i += 224) {
        int chunk = i & 3;
        int idx = i >> 2;
        int n = idx / 6, which = idx % 6;
        int sel = which >> 1, pl = which & 1;
        const __nv_bfloat16* src = (pl ? g_qkvl : g_qkvh)
            + (size_t)(bwin * NT + n) * (3 * Cz) + sel * Cz + head * HD + chunk * 8;
        uint32_t dst = sbase + (uint32_t)(((sel * 2 + pl) * APL + n * 40 + chunk * 8) * 2);
        cpasync16(dst, src);
    }
    asm volatile("cp.async.commit_group;");
    asm volatile("cp.async.wait_group 0;");
    __syncthreads();

    // window boundary class -> precomputed bias+mask slab
    int wi = bwin % NW;
    int cls = ((wi / 144) == 3 ? 4 : 0) | (((wi / 12) % 12) == 11 ? 2 : 0)
            | ((wi % 12) == 11 ? 1 : 0);
    const float* Bm = g_bias + (size_t)(cls * HEADS + head) * NTP * NTP;

    uint32_t bQh = sbase,            bQl = sbase + APL * 2;
    uint32_t bKh = sbase + 2*APL*2,  bKl = sbase + 3*APL*2;
    uint32_t bVh = sbase + 4*APL*2,  bVl = sbase + 5*APL*2;

    int wm = wid * 16;
    int aRow = wm + (lane & 15);
    int aCol = (lane >> 4) * 8;
    int bR = ((lane >> 4) << 3) + (lane & 7);
    int bCol = ((lane >> 3) & 1) * 8;
    int vR = ((lane >> 3) & 1) * 8 + (lane & 7);
    int vCol = (lane >> 4) * 8;

    float sacc[14][4];
    #pragma unroll
    for (int t = 0; t < 14; t++)
        #pragma unroll
        for (int e = 0; e < 4; e++) sacc[t][e] = 0.f;

    #pragma unroll
    for (int kk = 0; kk < 2; kk++) {
        int k0 = kk * 16;
        uint32_t aH[4], aL[4], bbH[4], bbL[4];
        uint32_t aoff = (uint32_t)((aRow * 40 + k0 + aCol) * 2);
        ldsm4(bQh + aoff, aH[0], aH[1], aH[2], aH[3]);
        ldsm4(bQl + aoff, aL[0], aL[1], aL[2], aL[3]);
        #pragma unroll
        for (int nt = 0; nt < 7; nt++) {
            uint32_t boff = (uint32_t)(((nt * 16 + bR) * 40 + k0 + bCol) * 2);
            ldsm4(bKh + boff, bbH[0], bbH[1], bbH[2], bbH[3]);
            ldsm4(bKl + boff, bbL[0], bbL[1], bbL[2], bbL[3]);
            mma_bf16(sacc[nt * 2 + 0], aH, &bbH[0]);
            mma_bf16(sacc[nt * 2 + 1], aH, &bbH[2]);
            mma_bf16(sacc[nt * 2 + 0], aH, &bbL[0]);
            mma_bf16(sacc[nt * 2 + 1], aH, &bbL[2]);
            mma_bf16(sacc[nt * 2 + 0], aL, &bbH[0]);
            mma_bf16(sacc[nt * 2 + 1], aL, &bbH[2]);
        }
    }

    // precomputed bias/mask add (Q already scaled in qkv epilogue)
    int r0 = wm + (lane >> 2);
    int cbase = (lane & 3) * 2;
    #pragma unroll
    for (int h = 0; h < 2; h++) {
        int r = r0 + h * 8;
        const float2* brow = (const float2*)(Bm + (size_t)r * NTP);
        #pragma unroll
        for (int t = 0; t < 14; t++) {
            float2 bb = brow[t * 4 + (lane & 3)];
            sacc[t][h * 2 + 0] += bb.x;
            sacc[t][h * 2 + 1] += bb.y;
        }
    }

    // softmax in regs (row = quad of lanes)
    #pragma unroll
    for (int h = 0; h < 2; h++) {
        float mx = -1e30f;
        #pragma unroll
        for (int t = 0; t < 14; t++) {
            mx = fmaxf(mx, sacc[t][h * 2 + 0]);
            mx = fmaxf(mx, sacc[t][h * 2 + 1]);
        }
        mx = fmaxf(mx, __shfl_xor_sync(0xffffffffu, mx, 1));
        mx = fmaxf(mx, __shfl_xor_sync(0xffffffffu, mx, 2));
        float sum = 0.f;
        #pragma unroll
        for (int t = 0; t < 14; t++) {
            #pragma unroll
            for (int e = 0; e < 2; e++) {
                float v = __expf(sacc[t][h * 2 + e] - mx);
                sacc[t][h * 2 + e] = v;
                sum += v;
            }
        }
        sum += __shfl_xor_sync(0xffffffffu, sum, 1);
        sum += __shfl_xor_sync(0xffffffffu, sum, 2);
        float inv = 1.f / sum;
        #pragma unroll
        for (int t = 0; t < 14; t++) {
            sacc[t][h * 2 + 0] *= inv;
            sacc[t][h * 2 + 1] *= inv;
        }
    }

    // P @ V (3-pass; V via trans-ldmatrix)
    float oacc[4][4];
    #pragma unroll
    for (int i = 0; i < 4; i++)
        #pragma unroll
        for (int e = 0; e < 4; e++) oacc[i][e] = 0.f;

    #pragma unroll
    for (int j = 0; j < 7; j++) {
        uint32_t aH[4], aL[4];
        #pragma unroll
        for (int q = 0; q < 2; q++) {
            float p0 = sacc[2 * j + q][0], p1 = sacc[2 * j + q][1];
            float p2 = sacc[2 * j + q][2], p3 = sacc[2 * j + q][3];
            aH[q * 2 + 0] = pack2bf(p0, p1);
            aH[q * 2 + 1] = pack2bf(p2, p3);
            aL[q * 2 + 0] = pack2bf(p0 - bf_hi(p0), p1 - bf_hi(p1));
            aL[q * 2 + 1] = pack2bf(p2 - bf_hi(p2), p3 - bf_hi(p3));
        }
        #pragma unroll
        for (int dg = 0; dg < 2; dg++) {
            uint32_t bbH[4], bbL[4];
            uint32_t boff = (uint32_t)(((j * 16 + vR) * 40 + vCol + dg * 16) * 2);
            ldsm4t(bVh + boff, bbH[0], bbH[1], bbH[2], bbH[3]);
            ldsm4t(bVl + boff, bbL[0], bbL[1], bbL[2], bbL[3]);
            mma_bf16(oacc[dg * 2 + 0], aH, &bbH[0]);
            mma_bf16(oacc[dg * 2 + 1], aH, &bbH[2]);
            mma_bf16(oacc[dg * 2 + 0], aH, &bbL[0]);
            mma_bf16(oacc[dg * 2 + 1], aH, &bbL[2]);
            mma_bf16(oacc[dg * 2 + 0], aL, &bbH[0]);
            mma_bf16(oacc[dg * 2 + 1], aL, &bbH[2]);
        }
    }

    #pragma unroll
    for (int h = 0; h < 2; h++) {
        int r = r0 + h * 8;
        if (r < NT) {
            size_t ob = ((size_t)bwin * NT + r) * Cz + head * HD;
            #pragma unroll
            for (int nt = 0; nt < 4; nt++) {
                int c = nt * 8 + cbase;
                *(uint32_t*)(g_aoh + ob + c) =
                    pack2bf(oacc[nt][h * 2 + 0], oacc[nt][h * 2 + 1]);
            }
        }
    }
}

// ---------------- 6: window reverse + unshift + residual + LN2 ----------------
__global__ void k_rev_res_ln2(const float* __restrict__ g2, const float* __restrict__ b2) {
    int t = blockIdx.x;
    int ft = map_token(t);
    int c = threadIdx.x;
    float v = g_po[(size_t)t * Cz + c] + g_xp[(size_t)ft * Cz + c];
    g_xres[(size_t)ft * Cz + c] = v;
    float m, inv;
    blockMeanVar(v, m, inv);
    float o = (v - m) * inv * g2[c] + b2[c];
    g_l2h[(size_t)ft * Cz + c] = __float2bfloat16(o);
}

// ---------------- 9: transpose out (B,D,H,W,C) -> (B,D,C,W,H) ----------------
__global__ void k_transpose_out(float* __restrict__ out) {
    __shared__ float tile[32][33];
    int bz = blockIdx.z;
    int bd = bz / Wz, w = bz % Wz;
    int h0 = blockIdx.x * 32, c0 = blockIdx.y * 32;
    #pragma unroll
    for (int j = 0; j < 32; j += 8) {
        int c = c0 + threadIdx.x;
        int h = h0 + threadIdx.y + j;
        if (h < Hz)
            tile[threadIdx.y + j][threadIdx.x] =
                g_y[(((size_t)bd * Hz + h) * Wz + w) * Cz + c];
    }
    __syncthreads();
    #pragma unroll
    for (int j = 0; j < 32; j += 8) {
        int h = h0 + threadIdx.x;
        int c = c0 + threadIdx.y + j;
        if (h < Hz)
            out[(((size_t)bd * Cz + c) * Wz + w) * Hz + h] =
                tile[threadIdx.x][threadIdx.y + j];
    }
}

// ---------------- launch ----------------
extern "C" void kernel_launch(void* const* d_in, const int* in_sizes, int n_in,
                              void* d_out, int out_size) {
    const float* x      = (const float*)d_in[0];
    const float* n1g    = (const float*)d_in[1];
    const float* n1b    = (const float*)d_in[2];
    const float* qkv_w  = (const float*)d_in[3];
    const float* rpb    = (const float*)d_in[4];
    const float* proj_w = (const float*)d_in[5];
    const float* proj_b = (const float*)d_in[6];
    const float* n2g    = (const float*)d_in[7];
    const float* n2b    = (const float*)d_in[8];
    const float* fc1_w  = (const float*)d_in[9];
    const float* fc1_b  = (const float*)d_in[10];
    const float* fc2_w  = (const float*)d_in[11];
    const float* fc2_b  = (const float*)d_in[12];
    float* out = (float*)d_out;

    void* p;
    cudaGetSymbolAddress(&p, g_po);   float* po   = (float*)p;
    cudaGetSymbolAddress(&p, g_xres); float* xres = (float*)p;
    cudaGetSymbolAddress(&p, g_y);    float* y    = (float*)p;
    cudaGetSymbolAddress(&p, g_xwh);  __nv_bfloat16* xwh = (__nv_bfloat16*)p;
    cudaGetSymbolAddress(&p, g_xwl);  __nv_bfloat16* xwl = (__nv_bfloat16*)p;
    cudaGetSymbolAddress(&p, g_qkvh); __nv_bfloat16* qkvh = (__nv_bfloat16*)p;
    cudaGetSymbolAddress(&p, g_qkvl); __nv_bfloat16* qkvl = (__nv_bfloat16*)p;
    cudaGetSymbolAddress(&p, g_aoh);  __nv_bfloat16* aoh = (__nv_bfloat16*)p;
    cudaGetSymbolAddress(&p, g_l2h);  __nv_bfloat16* l2h = (__nv_bfloat16*)p;
    cudaGetSymbolAddress(&p, g_hih);  __nv_bfloat16* hih = (__nv_bfloat16*)p;
    cudaGetSymbolAddress(&p, g_wqh);  __nv_bfloat16* wqh = (__nv_bfloat16*)p;
    cudaGetSymbolAddress(&p, g_wql);  __nv_bfloat16* wql = (__nv_bfloat16*)p;
    cudaGetSymbolAddress(&p, g_wph);  __nv_bfloat16* wph = (__nv_bfloat16*)p;
    cudaGetSymbolAddress(&p, g_w1h);  __nv_bfloat16* w1h = (__nv_bfloat16*)p;
    cudaGetSymbolAddress(&p, g_w2h);  __nv_bfloat16* w2h = (__nv_bfloat16*)p;
    cudaGetSymbolAddress(&p, g_wpl);  __nv_bfloat16* wpl = (__nv_bfloat16*)p;
    cudaGetSymbolAddress(&p, g_w1l);  __nv_bfloat16* w1l = (__nv_bfloat16*)p;
    cudaGetSymbolAddress(&p, g_w2l);  __nv_bfloat16* w2l = (__nv_bfloat16*)p;

    cudaFuncSetAttribute(k_attn_tc, cudaFuncAttributeMaxDynamicSharedMemorySize, ATTN_SMEM_TC);
    cudaFuncSetAttribute(k_gemm_bf<3, 0, false, false, 1, true>, cudaFuncAttributeMaxDynamicSharedMemorySize, 8 * PLANE_B);
    cudaFuncSetAttribute(k_gemm_bf<1, 0, true, false, 0, false>, cudaFuncAttributeMaxDynamicSharedMemorySize, 4 * PLANE_B);
    cudaFuncSetAttribute(k_gemm_bf<1, 1, true, false, 2, false>, cudaFuncAttributeMaxDynamicSharedMemorySize, 4 * PLANE_B);
    cudaFuncSetAttribute(k_gemm_bf<1, 0, true, true, 0, false>,  cudaFuncAttributeMaxDynamicSharedMemorySize, 4 * PLANE_B);

    dim3 tb(32, 8);
    dim3 tg(3, 8, Bz * Dz * Wz);

    // 0. weight splits + bias table (tiny)
    k_wsplit<<<(3 * Cz * Cz + 255) / 256, 256>>>(qkv_w, wqh, wql, 3 * Cz * Cz);
    k_wsplit<<<(Cz * Cz + 255) / 256, 256>>>(proj_w, wph, wpl, Cz * Cz);
    k_wsplit<<<(HID * Cz + 255) / 256, 256>>>(fc1_w, w1h, w1l, HID * Cz);
    k_wsplit<<<(Cz * HID + 255) / 256, 256>>>(fc2_w, w2h, w2l, Cz * HID);
    k_bias<<<64, 256>>>(rpb);
    // 1. transpose in
    k_transpose_in<<<tg, tb>>>(x);
    // 2. LN1 + shift + partition (split bf16 out)
    k_ln_part<<<TOK, 256>>>(n1g, n1b);
    // 3. qkv GEMM (3-pass, split bf16 out, Q pre-scaled)
    k_gemm_bf<3, 0, false, false, 1, true><<<dim3((3 * Cz) / 128, TOK / 128), 256, 8 * PLANE_B>>>(
        xwh, xwl, wqh, wql, nullptr, nullptr, nullptr, qkvh, qkvl, TOK, 3 * Cz, Cz);
    // 4. attention (tensor cores, precomputed bias)
    k_attn_tc<<<dim3(HEADS, BW), 224, ATTN_SMEM_TC>>>();
    // 5. proj GEMM (1-pass) -> g_po fp32
    k_gemm_bf<1, 0, true, false, 0, false><<<dim3(Cz / 128, TOK / 128), 256, 4 * PLANE_B>>>(
        aoh, nullptr, wph, nullptr, proj_b, nullptr, po, nullptr, nullptr, TOK, Cz, Cz);
    // 6. reverse + residual + LN2 (hi plane out)
    k_rev_res_ln2<<<TOK, 256>>>(n2g, n2b);
    // 7. fc1 GEMM (1-pass) + GELU -> hi plane
    k_gemm_bf<1, 1, true, false, 2, false><<<dim3(HID / 128, TOK / 128), 256, 4 * PLANE_B>>>(
        l2h, nullptr, w1h, nullptr, fc1_b, nullptr, nullptr, hih, nullptr, TOK, HID, Cz);
    // 8. fc2 GEMM (1-pass) + bias + residual -> y fp32
    k_gemm_bf<1, 0, true, true, 0, false><<<dim3(Cz / 128, TOK / 128), 256, 4 * PLANE_B>>>(
        hih, nullptr, w2h, nullptr, fc2_b, xres, y, nullptr, nullptr, TOK, Cz, HID);
    // 9. transpose out
    k_transpose_out<<<tg, tb>>>(out);
}

// round 11
// speedup vs baseline: 1.0839x; 1.0324x over previous
#include <cuda_runtime.h>
#include <cuda_bf16.h>
#include <math.h>
#include <stdint.h>

// ---------------- problem constants ----------------
#define Bz 2
#define Dz 8
#define Cz 256
#define Wz 84
#define Hz 84
#define HEADS 8
#define HD 32
#define NT 98            // tokens per window (2*7*7)
#define NTP 112          // padded to 7 x 16
#define NW 576           // windows per batch (4*12*12)
#define BW (Bz*NW)       // 1152 window-batches
#define TOK (BW*NT)      // 112896 tokens
#define HID 1024

// ---------------- scratch (device globals; allocation-free) ----------------
__device__ __align__(256) float g_xp  [(size_t)TOK*Cz];   // shortcut (B,D,H,W,C)
__device__ __align__(256) float g_po  [(size_t)TOK*Cz];   // proj output (windowed order)
__device__ __align__(256) float g_xres[(size_t)TOK*Cz];   // (B,D,H,W,C)
__device__ __align__(256) float g_y   [(size_t)TOK*Cz];
__device__ __align__(256) float g_bias[8 * HEADS * NTP * NTP];  // [cls][head][r][c]
// split bf16 activation planes
__device__ __align__(256) __nv_bfloat16 g_xwh[(size_t)TOK*Cz],   g_xwl[(size_t)TOK*Cz];
__device__ __align__(256) __nv_bfloat16 g_qkvh[(size_t)TOK*3*Cz], g_qkvl[(size_t)TOK*3*Cz];
__device__ __align__(256) __nv_bfloat16 g_aoh[(size_t)TOK*Cz];
__device__ __align__(256) __nv_bfloat16 g_l2h[(size_t)TOK*Cz];
__device__ __align__(256) __nv_bfloat16 g_hih[(size_t)TOK*HID];
// split bf16 weights
__device__ __align__(256) __nv_bfloat16 g_wqh[3*Cz*Cz], g_wql[3*Cz*Cz];
__device__ __align__(256) __nv_bfloat16 g_wph[Cz*Cz],   g_wpl[Cz*Cz];
__device__ __align__(256) __nv_bfloat16 g_w1h[HID*Cz],  g_w1l[HID*Cz];
__device__ __align__(256) __nv_bfloat16 g_w2h[Cz*HID],  g_w2l[Cz*HID];

// ---------------- helpers ----------------
__device__ __forceinline__ uint32_t smem_u32(const void* p) {
    uint32_t a;
    asm("{ .reg .u64 t; cvta.to.shared.u64 t, %1; cvt.u32.u64 %0, t; }" : "=r"(a) : "l"(p));
    return a;
}
__device__ __forceinline__ uint32_t pack2bf(float x, float y) {
    __nv_bfloat162 t = __floats2bfloat162_rn(x, y);
    return *(uint32_t*)&t;
}
__device__ __forceinline__ float bf_hi(float x) {
    return __bfloat162float(__float2bfloat16(x));
}
__device__ __forceinline__ void ldsm4(uint32_t addr, uint32_t& r0, uint32_t& r1,
                                      uint32_t& r2, uint32_t& r3) {
    asm volatile("ldmatrix.sync.aligned.m8n8.x4.shared.b16 {%0,%1,%2,%3}, [%4];"
                 : "=r"(r0), "=r"(r1), "=r"(r2), "=r"(r3) : "r"(addr));
}
__device__ __forceinline__ void ldsm4t(uint32_t addr, uint32_t& r0, uint32_t& r1,
                                       uint32_t& r2, uint32_t& r3) {
    asm volatile("ldmatrix.sync.aligned.m8n8.x4.trans.shared.b16 {%0,%1,%2,%3}, [%4];"
                 : "=r"(r0), "=r"(r1), "=r"(r2), "=r"(r3) : "r"(addr));
}
__device__ __forceinline__ void mma_bf16(float* d, const uint32_t* a, const uint32_t* b) {
    asm volatile(
        "mma.sync.aligned.m16n8k16.row.col.f32.bf16.bf16.f32 "
        "{%0,%1,%2,%3}, {%4,%5,%6,%7}, {%8,%9}, {%0,%1,%2,%3};"
        : "+f"(d[0]), "+f"(d[1]), "+f"(d[2]), "+f"(d[3])
        : "r"(a[0]), "r"(a[1]), "r"(a[2]), "r"(a[3]), "r"(b[0]), "r"(b[1]));
}
__device__ __forceinline__ void cpasync16(uint32_t dst, const void* src) {
    asm volatile("cp.async.cg.shared.global [%0], [%1], 16;" :: "r"(dst), "l"(src));
}

// ---------------- 0a: weight split ----------------
__global__ void k_wsplit(const float* __restrict__ src, __nv_bfloat16* __restrict__ hi,
                         __nv_bfloat16* __restrict__ lo, int n) {
    int i = blockIdx.x * 256 + threadIdx.x;
    if (i < n) {
        float v = src[i];
        float h = bf_hi(v);
        hi[i] = __float2bfloat16(v);
        lo[i] = __float2bfloat16(v - h);
    }
}

// ---------------- 0b: precompute bias+mask per (class, head) ----------------
__global__ void k_bias(const float* __restrict__ rpb) {
    int blk = blockIdx.x;          // cls*8 + head
    int cls = blk >> 3, head = blk & 7;
    float* outp = g_bias + (size_t)blk * NTP * NTP;
    for (int i = threadIdx.x; i < NTP * NTP; i += 256) {
        int r = i / NTP, c = i % NTP;
        float v;
        if (r < NT && c < NT) {
            int dr = r / 49, hr = (r % 49) / 7, wr = r % 7;
            int dc = c / 49, hc = (c % 49) / 7, wc = c % 7;
            int idx = (dr - dc + 1) * 169 + (hr - hc + 6) * 13 + (wr - wc + 6);
            int rgr = ((cls & 4) ? (dr == 0 ? 1 : 2) : 0) * 9
                    + ((cls & 2) ? (hr < 4 ? 1 : 2) : 0) * 3
                    + ((cls & 1) ? (wr < 4 ? 1 : 2) : 0);
            int rgc = ((cls & 4) ? (dc == 0 ? 1 : 2) : 0) * 9
                    + ((cls & 2) ? (hc < 4 ? 1 : 2) : 0) * 3
                    + ((cls & 1) ? (wc < 4 ? 1 : 2) : 0);
            v = rpb[idx * HEADS + head] + (rgr != rgc ? -100.f : 0.f);
        } else {
            v = -30000.f;
        }
        outp[i] = v;
    }
}

// ---------------- 1: transpose in (B,D,C,W,H) -> (B,D,H,W,C) ----------------
__global__ void k_transpose_in(const float* __restrict__ x) {
    __shared__ float tile[32][33];
    int bz = blockIdx.z;
    int bd = bz / Wz, w = bz % Wz;
    int h0 = blockIdx.x * 32, c0 = blockIdx.y * 32;
    #pragma unroll
    for (int j = 0; j < 32; j += 8) {
        int c = c0 + threadIdx.y + j;
        int h = h0 + threadIdx.x;
        if (h < Hz)
            tile[threadIdx.y + j][threadIdx.x] =
                x[(((size_t)bd * Cz + c) * Wz + w) * Hz + h];
    }
    __syncthreads();
    #pragma unroll
    for (int j = 0; j < 32; j += 8) {
        int c = c0 + threadIdx.x;
        int h = h0 + threadIdx.y + j;
        if (h < Hz)
            g_xp[(((size_t)bd * Hz + h) * Wz + w) * Cz + c] =
                tile[threadIdx.x][threadIdx.y + j];
    }
}

__device__ __forceinline__ int map_token(int t) {
    int b   = t / (NW * NT);
    int rem = t % (NW * NT);
    int wi = rem / NT, n = rem % NT;
    int d2 = wi / 144, h2 = (wi / 12) % 12, w2 = wi % 12;
    int dd = n / 49, r = n % 49, hh = r / 7, ww = r % 7;
    int d = d2 * 2 + dd, h = h2 * 7 + hh, w = w2 * 7 + ww;
    int ds = (d + 1) & 7;
    int hs = h + 3; if (hs >= Hz) hs -= Hz;
    int ws = w + 3; if (ws >= Wz) ws -= Wz;
    return ((b * Dz + ds) * Hz + hs) * Wz + ws;
}

__device__ __forceinline__ void blockMeanVar(float v, float& mean, float& invstd) {
    __shared__ float sbuf[16];
    float s1 = v, s2 = v * v;
    #pragma unroll
    for (int o = 16; o; o >>= 1) {
        s1 += __shfl_down_sync(0xffffffffu, s1, o);
        s2 += __shfl_down_sync(0xffffffffu, s2, o);
    }
    int wp = threadIdx.x >> 5, ln = threadIdx.x & 31;
    if (!ln) { sbuf[wp] = s1; sbuf[8 + wp] = s2; }
    __syncthreads();
    float m = 0.f, q = 0.f;
    #pragma unroll
    for (int i = 0; i < 8; i++) { m += sbuf[i]; q += sbuf[8 + i]; }
    m *= (1.f / Cz);
    q = q * (1.f / Cz) - m * m;
    mean = m;
    invstd = rsqrtf(q + 1e-5f);
}

// ---------------- 2: LN1 + shift + partition -> split bf16 ----------------
__global__ void k_ln_part(const float* __restrict__ g, const float* __restrict__ bta) {
    int t = blockIdx.x;
    int srct = map_token(t);
    int c = threadIdx.x;
    float v = g_xp[(size_t)srct * Cz + c];
    float m, inv;
    blockMeanVar(v, m, inv);
    float o = (v - m) * inv * g[c] + bta[c];
    float oh = bf_hi(o);
    g_xwh[(size_t)t * Cz + c] = __float2bfloat16(o);
    g_xwl[(size_t)t * Cz + c] = __float2bfloat16(o - oh);
}

// ---------------- GEMM: out[M,N] = A[M,K] @ Wt[N,K]^T --------------------
// PASSES=3: split-bf16 hi/lo, 3 mma passes. PASSES=1: hi only.
// OSPLIT: 0 = fp32 out, 1 = bf16 hi+lo planes, 2 = bf16 hi plane only.
// QSCALE: scale output columns n < Cz by 1/sqrt(HD).
// ostr: output (and res) row stride in elements (>= N; for sub-column writes).
#define PADK 40
#define PLANE_B (128 * PADK * 2)       // 10240 bytes
template <int PASSES, int ACT, bool HAS_BIAS, bool HAS_RES, int OSPLIT, bool QSCALE>
__global__ __launch_bounds__(256, 2) void k_gemm_bf(
    const __nv_bfloat16* __restrict__ Ah, const __nv_bfloat16* __restrict__ Al,
    const __nv_bfloat16* __restrict__ Bh, const __nv_bfloat16* __restrict__ Bl,
    const float* __restrict__ bias, const float* __restrict__ res,
    float* __restrict__ out,
    __nv_bfloat16* __restrict__ outh, __nv_bfloat16* __restrict__ outl,
    int M, int N, int K, int ostr) {
    extern __shared__ __align__(16) unsigned char dsm[];
    constexpr int NPL = (PASSES == 3) ? 4 : 2;
    constexpr int STB = NPL * PLANE_B;
    uint32_t sbase = smem_u32(dsm);
    int tid = threadIdx.x, lane = tid & 31, wid = tid >> 5;
    int bm = blockIdx.y * 128, bn = blockIdx.x * 128;
    int wm = (wid & 1) * 64, wn = (wid >> 1) * 32;

    int aRow = wm + (lane & 15);
    int aCol = (lane >> 4) * 8;
    int bRow = wn + ((lane >> 4) << 3) + (lane & 7);
    int bCol = ((lane >> 3) & 1) * 8;

    float acc[4][4][4];
    #pragma unroll
    for (int i = 0; i < 4; i++)
        #pragma unroll
        for (int j = 0; j < 4; j++)
            #pragma unroll
            for (int c = 0; c < 4; c++) acc[i][j][c] = 0.f;

    const int nChunks = K >> 5;

    #define ISSUE(ch, s) do {                                                   \
        int k0_ = (ch) << 5;                                                    \
        uint32_t sb_ = sbase + (s) * STB;                                       \
        _Pragma("unroll")                                                       \
        for (int q_ = 0; q_ < 2; q_++) {                                        \
            int j_ = q_ * 256 + tid;                                            \
            int row_ = j_ >> 2, c8_ = (j_ & 3) * 8;                             \
            uint32_t so_ = (uint32_t)((row_ * PADK + c8_) * 2);                 \
            size_t ga_ = (size_t)(bm + row_) * K + k0_ + c8_;                   \
            size_t gb_ = (size_t)(bn + row_) * K + k0_ + c8_;                   \
            cpasync16(sb_ + 0 * PLANE_B + so_, Ah + ga_);                       \
            if (PASSES == 3) cpasync16(sb_ + 1 * PLANE_B + so_, Al + ga_);      \
            cpasync16(sb_ + (PASSES == 3 ? 2 : 1) * PLANE_B + so_, Bh + gb_);   \
            if (PASSES == 3) cpasync16(sb_ + 3 * PLANE_B + so_, Bl + gb_);      \
        }                                                                       \
        asm volatile("cp.async.commit_group;");                                 \
    } while (0)

    ISSUE(0, 0);
    for (int ch = 0; ch < nChunks; ch++) {
        int s = ch & 1;
        if (ch + 1 < nChunks) {
            ISSUE(ch + 1, (ch + 1) & 1);
            asm volatile("cp.async.wait_group 1;");
        } else {
            asm volatile("cp.async.wait_group 0;");
        }
        __syncthreads();

        uint32_t baseAH = sbase + s * STB;
        uint32_t baseAL = baseAH + PLANE_B;
        uint32_t baseBH = baseAH + (PASSES == 3 ? 2 : 1) * PLANE_B;
        uint32_t baseBL = baseAH + 3 * PLANE_B;

        #pragma unroll
        for (int kk = 0; kk < 2; kk++) {
            int k0 = kk * 16;
            uint32_t aH[4][4], aL[4][4], bb[8];
            #pragma unroll
            for (int mi = 0; mi < 4; mi++) {
                uint32_t off = (uint32_t)(((aRow + mi * 16) * PADK + k0 + aCol) * 2);
                ldsm4(baseAH + off, aH[mi][0], aH[mi][1], aH[mi][2], aH[mi][3]);
                if (PASSES == 3)
                    ldsm4(baseAL + off, aL[mi][0], aL[mi][1], aL[mi][2], aL[mi][3]);
            }
            #pragma unroll
            for (int p = 0; p < 2; p++) {
                uint32_t off = (uint32_t)(((bRow + p * 16) * PADK + k0 + bCol) * 2);
                ldsm4(baseBH + off, bb[p * 4 + 0], bb[p * 4 + 1], bb[p * 4 + 2], bb[p * 4 + 3]);
            }
            #pragma unroll
            for (int mi = 0; mi < 4; mi++)
                #pragma unroll
                for (int ni = 0; ni < 4; ni++)
                    mma_bf16(acc[mi][ni], aH[mi], &bb[ni * 2]);
            if (PASSES == 3) {
                #pragma unroll
                for (int mi = 0; mi < 4; mi++)
                    #pragma unroll
                    for (int ni = 0; ni < 4; ni++)
                        mma_bf16(acc[mi][ni], aL[mi], &bb[ni * 2]);
                #pragma unroll
                for (int p = 0; p < 2; p++) {
                    uint32_t off = (uint32_t)(((bRow + p * 16) * PADK + k0 + bCol) * 2);
                    ldsm4(baseBL + off, bb[p * 4 + 0], bb[p * 4 + 1], bb[p * 4 + 2], bb[p * 4 + 3]);
                }
                #pragma unroll
                for (int mi = 0; mi < 4; mi++)
                    #pragma unroll
                    for (int ni = 0; ni < 4; ni++)
                        mma_bf16(acc[mi][ni], aH[mi], &bb[ni * 2]);
            }
        }
        __syncthreads();
    }
    #undef ISSUE

    int orow = lane >> 2, ocol = (lane & 3) * 2;
    #pragma unroll
    for (int mi = 0; mi < 4; mi++) {
        int m0 = bm + wm + mi * 16;
        #pragma unroll
        for (int ni = 0; ni < 4; ni++) {
            int n = bn + wn + ni * 8 + ocol;
            float bi0 = 0.f, bi1 = 0.f;
            if (HAS_BIAS) { bi0 = bias[n]; bi1 = bias[n + 1]; }
            float sc = (QSCALE && n < Cz) ? 0.17677669529663687f : 1.f;
            #pragma unroll
            for (int half = 0; half < 2; half++) {
                int m = m0 + orow + half * 8;
                float v0 = acc[mi][ni][half * 2 + 0] + bi0;
                float v1 = acc[mi][ni][half * 2 + 1] + bi1;
                if (QSCALE) { v0 *= sc; v1 *= sc; }
                if (ACT == 1) {
                    v0 = 0.5f * v0 * (1.f + erff(v0 * 0.70710678118654752f));
                    v1 = 0.5f * v1 * (1.f + erff(v1 * 0.70710678118654752f));
                }
                if (HAS_RES) {
                    const float2 r2 = *(const float2*)(res + (size_t)m * ostr + n);
                    v0 += r2.x; v1 += r2.y;
                }
                if (OSPLIT == 1) {
                    *(uint32_t*)(outh + (size_t)m * ostr + n) = pack2bf(v0, v1);
                    *(uint32_t*)(outl + (size_t)m * ostr + n) =
                        pack2bf(v0 - bf_hi(v0), v1 - bf_hi(v1));
                } else if (OSPLIT == 2) {
                    *(uint32_t*)(outh + (size_t)m * ostr + n) = pack2bf(v0, v1);
                } else {
                    *(float2*)(out + (size_t)m * ostr + n) = make_float2(v0, v1);
                }
            }
        }
    }
}

// ---------------- 4: tensor-core attention per (head, window) ----------------
#define APL (NTP * 40)                 // 4480 halves per plane
#define ATTN_SMEM_TC (6 * APL * 2)     // 53760 bytes
__global__ __launch_bounds__(224, 2) void k_attn_tc() {
    extern __shared__ __nv_bfloat16 asm_[];
    int head = blockIdx.x, bwin = blockIdx.y;
    int tid = threadIdx.x, lane = tid & 31, wid = tid >> 5;
    uint32_t sbase = smem_u32(asm_);

    // zero pad rows 98..111 of all 6 planes
    for (int i = tid; i < 6 * 280; i += 224) {
        int p = i / 280, r = i % 280;
        ((uint32_t*)(asm_ + p * APL + NT * 40))[r] = 0u;
    }

    // fill: 98 tokens x {q,k,v} x {hi,lo} x 4 x 16B cp.async copies
    for (int i = tid; i < 98 * 6 * 4; i += 224) {
        int chunk = i & 3;
        int idx = i >> 2;
        int n = idx / 6, which = idx % 6;
        int sel = which >> 1, pl = which & 1;
        const __nv_bfloat16* src = (pl ? g_qkvl : g_qkvh)
            + (size_t)(bwin * NT + n) * (3 * Cz) + sel * Cz + head * HD + chunk * 8;
        uint32_t dst = sbase + (uint32_t)(((sel * 2 + pl) * APL + n * 40 + chunk * 8) * 2);
        cpasync16(dst, src);
    }
    asm volatile("cp.async.commit_group;");
    asm volatile("cp.async.wait_group 0;");
    __syncthreads();

    // window boundary class -> precomputed bias+mask slab
    int wi = bwin % NW;
    int cls = ((wi / 144) == 3 ? 4 : 0) | (((wi / 12) % 12) == 11 ? 2 : 0)
            | ((wi % 12) == 11 ? 1 : 0);
    const float* Bm = g_bias + (size_t)(cls * HEADS + head) * NTP * NTP;

    uint32_t bQh = sbase,            bQl = sbase + APL * 2;
    uint32_t bKh = sbase + 2*APL*2,  bKl = sbase + 3*APL*2;
    uint32_t bVh = sbase + 4*APL*2,  bVl = sbase + 5*APL*2;

    int wm = wid * 16;
    int aRow = wm + (lane & 15);
    int aCol = (lane >> 4) * 8;
    int bR = ((lane >> 4) << 3) + (lane & 7);
    int bCol = ((lane >> 3) & 1) * 8;
    int vR = ((lane >> 3) & 1) * 8 + (lane & 7);
    int vCol = (lane >> 4) * 8;

    float sacc[14][4];
    #pragma unroll
    for (int t = 0; t < 14; t++)
        #pragma unroll
        for (int e = 0; e < 4; e++) sacc[t][e] = 0.f;

    #pragma unroll
    for (int kk = 0; kk < 2; kk++) {
        int k0 = kk * 16;
        uint32_t aH[4], aL[4], bbH[4], bbL[4];
        uint32_t aoff = (uint32_t)((aRow * 40 + k0 + aCol) * 2);
        ldsm4(bQh + aoff, aH[0], aH[1], aH[2], aH[3]);
        ldsm4(bQl + aoff, aL[0], aL[1], aL[2], aL[3]);
        #pragma unroll
        for (int nt = 0; nt < 7; nt++) {
            uint32_t boff = (uint32_t)(((nt * 16 + bR) * 40 + k0 + bCol) * 2);
            ldsm4(bKh + boff, bbH[0], bbH[1], bbH[2], bbH[3]);
            ldsm4(bKl + boff, bbL[0], bbL[1], bbL[2], bbL[3]);
            mma_bf16(sacc[nt * 2 + 0], aH, &bbH[0]);
            mma_bf16(sacc[nt * 2 + 1], aH, &bbH[2]);
            mma_bf16(sacc[nt * 2 + 0], aH, &bbL[0]);
            mma_bf16(sacc[nt * 2 + 1], aH, &bbL[2]);
            mma_bf16(sacc[nt * 2 + 0], aL, &bbH[0]);
            mma_bf16(sacc[nt * 2 + 1], aL, &bbH[2]);
        }
    }

    // precomputed bias/mask add (Q already scaled in qkv epilogue)
    int r0 = wm + (lane >> 2);
    int cbase = (lane & 3) * 2;
    #pragma unroll
    for (int h = 0; h < 2; h++) {
        int r = r0 + h * 8;
        const float2* brow = (const float2*)(Bm + (size_t)r * NTP);
        #pragma unroll
        for (int t = 0; t < 14; t++) {
            float2 bb = brow[t * 4 + (lane & 3)];
            sacc[t][h * 2 + 0] += bb.x;
            sacc[t][h * 2 + 1] += bb.y;
        }
    }

    // softmax in regs (row = quad of lanes)
    #pragma unroll
    for (int h = 0; h < 2; h++) {
        float mx = -1e30f;
        #pragma unroll
        for (int t = 0; t < 14; t++) {
            mx = fmaxf(mx, sacc[t][h * 2 + 0]);
            mx = fmaxf(mx, sacc[t][h * 2 + 1]);
        }
        mx = fmaxf(mx, __shfl_xor_sync(0xffffffffu, mx, 1));
        mx = fmaxf(mx, __shfl_xor_sync(0xffffffffu, mx, 2));
        float sum = 0.f;
        #pragma unroll
        for (int t = 0; t < 14; t++) {
            #pragma unroll
            for (int e = 0; e < 2; e++) {
                float v = __expf(sacc[t][h * 2 + e] - mx);
                sacc[t][h * 2 + e] = v;
                sum += v;
            }
        }
        sum += __shfl_xor_sync(0xffffffffu, sum, 1);
        sum += __shfl_xor_sync(0xffffffffu, sum, 2);
        float inv = 1.f / sum;
        #pragma unroll
        for (int t = 0; t < 14; t++) {
            sacc[t][h * 2 + 0] *= inv;
            sacc[t][h * 2 + 1] *= inv;
        }
    }

    // P @ V (3-pass; V via trans-ldmatrix)
    float oacc[4][4];
    #pragma unroll
    for (int i = 0; i < 4; i++)
        #pragma unroll
        for (int e = 0; e < 4; e++) oacc[i][e] = 0.f;

    #pragma unroll
    for (int j = 0; j < 7; j++) {
        uint32_t aH[4], aL[4];
        #pragma unroll
        for (int q = 0; q < 2; q++) {
            float p0 = sacc[2 * j + q][0], p1 = sacc[2 * j + q][1];
            float p2 = sacc[2 * j + q][2], p3 = sacc[2 * j + q][3];
            aH[q * 2 + 0] = pack2bf(p0, p1);
            aH[q * 2 + 1] = pack2bf(p2, p3);
            aL[q * 2 + 0] = pack2bf(p0 - bf_hi(p0), p1 - bf_hi(p1));
            aL[q * 2 + 1] = pack2bf(p2 - bf_hi(p2), p3 - bf_hi(p3));
        }
        #pragma unroll
        for (int dg = 0; dg < 2; dg++) {
            uint32_t bbH[4], bbL[4];
            uint32_t boff = (uint32_t)(((j * 16 + vR) * 40 + vCol + dg * 16) * 2);
            ldsm4t(bVh + boff, bbH[0], bbH[1], bbH[2], bbH[3]);
            ldsm4t(bVl + boff, bbL[0], bbL[1], bbL[2], bbL[3]);
            mma_bf16(oacc[dg * 2 + 0], aH, &bbH[0]);
            mma_bf16(oacc[dg * 2 + 1], aH, &bbH[2]);
            mma_bf16(oacc[dg * 2 + 0], aH, &bbL[0]);
            mma_bf16(oacc[dg * 2 + 1], aH, &bbL[2]);
            mma_bf16(oacc[dg * 2 + 0], aL, &bbH[0]);
            mma_bf16(oacc[dg * 2 + 1], aL, &bbH[2]);
        }
    }

    #pragma unroll
    for (int h = 0; h < 2; h++) {
        int r = r0 + h * 8;
        if (r < NT) {
            size_t ob = ((size_t)bwin * NT + r) * Cz + head * HD;
            #pragma unroll
            for (int nt = 0; nt < 4; nt++) {
                int c = nt * 8 + cbase;
                *(uint32_t*)(g_aoh + ob + c) =
                    pack2bf(oacc[nt][h * 2 + 0], oacc[nt][h * 2 + 1]);
            }
        }
    }
}

// ---------------- 6: window reverse + unshift + residual + LN2 ----------------
__global__ void k_rev_res_ln2(const float* __restrict__ g2, const float* __restrict__ b2) {
    int t = blockIdx.x;
    int ft = map_token(t);
    int c = threadIdx.x;
    float v = g_po[(size_t)t * Cz + c] + g_xp[(size_t)ft * Cz + c];
    g_xres[(size_t)ft * Cz + c] = v;
    float m, inv;
    blockMeanVar(v, m, inv);
    float o = (v - m) * inv * g2[c] + b2[c];
    g_l2h[(size_t)ft * Cz + c] = __float2bfloat16(o);
}

// ---------------- 9: transpose out (B,D,H,W,C) -> (B,D,C,W,H) ----------------
__global__ void k_transpose_out(float* __restrict__ out) {
    __shared__ float tile[32][33];
    int bz = blockIdx.z;
    int bd = bz / Wz, w = bz % Wz;
    int h0 = blockIdx.x * 32, c0 = blockIdx.y * 32;
    #pragma unroll
    for (int j = 0; j < 32; j += 8) {
        int c = c0 + threadIdx.x;
        int h = h0 + threadIdx.y + j;
        if (h < Hz)
            tile[threadIdx.y + j][threadIdx.x] =
                g_y[(((size_t)bd * Hz + h) * Wz + w) * Cz + c];
    }
    __syncthreads();
    #pragma unroll
    for (int j = 0; j < 32; j += 8) {
        int h = h0 + threadIdx.x;
        int c = c0 + threadIdx.y + j;
        if (h < Hz)
            out[(((size_t)bd * Cz + c) * Wz + w) * Hz + h] =
                tile[threadIdx.x][threadIdx.y + j];
    }
}

// ---------------- launch ----------------
extern "C" void kernel_launch(void* const* d_in, const int* in_sizes, int n_in,
                              void* d_out, int out_size) {
    const float* x      = (const float*)d_in[0];
    const float* n1g    = (const float*)d_in[1];
    const float* n1b    = (const float*)d_in[2];
    const float* qkv_w  = (const float*)d_in[3];
    const float* rpb    = (const float*)d_in[4];
    const float* proj_w = (const float*)d_in[5];
    const float* proj_b = (const float*)d_in[6];
    const float* n2g    = (const float*)d_in[7];
    const float* n2b    = (const float*)d_in[8];
    const float* fc1_w  = (const float*)d_in[9];
    const float* fc1_b  = (const float*)d_in[10];
    const float* fc2_w  = (const float*)d_in[11];
    const float* fc2_b  = (const float*)d_in[12];
    float* out = (float*)d_out;

    void* p;
    cudaGetSymbolAddress(&p, g_po);   float* po   = (float*)p;
    cudaGetSymbolAddress(&p, g_xres); float* xres = (float*)p;
    cudaGetSymbolAddress(&p, g_y);    float* y    = (float*)p;
    cudaGetSymbolAddress(&p, g_xwh);  __nv_bfloat16* xwh = (__nv_bfloat16*)p;
    cudaGetSymbolAddress(&p, g_xwl);  __nv_bfloat16* xwl = (__nv_bfloat16*)p;
    cudaGetSymbolAddress(&p, g_qkvh); __nv_bfloat16* qkvh = (__nv_bfloat16*)p;
    cudaGetSymbolAddress(&p, g_qkvl); __nv_bfloat16* qkvl = (__nv_bfloat16*)p;
    cudaGetSymbolAddress(&p, g_aoh);  __nv_bfloat16* aoh = (__nv_bfloat16*)p;
    cudaGetSymbolAddress(&p, g_l2h);  __nv_bfloat16* l2h = (__nv_bfloat16*)p;
    cudaGetSymbolAddress(&p, g_hih);  __nv_bfloat16* hih = (__nv_bfloat16*)p;
    cudaGetSymbolAddress(&p, g_wqh);  __nv_bfloat16* wqh = (__nv_bfloat16*)p;
    cudaGetSymbolAddress(&p, g_wql);  __nv_bfloat16* wql = (__nv_bfloat16*)p;
    cudaGetSymbolAddress(&p, g_wph);  __nv_bfloat16* wph = (__nv_bfloat16*)p;
    cudaGetSymbolAddress(&p, g_w1h);  __nv_bfloat16* w1h = (__nv_bfloat16*)p;
    cudaGetSymbolAddress(&p, g_w2h);  __nv_bfloat16* w2h = (__nv_bfloat16*)p;
    cudaGetSymbolAddress(&p, g_wpl);  __nv_bfloat16* wpl = (__nv_bfloat16*)p;
    cudaGetSymbolAddress(&p, g_w1l);  __nv_bfloat16* w1l = (__nv_bfloat16*)p;
    cudaGetSymbolAddress(&p, g_w2l);  __nv_bfloat16* w2l = (__nv_bfloat16*)p;

    cudaFuncSetAttribute(k_attn_tc, cudaFuncAttributeMaxDynamicSharedMemorySize, ATTN_SMEM_TC);
    cudaFuncSetAttribute(k_gemm_bf<3, 0, false, false, 1, true>,  cudaFuncAttributeMaxDynamicSharedMemorySize, 8 * PLANE_B);
    cudaFuncSetAttribute(k_gemm_bf<1, 0, false, false, 1, false>, cudaFuncAttributeMaxDynamicSharedMemorySize, 4 * PLANE_B);
    cudaFuncSetAttribute(k_gemm_bf<1, 0, true, false, 0, false>,  cudaFuncAttributeMaxDynamicSharedMemorySize, 4 * PLANE_B);
    cudaFuncSetAttribute(k_gemm_bf<1, 1, true, false, 2, false>,  cudaFuncAttributeMaxDynamicSharedMemorySize, 4 * PLANE_B);
    cudaFuncSetAttribute(k_gemm_bf<1, 0, true, true, 0, false>,   cudaFuncAttributeMaxDynamicSharedMemorySize, 4 * PLANE_B);

    dim3 tb(32, 8);
    dim3 tg(3, 8, Bz * Dz * Wz);

    // 0. weight splits + bias table (tiny)
    k_wsplit<<<(3 * Cz * Cz + 255) / 256, 256>>>(qkv_w, wqh, wql, 3 * Cz * Cz);
    k_wsplit<<<(Cz * Cz + 255) / 256, 256>>>(proj_w, wph, wpl, Cz * Cz);
    k_wsplit<<<(HID * Cz + 255) / 256, 256>>>(fc1_w, w1h, w1l, HID * Cz);
    k_wsplit<<<(Cz * HID + 255) / 256, 256>>>(fc2_w, w2h, w2l, Cz * HID);
    k_bias<<<64, 256>>>(rpb);
    // 1. transpose in
    k_transpose_in<<<tg, tb>>>(x);
    // 2. LN1 + shift + partition (split bf16 out)
    k_ln_part<<<TOK, 256>>>(n1g, n1b);
    // 3a. QK GEMM (3-pass, N=512, split out with stride 768, Q pre-scaled)
    k_gemm_bf<3, 0, false, false, 1, true><<<dim3(4, TOK / 128), 256, 8 * PLANE_B>>>(
        xwh, xwl, wqh, wql, nullptr, nullptr, nullptr, qkvh, qkvl,
        TOK, 2 * Cz, Cz, 3 * Cz);
    // 3b. V GEMM (1-pass, N=256, split out with stride 768)
    k_gemm_bf<1, 0, false, false, 1, false><<<dim3(2, TOK / 128), 256, 4 * PLANE_B>>>(
        xwh, nullptr, wqh + (size_t)2 * Cz * Cz, nullptr, nullptr, nullptr, nullptr,
        qkvh + 2 * Cz, qkvl + 2 * Cz, TOK, Cz, Cz, 3 * Cz);
    // 4. attention (tensor cores, precomputed bias)
    k_attn_tc<<<dim3(HEADS, BW), 224, ATTN_SMEM_TC>>>();
    // 5. proj GEMM (1-pass) -> g_po fp32
    k_gemm_bf<1, 0, true, false, 0, false><<<dim3(Cz / 128, TOK / 128), 256, 4 * PLANE_B>>>(
        aoh, nullptr, wph, nullptr, proj_b, nullptr, po, nullptr, nullptr, TOK, Cz, Cz, Cz);
    // 6. reverse + residual + LN2 (hi plane out)
    k_rev_res_ln2<<<TOK, 256>>>(n2g, n2b);
    // 7. fc1 GEMM (1-pass) + GELU -> hi plane
    k_gemm_bf<1, 1, true, false, 2, false><<<dim3(HID / 128, TOK / 128), 256, 4 * PLANE_B>>>(
        l2h, nullptr, w1h, nullptr, fc1_b, nullptr, nullptr, hih, nullptr, TOK, HID, Cz, HID);
    // 8. fc2 GEMM (1-pass) + bias + residual -> y fp32
    k_gemm_bf<1, 0, true, true, 0, false><<<dim3(Cz / 128, TOK / 128), 256, 4 * PLANE_B>>>(
        hih, nullptr, w2h, nullptr, fc2_b, xres, y, nullptr, nullptr, TOK, Cz, HID, Cz);
    // 9. transpose out
    k_transpose_out<<<tg, tb>>>(out);
}

// round 12
// speedup vs baseline: 1.2591x; 1.1616x over previous
#include <cuda_runtime.h>
#include <cuda_bf16.h>
#include <math.h>
#include <stdint.h>

// ---------------- problem constants ----------------
#define Bz 2
#define Dz 8
#define Cz 256
#define Wz 84
#define Hz 84
#define HEADS 8
#define HD 32
#define NT 98            // tokens per window (2*7*7)
#define NTP 112          // padded to 7 x 16
#define NW 576           // windows per batch (4*12*12)
#define BW (Bz*NW)       // 1152 window-batches
#define TOK (BW*NT)      // 112896 tokens
#define HID 1024

// ---------------- scratch (device globals; allocation-free) ----------------
__device__ __align__(256) float g_xp  [(size_t)TOK*Cz];   // shortcut (B,D,H,W,C)
__device__ __align__(256) float g_po  [(size_t)TOK*Cz];   // proj output (windowed order)
__device__ __align__(256) float g_xres[(size_t)TOK*Cz];   // (B,D,H,W,C)
__device__ __align__(256) float g_y   [(size_t)TOK*Cz];
__device__ __align__(256) float g_bias[8 * HEADS * NTP * NTP];  // [cls][head][r][c]
// split bf16 activation planes
__device__ __align__(256) __nv_bfloat16 g_xwh[(size_t)TOK*Cz],   g_xwl[(size_t)TOK*Cz];
__device__ __align__(256) __nv_bfloat16 g_qkvh[(size_t)TOK*3*Cz], g_qkvl[(size_t)TOK*3*Cz];
__device__ __align__(256) __nv_bfloat16 g_aoh[(size_t)TOK*Cz];
__device__ __align__(256) __nv_bfloat16 g_l2h[(size_t)TOK*Cz];
__device__ __align__(256) __nv_bfloat16 g_hih[(size_t)TOK*HID];
// split bf16 weights
__device__ __align__(256) __nv_bfloat16 g_wqh[3*Cz*Cz], g_wql[3*Cz*Cz];
__device__ __align__(256) __nv_bfloat16 g_wph[Cz*Cz],   g_wpl[Cz*Cz];
__device__ __align__(256) __nv_bfloat16 g_w1h[HID*Cz],  g_w1l[HID*Cz];
__device__ __align__(256) __nv_bfloat16 g_w2h[Cz*HID],  g_w2l[Cz*HID];

// ---------------- helpers ----------------
__device__ __forceinline__ uint32_t smem_u32(const void* p) {
    uint32_t a;
    asm("{ .reg .u64 t; cvta.to.shared.u64 t, %1; cvt.u32.u64 %0, t; }" : "=r"(a) : "l"(p));
    return a;
}
__device__ __forceinline__ uint32_t pack2bf(float x, float y) {
    __nv_bfloat162 t = __floats2bfloat162_rn(x, y);
    return *(uint32_t*)&t;
}
__device__ __forceinline__ float bf_hi(float x) {
    return __bfloat162float(__float2bfloat16(x));
}
__device__ __forceinline__ void ldsm4(uint32_t addr, uint32_t& r0, uint32_t& r1,
                                      uint32_t& r2, uint32_t& r3) {
    asm volatile("ldmatrix.sync.aligned.m8n8.x4.shared.b16 {%0,%1,%2,%3}, [%4];"
                 : "=r"(r0), "=r"(r1), "=r"(r2), "=r"(r3) : "r"(addr));
}
__device__ __forceinline__ void ldsm4t(uint32_t addr, uint32_t& r0, uint32_t& r1,
                                       uint32_t& r2, uint32_t& r3) {
    asm volatile("ldmatrix.sync.aligned.m8n8.x4.trans.shared.b16 {%0,%1,%2,%3}, [%4];"
                 : "=r"(r0), "=r"(r1), "=r"(r2), "=r"(r3) : "r"(addr));
}
__device__ __forceinline__ void mma_bf16(float* d, const uint32_t* a, const uint32_t* b) {
    asm volatile(
        "mma.sync.aligned.m16n8k16.row.col.f32.bf16.bf16.f32 "
        "{%0,%1,%2,%3}, {%4,%5,%6,%7}, {%8,%9}, {%0,%1,%2,%3};"
        : "+f"(d[0]), "+f"(d[1]), "+f"(d[2]), "+f"(d[3])
        : "r"(a[0]), "r"(a[1]), "r"(a[2]), "r"(a[3]), "r"(b[0]), "r"(b[1]));
}
__device__ __forceinline__ void cpasync16(uint32_t dst, const void* src) {
    asm volatile("cp.async.cg.shared.global [%0], [%1], 16;" :: "r"(dst), "l"(src));
}

// ---------------- 0a: weight split ----------------
__global__ void k_wsplit(const float* __restrict__ src, __nv_bfloat16* __restrict__ hi,
                         __nv_bfloat16* __restrict__ lo, int n) {
    int i = blockIdx.x * 256 + threadIdx.x;
    if (i < n) {
        float v = src[i];
        float h = bf_hi(v);
        hi[i] = __float2bfloat16(v);
        lo[i] = __float2bfloat16(v - h);
    }
}

// ---------------- 0b: precompute bias+mask per (class, head) ----------------
__global__ void k_bias(const float* __restrict__ rpb) {
    int blk = blockIdx.x;          // cls*8 + head
    int cls = blk >> 3, head = blk & 7;
    float* outp = g_bias + (size_t)blk * NTP * NTP;
    for (int i = threadIdx.x; i < NTP * NTP; i += 256) {
        int r = i / NTP, c = i % NTP;
        float v;
        if (r < NT && c < NT) {
            int dr = r / 49, hr = (r % 49) / 7, wr = r % 7;
            int dc = c / 49, hc = (c % 49) / 7, wc = c % 7;
            int idx = (dr - dc + 1) * 169 + (hr - hc + 6) * 13 + (wr - wc + 6);
            int rgr = ((cls & 4) ? (dr == 0 ? 1 : 2) : 0) * 9
                    + ((cls & 2) ? (hr < 4 ? 1 : 2) : 0) * 3
                    + ((cls & 1) ? (wr < 4 ? 1 : 2) : 0);
            int rgc = ((cls & 4) ? (dc == 0 ? 1 : 2) : 0) * 9
                    + ((cls & 2) ? (hc < 4 ? 1 : 2) : 0) * 3
                    + ((cls & 1) ? (wc < 4 ? 1 : 2) : 0);
            v = rpb[idx * HEADS + head] + (rgr != rgc ? -100.f : 0.f);
        } else {
            v = -30000.f;
        }
        outp[i] = v;
    }
}

// ---------------- 1: transpose in (B,D,C,W,H) -> (B,D,H,W,C) ----------------
__global__ void k_transpose_in(const float* __restrict__ x) {
    __shared__ float tile[32][33];
    int bz = blockIdx.z;
    int bd = bz / Wz, w = bz % Wz;
    int h0 = blockIdx.x * 32, c0 = blockIdx.y * 32;
    #pragma unroll
    for (int j = 0; j < 32; j += 8) {
        int c = c0 + threadIdx.y + j;
        int h = h0 + threadIdx.x;
        if (h < Hz)
            tile[threadIdx.y + j][threadIdx.x] =
                x[(((size_t)bd * Cz + c) * Wz + w) * Hz + h];
    }
    __syncthreads();
    #pragma unroll
    for (int j = 0; j < 32; j += 8) {
        int c = c0 + threadIdx.x;
        int h = h0 + threadIdx.y + j;
        if (h < Hz)
            g_xp[(((size_t)bd * Hz + h) * Wz + w) * Cz + c] =
                tile[threadIdx.x][threadIdx.y + j];
    }
}

__device__ __forceinline__ int map_token(int t) {
    int b   = t / (NW * NT);
    int rem = t % (NW * NT);
    int wi = rem / NT, n = rem % NT;
    int d2 = wi / 144, h2 = (wi / 12) % 12, w2 = wi % 12;
    int dd = n / 49, r = n % 49, hh = r / 7, ww = r % 7;
    int d = d2 * 2 + dd, h = h2 * 7 + hh, w = w2 * 7 + ww;
    int ds = (d + 1) & 7;
    int hs = h + 3; if (hs >= Hz) hs -= Hz;
    int ws = w + 3; if (ws >= Wz) ws -= Wz;
    return ((b * Dz + ds) * Hz + hs) * Wz + ws;
}

// warp-level mean/invstd over 8 regs/thread (256 channels per warp)
__device__ __forceinline__ void warpMeanVar8(const float* v, float& mean, float& invstd) {
    float s1 = 0.f, s2 = 0.f;
    #pragma unroll
    for (int i = 0; i < 8; i++) { s1 += v[i]; s2 += v[i] * v[i]; }
    #pragma unroll
    for (int o = 16; o; o >>= 1) {
        s1 += __shfl_xor_sync(0xffffffffu, s1, o);
        s2 += __shfl_xor_sync(0xffffffffu, s2, o);
    }
    float m = s1 * (1.f / Cz);
    float q = s2 * (1.f / Cz) - m * m;
    mean = m;
    invstd = rsqrtf(q + 1e-5f);
}

// ---------------- 2: LN1 + shift + partition (warp per token) -------------
__global__ __launch_bounds__(256) void k_ln_part(
    const float* __restrict__ g, const float* __restrict__ bta) {
    int t = blockIdx.x * 8 + (threadIdx.x >> 5);
    int lane = threadIdx.x & 31;
    int srct = map_token(t);
    const float4* src = (const float4*)(g_xp + (size_t)srct * Cz);
    float4 a = src[lane], b4 = src[lane + 32];
    float v[8] = { a.x, a.y, a.z, a.w, b4.x, b4.y, b4.z, b4.w };
    float m, inv;
    warpMeanVar8(v, m, inv);
    float4 g0 = ((const float4*)g)[lane],   g1 = ((const float4*)g)[lane + 32];
    float4 b0 = ((const float4*)bta)[lane], b1 = ((const float4*)bta)[lane + 32];
    float gg[8] = { g0.x, g0.y, g0.z, g0.w, g1.x, g1.y, g1.z, g1.w };
    float bb[8] = { b0.x, b0.y, b0.z, b0.w, b1.x, b1.y, b1.z, b1.w };
    float o[8];
    #pragma unroll
    for (int i = 0; i < 8; i++) o[i] = (v[i] - m) * inv * gg[i] + bb[i];
    size_t base = (size_t)t * Cz;
    uint2 h0 = make_uint2(pack2bf(o[0], o[1]), pack2bf(o[2], o[3]));
    uint2 h1 = make_uint2(pack2bf(o[4], o[5]), pack2bf(o[6], o[7]));
    *(uint2*)(g_xwh + base + lane * 4)       = h0;
    *(uint2*)(g_xwh + base + 128 + lane * 4) = h1;
    uint2 l0 = make_uint2(pack2bf(o[0] - bf_hi(o[0]), o[1] - bf_hi(o[1])),
                          pack2bf(o[2] - bf_hi(o[2]), o[3] - bf_hi(o[3])));
    uint2 l1 = make_uint2(pack2bf(o[4] - bf_hi(o[4]), o[5] - bf_hi(o[5])),
                          pack2bf(o[6] - bf_hi(o[6]), o[7] - bf_hi(o[7])));
    *(uint2*)(g_xwl + base + lane * 4)       = l0;
    *(uint2*)(g_xwl + base + 128 + lane * 4) = l1;
}

// ---------------- GEMM: out[M,N] = A[M,K] @ Wt[N,K]^T --------------------
// PASSES=3: split-bf16 hi/lo, 3 mma passes. PASSES=1: hi only.
// OSPLIT: 0 = fp32 out, 1 = bf16 hi+lo planes, 2 = bf16 hi plane only.
// QSCALE: scale output columns n < Cz by 1/sqrt(HD).
// ostr: output (and res) row stride in elements (>= N; for sub-column writes).
#define PADK 40
#define PLANE_B (128 * PADK * 2)       // 10240 bytes
template <int PASSES, int ACT, bool HAS_BIAS, bool HAS_RES, int OSPLIT, bool QSCALE>
__global__ __launch_bounds__(256, 2) void k_gemm_bf(
    const __nv_bfloat16* __restrict__ Ah, const __nv_bfloat16* __restrict__ Al,
    const __nv_bfloat16* __restrict__ Bh, const __nv_bfloat16* __restrict__ Bl,
    const float* __restrict__ bias, const float* __restrict__ res,
    float* __restrict__ out,
    __nv_bfloat16* __restrict__ outh, __nv_bfloat16* __restrict__ outl,
    int M, int N, int K, int ostr) {
    extern __shared__ __align__(16) unsigned char dsm[];
    constexpr int NPL = (PASSES == 3) ? 4 : 2;
    constexpr int STB = NPL * PLANE_B;
    uint32_t sbase = smem_u32(dsm);
    int tid = threadIdx.x, lane = tid & 31, wid = tid >> 5;
    int bm = blockIdx.y * 128, bn = blockIdx.x * 128;
    int wm = (wid & 1) * 64, wn = (wid >> 1) * 32;

    int aRow = wm + (lane & 15);
    int aCol = (lane >> 4) * 8;
    int bRow = wn + ((lane >> 4) << 3) + (lane & 7);
    int bCol = ((lane >> 3) & 1) * 8;

    float acc[4][4][4];
    #pragma unroll
    for (int i = 0; i < 4; i++)
        #pragma unroll
        for (int j = 0; j < 4; j++)
            #pragma unroll
            for (int c = 0; c < 4; c++) acc[i][j][c] = 0.f;

    const int nChunks = K >> 5;

    #define ISSUE(ch, s) do {                                                   \
        int k0_ = (ch) << 5;                                                    \
        uint32_t sb_ = sbase + (s) * STB;                                       \
        _Pragma("unroll")                                                       \
        for (int q_ = 0; q_ < 2; q_++) {                                        \
            int j_ = q_ * 256 + tid;                                            \
            int row_ = j_ >> 2, c8_ = (j_ & 3) * 8;                             \
            uint32_t so_ = (uint32_t)((row_ * PADK + c8_) * 2);                 \
            size_t ga_ = (size_t)(bm + row_) * K + k0_ + c8_;                   \
            size_t gb_ = (size_t)(bn + row_) * K + k0_ + c8_;                   \
            cpasync16(sb_ + 0 * PLANE_B + so_, Ah + ga_);                       \
            if (PASSES == 3) cpasync16(sb_ + 1 * PLANE_B + so_, Al + ga_);      \
            cpasync16(sb_ + (PASSES == 3 ? 2 : 1) * PLANE_B + so_, Bh + gb_);   \
            if (PASSES == 3) cpasync16(sb_ + 3 * PLANE_B + so_, Bl + gb_);      \
        }                                                                       \
        asm volatile("cp.async.commit_group;");                                 \
    } while (0)

    ISSUE(0, 0);
    for (int ch = 0; ch < nChunks; ch++) {
        int s = ch & 1;
        if (ch + 1 < nChunks) {
            ISSUE(ch + 1, (ch + 1) & 1);
            asm volatile("cp.async.wait_group 1;");
        } else {
            asm volatile("cp.async.wait_group 0;");
        }
        __syncthreads();

        uint32_t baseAH = sbase + s * STB;
        uint32_t baseAL = baseAH + PLANE_B;
        uint32_t baseBH = baseAH + (PASSES == 3 ? 2 : 1) * PLANE_B;
        uint32_t baseBL = baseAH + 3 * PLANE_B;

        #pragma unroll
        for (int kk = 0; kk < 2; kk++) {
            int k0 = kk * 16;
            uint32_t aH[4][4], aL[4][4], bb[8];
            #pragma unroll
            for (int mi = 0; mi < 4; mi++) {
                uint32_t off = (uint32_t)(((aRow + mi * 16) * PADK + k0 + aCol) * 2);
                ldsm4(baseAH + off, aH[mi][0], aH[mi][1], aH[mi][2], aH[mi][3]);
                if (PASSES == 3)
                    ldsm4(baseAL + off, aL[mi][0], aL[mi][1], aL[mi][2], aL[mi][3]);
            }
            #pragma unroll
            for (int p = 0; p < 2; p++) {
                uint32_t off = (uint32_t)(((bRow + p * 16) * PADK + k0 + bCol) * 2);
                ldsm4(baseBH + off, bb[p * 4 + 0], bb[p * 4 + 1], bb[p * 4 + 2], bb[p * 4 + 3]);
            }
            #pragma unroll
            for (int mi = 0; mi < 4; mi++)
                #pragma unroll
                for (int ni = 0; ni < 4; ni++)
                    mma_bf16(acc[mi][ni], aH[mi], &bb[ni * 2]);
            if (PASSES == 3) {
                #pragma unroll
                for (int mi = 0; mi < 4; mi++)
                    #pragma unroll
                    for (int ni = 0; ni < 4; ni++)
                        mma_bf16(acc[mi][ni], aL[mi], &bb[ni * 2]);
                #pragma unroll
                for (int p = 0; p < 2; p++) {
                    uint32_t off = (uint32_t)(((bRow + p * 16) * PADK + k0 + bCol) * 2);
                    ldsm4(baseBL + off, bb[p * 4 + 0], bb[p * 4 + 1], bb[p * 4 + 2], bb[p * 4 + 3]);
                }
                #pragma unroll
                for (int mi = 0; mi < 4; mi++)
                    #pragma unroll
                    for (int ni = 0; ni < 4; ni++)
                        mma_bf16(acc[mi][ni], aH[mi], &bb[ni * 2]);
            }
        }
        __syncthreads();
    }
    #undef ISSUE

    int orow = lane >> 2, ocol = (lane & 3) * 2;
    #pragma unroll
    for (int mi = 0; mi < 4; mi++) {
        int m0 = bm + wm + mi * 16;
        #pragma unroll
        for (int ni = 0; ni < 4; ni++) {
            int n = bn + wn + ni * 8 + ocol;
            float bi0 = 0.f, bi1 = 0.f;
            if (HAS_BIAS) { bi0 = bias[n]; bi1 = bias[n + 1]; }
            float sc = (QSCALE && n < Cz) ? 0.17677669529663687f : 1.f;
            #pragma unroll
            for (int half = 0; half < 2; half++) {
                int m = m0 + orow + half * 8;
                float v0 = acc[mi][ni][half * 2 + 0] + bi0;
                float v1 = acc[mi][ni][half * 2 + 1] + bi1;
                if (QSCALE) { v0 *= sc; v1 *= sc; }
                if (ACT == 1) {
                    v0 = 0.5f * v0 * (1.f + erff(v0 * 0.70710678118654752f));
                    v1 = 0.5f * v1 * (1.f + erff(v1 * 0.70710678118654752f));
                }
                if (HAS_RES) {
                    const float2 r2 = *(const float2*)(res + (size_t)m * ostr + n);
                    v0 += r2.x; v1 += r2.y;
                }
                if (OSPLIT == 1) {
                    *(uint32_t*)(outh + (size_t)m * ostr + n) = pack2bf(v0, v1);
                    *(uint32_t*)(outl + (size_t)m * ostr + n) =
                        pack2bf(v0 - bf_hi(v0), v1 - bf_hi(v1));
                } else if (OSPLIT == 2) {
                    *(uint32_t*)(outh + (size_t)m * ostr + n) = pack2bf(v0, v1);
                } else {
                    *(float2*)(out + (size_t)m * ostr + n) = make_float2(v0, v1);
                }
            }
        }
    }
}

// ---------------- 4: tensor-core attention per (head, window) ----------------
#define APL (NTP * 40)                 // 4480 halves per plane
#define ATTN_SMEM_TC (6 * APL * 2)     // 53760 bytes
__global__ __launch_bounds__(224, 2) void k_attn_tc() {
    extern __shared__ __nv_bfloat16 asm_[];
    int head = blockIdx.x, bwin = blockIdx.y;
    int tid = threadIdx.x, lane = tid & 31, wid = tid >> 5;
    uint32_t sbase = smem_u32(asm_);

    // zero pad rows 98..111 of all 6 planes
    for (int i = tid; i < 6 * 280; i += 224) {
        int p = i / 280, r = i % 280;
        ((uint32_t*)(asm_ + p * APL + NT * 40))[r] = 0u;
    }

    // fill: 98 tokens x {q,k,v} x {hi,lo} x 4 x 16B cp.async copies
    for (int i = tid; i < 98 * 6 * 4; i += 224) {
        int chunk = i & 3;
        int idx = i >> 2;
        int n = idx / 6, which = idx % 6;
        int sel = which >> 1, pl = which & 1;
        const __nv_bfloat16* src = (pl ? g_qkvl : g_qkvh)
            + (size_t)(bwin * NT + n) * (3 * Cz) + sel * Cz + head * HD + chunk * 8;
        uint32_t dst = sbase + (uint32_t)(((sel * 2 + pl) * APL + n * 40 + chunk * 8) * 2);
        cpasync16(dst, src);
    }
    asm volatile("cp.async.commit_group;");
    asm volatile("cp.async.wait_group 0;");
    __syncthreads();

    // window boundary class -> precomputed bias+mask slab
    int wi = bwin % NW;
    int cls = ((wi / 144) == 3 ? 4 : 0) | (((wi / 12) % 12) == 11 ? 2 : 0)
            | ((wi % 12) == 11 ? 1 : 0);
    const float* Bm = g_bias + (size_t)(cls * HEADS + head) * NTP * NTP;

    uint32_t bQh = sbase,            bQl = sbase + APL * 2;
    uint32_t bKh = sbase + 2*APL*2,  bKl = sbase + 3*APL*2;
    uint32_t bVh = sbase + 4*APL*2,  bVl = sbase + 5*APL*2;

    int wm = wid * 16;
    int aRow = wm + (lane & 15);
    int aCol = (lane >> 4) * 8;
    int bR = ((lane >> 4) << 3) + (lane & 7);
    int bCol = ((lane >> 3) & 1) * 8;
    int vR = ((lane >> 3) & 1) * 8 + (lane & 7);
    int vCol = (lane >> 4) * 8;

    float sacc[14][4];
    #pragma unroll
    for (int t = 0; t < 14; t++)
        #pragma unroll
        for (int e = 0; e < 4; e++) sacc[t][e] = 0.f;

    #pragma unroll
    for (int kk = 0; kk < 2; kk++) {
        int k0 = kk * 16;
        uint32_t aH[4], aL[4], bbH[4], bbL[4];
        uint32_t aoff = (uint32_t)((aRow * 40 + k0 + aCol) * 2);
        ldsm4(bQh + aoff, aH[0], aH[1], aH[2], aH[3]);
        ldsm4(bQl + aoff, aL[0], aL[1], aL[2], aL[3]);
        #pragma unroll
        for (int nt = 0; nt < 7; nt++) {
            uint32_t boff = (uint32_t)(((nt * 16 + bR) * 40 + k0 + bCol) * 2);
            ldsm4(bKh + boff, bbH[0], bbH[1], bbH[2], bbH[3]);
            ldsm4(bKl + boff, bbL[0], bbL[1], bbL[2], bbL[3]);
            mma_bf16(sacc[nt * 2 + 0], aH, &bbH[0]);
            mma_bf16(sacc[nt * 2 + 1], aH, &bbH[2]);
            mma_bf16(sacc[nt * 2 + 0], aH, &bbL[0]);
            mma_bf16(sacc[nt * 2 + 1], aH, &bbL[2]);
            mma_bf16(sacc[nt * 2 + 0], aL, &bbH[0]);
            mma_bf16(sacc[nt * 2 + 1], aL, &bbH[2]);
        }
    }

    // precomputed bias/mask add (Q already scaled in qkv epilogue)
    int r0 = wm + (lane >> 2);
    int cbase = (lane & 3) * 2;
    #pragma unroll
    for (int h = 0; h < 2; h++) {
        int r = r0 + h * 8;
        const float2* brow = (const float2*)(Bm + (size_t)r * NTP);
        #pragma unroll
        for (int t = 0; t < 14; t++) {
            float2 bb = brow[t * 4 + (lane & 3)];
            sacc[t][h * 2 + 0] += bb.x;
            sacc[t][h * 2 + 1] += bb.y;
        }
    }

    // softmax in regs (row = quad of lanes)
    #pragma unroll
    for (int h = 0; h < 2; h++) {
        float mx = -1e30f;
        #pragma unroll
        for (int t = 0; t < 14; t++) {
            mx = fmaxf(mx, sacc[t][h * 2 + 0]);
            mx = fmaxf(mx, sacc[t][h * 2 + 1]);
        }
        mx = fmaxf(mx, __shfl_xor_sync(0xffffffffu, mx, 1));
        mx = fmaxf(mx, __shfl_xor_sync(0xffffffffu, mx, 2));
        float sum = 0.f;
        #pragma unroll
        for (int t = 0; t < 14; t++) {
            #pragma unroll
            for (int e = 0; e < 2; e++) {
                float v = __expf(sacc[t][h * 2 + e] - mx);
                sacc[t][h * 2 + e] = v;
                sum += v;
            }
        }
        sum += __shfl_xor_sync(0xffffffffu, sum, 1);
        sum += __shfl_xor_sync(0xffffffffu, sum, 2);
        float inv = 1.f / sum;
        #pragma unroll
        for (int t = 0; t < 14; t++) {
            sacc[t][h * 2 + 0] *= inv;
            sacc[t][h * 2 + 1] *= inv;
        }
    }

    // P @ V (P hi-only + V hi/lo: 2 mma passes; V via trans-ldmatrix)
    float oacc[4][4];
    #pragma unroll
    for (int i = 0; i < 4; i++)
        #pragma unroll
        for (int e = 0; e < 4; e++) oacc[i][e] = 0.f;

    #pragma unroll
    for (int j = 0; j < 7; j++) {
        uint32_t aH[4];
        #pragma unroll
        for (int q = 0; q < 2; q++) {
            aH[q * 2 + 0] = pack2bf(sacc[2 * j + q][0], sacc[2 * j + q][1]);
            aH[q * 2 + 1] = pack2bf(sacc[2 * j + q][2], sacc[2 * j + q][3]);
        }
        #pragma unroll
        for (int dg = 0; dg < 2; dg++) {
            uint32_t bbH[4], bbL[4];
            uint32_t boff = (uint32_t)(((j * 16 + vR) * 40 + vCol + dg * 16) * 2);
            ldsm4t(bVh + boff, bbH[0], bbH[1], bbH[2], bbH[3]);
            ldsm4t(bVl + boff, bbL[0], bbL[1], bbL[2], bbL[3]);
            mma_bf16(oacc[dg * 2 + 0], aH, &bbH[0]);
            mma_bf16(oacc[dg * 2 + 1], aH, &bbH[2]);
            mma_bf16(oacc[dg * 2 + 0], aH, &bbL[0]);
            mma_bf16(oacc[dg * 2 + 1], aH, &bbL[2]);
        }
    }

    #pragma unroll
    for (int h = 0; h < 2; h++) {
        int r = r0 + h * 8;
        if (r < NT) {
            size_t ob = ((size_t)bwin * NT + r) * Cz + head * HD;
            #pragma unroll
            for (int nt = 0; nt < 4; nt++) {
                int c = nt * 8 + cbase;
                *(uint32_t*)(g_aoh + ob + c) =
                    pack2bf(oacc[nt][h * 2 + 0], oacc[nt][h * 2 + 1]);
            }
        }
    }
}

// ---------------- 6: reverse + residual + LN2 (warp per token) ------------
__global__ __launch_bounds__(256) void k_rev_res_ln2(
    const float* __restrict__ g2, const float* __restrict__ b2) {
    int t = blockIdx.x * 8 + (threadIdx.x >> 5);
    int lane = threadIdx.x & 31;
    int ft = map_token(t);
    const float4* posrc = (const float4*)(g_po + (size_t)t * Cz);
    const float4* xpsrc = (const float4*)(g_xp + (size_t)ft * Cz);
    float4 p0 = posrc[lane], p1 = posrc[lane + 32];
    float4 x0 = xpsrc[lane], x1 = xpsrc[lane + 32];
    float v[8] = { p0.x + x0.x, p0.y + x0.y, p0.z + x0.z, p0.w + x0.w,
                   p1.x + x1.x, p1.y + x1.y, p1.z + x1.z, p1.w + x1.w };
    float4* xrd = (float4*)(g_xres + (size_t)ft * Cz);
    xrd[lane]      = make_float4(v[0], v[1], v[2], v[3]);
    xrd[lane + 32] = make_float4(v[4], v[5], v[6], v[7]);
    float m, inv;
    warpMeanVar8(v, m, inv);
    float4 g0 = ((const float4*)g2)[lane], g1 = ((const float4*)g2)[lane + 32];
    float4 b0 = ((const float4*)b2)[lane], b1 = ((const float4*)b2)[lane + 32];
    float gg[8] = { g0.x, g0.y, g0.z, g0.w, g1.x, g1.y, g1.z, g1.w };
    float bb[8] = { b0.x, b0.y, b0.z, b0.w, b1.x, b1.y, b1.z, b1.w };
    float o[8];
    #pragma unroll
    for (int i = 0; i < 8; i++) o[i] = (v[i] - m) * inv * gg[i] + bb[i];
    size_t base = (size_t)ft * Cz;
    *(uint2*)(g_l2h + base + lane * 4) =
        make_uint2(pack2bf(o[0], o[1]), pack2bf(o[2], o[3]));
    *(uint2*)(g_l2h + base + 128 + lane * 4) =
        make_uint2(pack2bf(o[4], o[5]), pack2bf(o[6], o[7]));
}

// ---------------- 9: transpose out (B,D,H,W,C) -> (B,D,C,W,H) ----------------
__global__ void k_transpose_out(float* __restrict__ out) {
    __shared__ float tile[32][33];
    int bz = blockIdx.z;
    int bd = bz / Wz, w = bz % Wz;
    int h0 = blockIdx.x * 32, c0 = blockIdx.y * 32;
    #pragma unroll
    for (int j = 0; j < 32; j += 8) {
        int c = c0 + threadIdx.x;
        int h = h0 + threadIdx.y + j;
        if (h < Hz)
            tile[threadIdx.y + j][threadIdx.x] =
                g_y[(((size_t)bd * Hz + h) * Wz + w) * Cz + c];
    }
    __syncthreads();
    #pragma unroll
    for (int j = 0; j < 32; j += 8) {
        int h = h0 + threadIdx.x;
        int c = c0 + threadIdx.y + j;
        if (h < Hz)
            out[(((size_t)bd * Cz + c) * Wz + w) * Hz + h] =
                tile[threadIdx.x][threadIdx.y + j];
    }
}

// ---------------- launch ----------------
extern "C" void kernel_launch(void* const* d_in, const int* in_sizes, int n_in,
                              void* d_out, int out_size) {
    const float* x      = (const float*)d_in[0];
    const float* n1g    = (const float*)d_in[1];
    const float* n1b    = (const float*)d_in[2];
    const float* qkv_w  = (const float*)d_in[3];
    const float* rpb    = (const float*)d_in[4];
    const float* proj_w = (const float*)d_in[5];
    const float* proj_b = (const float*)d_in[6];
    const float* n2g    = (const float*)d_in[7];
    const float* n2b    = (const float*)d_in[8];
    const float* fc1_w  = (const float*)d_in[9];
    const float* fc1_b  = (const float*)d_in[10];
    const float* fc2_w  = (const float*)d_in[11];
    const float* fc2_b  = (const float*)d_in[12];
    float* out = (float*)d_out;

    void* p;
    cudaGetSymbolAddress(&p, g_po);   float* po   = (float*)p;
    cudaGetSymbolAddress(&p, g_xres); float* xres = (float*)p;
    cudaGetSymbolAddress(&p, g_y);    float* y    = (float*)p;
    cudaGetSymbolAddress(&p, g_xwh);  __nv_bfloat16* xwh = (__nv_bfloat16*)p;
    cudaGetSymbolAddress(&p, g_xwl);  __nv_bfloat16* xwl = (__nv_bfloat16*)p;
    cudaGetSymbolAddress(&p, g_qkvh); __nv_bfloat16* qkvh = (__nv_bfloat16*)p;
    cudaGetSymbolAddress(&p, g_qkvl); __nv_bfloat16* qkvl = (__nv_bfloat16*)p;
    cudaGetSymbolAddress(&p, g_aoh);  __nv_bfloat16* aoh = (__nv_bfloat16*)p;
    cudaGetSymbolAddress(&p, g_l2h);  __nv_bfloat16* l2h = (__nv_bfloat16*)p;
    cudaGetSymbolAddress(&p, g_hih);  __nv_bfloat16* hih = (__nv_bfloat16*)p;
    cudaGetSymbolAddress(&p, g_wqh);  __nv_bfloat16* wqh = (__nv_bfloat16*)p;
    cudaGetSymbolAddress(&p, g_wql);  __nv_bfloat16* wql = (__nv_bfloat16*)p;
    cudaGetSymbolAddress(&p, g_wph);  __nv_bfloat16* wph = (__nv_bfloat16*)p;
    cudaGetSymbolAddress(&p, g_w1h);  __nv_bfloat16* w1h = (__nv_bfloat16*)p;
    cudaGetSymbolAddress(&p, g_w2h);  __nv_bfloat16* w2h = (__nv_bfloat16*)p;
    cudaGetSymbolAddress(&p, g_wpl);  __nv_bfloat16* wpl = (__nv_bfloat16*)p;
    cudaGetSymbolAddress(&p, g_w1l);  __nv_bfloat16* w1l = (__nv_bfloat16*)p;
    cudaGetSymbolAddress(&p, g_w2l);  __nv_bfloat16* w2l = (__nv_bfloat16*)p;

    cudaFuncSetAttribute(k_attn_tc, cudaFuncAttributeMaxDynamicSharedMemorySize, ATTN_SMEM_TC);
    cudaFuncSetAttribute(k_gemm_bf<3, 0, false, false, 1, true>,  cudaFuncAttributeMaxDynamicSharedMemorySize, 8 * PLANE_B);
    cudaFuncSetAttribute(k_gemm_bf<1, 0, false, false, 1, false>, cudaFuncAttributeMaxDynamicSharedMemorySize, 4 * PLANE_B);
    cudaFuncSetAttribute(k_gemm_bf<1, 0, true, false, 0, false>,  cudaFuncAttributeMaxDynamicSharedMemorySize, 4 * PLANE_B);
    cudaFuncSetAttribute(k_gemm_bf<1, 1, true, false, 2, false>,  cudaFuncAttributeMaxDynamicSharedMemorySize, 4 * PLANE_B);
    cudaFuncSetAttribute(k_gemm_bf<1, 0, true, true, 0, false>,   cudaFuncAttributeMaxDynamicSharedMemorySize, 4 * PLANE_B);

    dim3 tb(32, 8);
    dim3 tg(3, 8, Bz * Dz * Wz);

    // 0. weight splits + bias table (tiny)
    k_wsplit<<<(3 * Cz * Cz + 255) / 256, 256>>>(qkv_w, wqh, wql, 3 * Cz * Cz);
    k_wsplit<<<(Cz * Cz + 255) / 256, 256>>>(proj_w, wph, wpl, Cz * Cz);
    k_wsplit<<<(HID * Cz + 255) / 256, 256>>>(fc1_w, w1h, w1l, HID * Cz);
    k_wsplit<<<(Cz * HID + 255) / 256, 256>>>(fc2_w, w2h, w2l, Cz * HID);
    k_bias<<<64, 256>>>(rpb);
    // 1. transpose in
    k_transpose_in<<<tg, tb>>>(x);
    // 2. LN1 + shift + partition (warp per token, split bf16 out)
    k_ln_part<<<TOK / 8, 256>>>(n1g, n1b);
    // 3a. QK GEMM (3-pass, N=512, split out with stride 768, Q pre-scaled)
    k_gemm_bf<3, 0, false, false, 1, true><<<dim3(4, TOK / 128), 256, 8 * PLANE_B>>>(
        xwh, xwl, wqh, wql, nullptr, nullptr, nullptr, qkvh, qkvl,
        TOK, 2 * Cz, Cz, 3 * Cz);
    // 3b. V GEMM (1-pass, N=256, split out with stride 768)
    k_gemm_bf<1, 0, false, false, 1, false><<<dim3(2, TOK / 128), 256, 4 * PLANE_B>>>(
        xwh, nullptr, wqh + (size_t)2 * Cz * Cz, nullptr, nullptr, nullptr, nullptr,
        qkvh + 2 * Cz, qkvl + 2 * Cz, TOK, Cz, Cz, 3 * Cz);
    // 4. attention (tensor cores, precomputed bias, P hi-only PV)
    k_attn_tc<<<dim3(HEADS, BW), 224, ATTN_SMEM_TC>>>();
    // 5. proj GEMM (1-pass) -> g_po fp32
    k_gemm_bf<1, 0, true, false, 0, false><<<dim3(Cz / 128, TOK / 128), 256, 4 * PLANE_B>>>(
        aoh, nullptr, wph, nullptr, proj_b, nullptr, po, nullptr, nullptr, TOK, Cz, Cz, Cz);
    // 6. reverse + residual + LN2 (warp per token)
    k_rev_res_ln2<<<TOK / 8, 256>>>(n2g, n2b);
    // 7. fc1 GEMM (1-pass) + GELU -> hi plane
    k_gemm_bf<1, 1, true, false, 2, false><<<dim3(HID / 128, TOK / 128), 256, 4 * PLANE_B>>>(
        l2h, nullptr, w1h, nullptr, fc1_b, nullptr, nullptr, hih, nullptr, TOK, HID, Cz, HID);
    // 8. fc2 GEMM (1-pass) + bias + residual -> y fp32
    k_gemm_bf<1, 0, true, true, 0, false><<<dim3(Cz / 128, TOK / 128), 256, 4 * PLANE_B>>>(
        hih, nullptr, w2h, nullptr, fc2_b, xres, y, nullptr, nullptr, TOK, Cz, HID, Cz);
    // 9. transpose out
    k_transpose_out<<<tg, tb>>>(out);
}

// round 13
// speedup vs baseline: 1.5289x; 1.2143x over previous
#include <cuda_runtime.h>
#include <cuda_fp16.h>
#include <math.h>
#include <stdint.h>

// ---------------- problem constants ----------------
#define Bz 2
#define Dz 8
#define Cz 256
#define Wz 84
#define Hz 84
#define HEADS 8
#define HD 32
#define NT 98            // tokens per window (2*7*7)
#define NTP 112          // padded to 7 x 16
#define NW 576           // windows per batch (4*12*12)
#define BW (Bz*NW)       // 1152 window-batches
#define TOK (BW*NT)      // 112896 tokens
#define HID 1024

// ---------------- scratch (device globals; allocation-free) ----------------
__device__ __align__(256) float g_xp  [(size_t)TOK*Cz];   // shortcut (B,D,H,W,C)
__device__ __align__(256) float g_po  [(size_t)TOK*Cz];   // proj output (windowed order)
__device__ __align__(256) float g_xres[(size_t)TOK*Cz];   // (B,D,H,W,C)
__device__ __align__(256) float g_y   [(size_t)TOK*Cz];
__device__ __align__(256) float g_bias[8 * HEADS * NTP * NTP];  // [cls][head][r][c]
// fp16 activation planes
__device__ __align__(256) __half g_xwh[(size_t)TOK*Cz];
__device__ __align__(256) __half g_qkvh[(size_t)TOK*3*Cz];
__device__ __align__(256) __half g_aoh[(size_t)TOK*Cz];
__device__ __align__(256) __half g_l2h[(size_t)TOK*Cz];
__device__ __align__(256) __half g_hih[(size_t)TOK*HID];
// fp16 weights
__device__ __align__(256) __half g_wqh[3*Cz*Cz];
__device__ __align__(256) __half g_wph[Cz*Cz];
__device__ __align__(256) __half g_w1h[HID*Cz];
__device__ __align__(256) __half g_w2h[Cz*HID];

// ---------------- helpers ----------------
__device__ __forceinline__ uint32_t smem_u32(const void* p) {
    uint32_t a;
    asm("{ .reg .u64 t; cvta.to.shared.u64 t, %1; cvt.u32.u64 %0, t; }" : "=r"(a) : "l"(p));
    return a;
}
__device__ __forceinline__ uint32_t pack2h(float x, float y) {
    __half2 t = __floats2half2_rn(x, y);
    return *(uint32_t*)&t;
}
__device__ __forceinline__ void ldsm4(uint32_t addr, uint32_t& r0, uint32_t& r1,
                                      uint32_t& r2, uint32_t& r3) {
    asm volatile("ldmatrix.sync.aligned.m8n8.x4.shared.b16 {%0,%1,%2,%3}, [%4];"
                 : "=r"(r0), "=r"(r1), "=r"(r2), "=r"(r3) : "r"(addr));
}
__device__ __forceinline__ void ldsm4t(uint32_t addr, uint32_t& r0, uint32_t& r1,
                                       uint32_t& r2, uint32_t& r3) {
    asm volatile("ldmatrix.sync.aligned.m8n8.x4.trans.shared.b16 {%0,%1,%2,%3}, [%4];"
                 : "=r"(r0), "=r"(r1), "=r"(r2), "=r"(r3) : "r"(addr));
}
__device__ __forceinline__ void mma_f16(float* d, const uint32_t* a, const uint32_t* b) {
    asm volatile(
        "mma.sync.aligned.m16n8k16.row.col.f32.f16.f16.f32 "
        "{%0,%1,%2,%3}, {%4,%5,%6,%7}, {%8,%9}, {%0,%1,%2,%3};"
        : "+f"(d[0]), "+f"(d[1]), "+f"(d[2]), "+f"(d[3])
        : "r"(a[0]), "r"(a[1]), "r"(a[2]), "r"(a[3]), "r"(b[0]), "r"(b[1]));
}
__device__ __forceinline__ void cpasync16(uint32_t dst, const void* src) {
    asm volatile("cp.async.cg.shared.global [%0], [%1], 16;" :: "r"(dst), "l"(src));
}

// ---------------- 0a: weight convert fp32 -> fp16 ----------------
__global__ void k_wcvt(const float* __restrict__ src, __half* __restrict__ dst, int n) {
    int i = blockIdx.x * 256 + threadIdx.x;
    if (i < n) dst[i] = __float2half(src[i]);
}

// ---------------- 0b: precompute bias+mask per (class, head) ----------------
__global__ void k_bias(const float* __restrict__ rpb) {
    int blk = blockIdx.x;          // cls*8 + head
    int cls = blk >> 3, head = blk & 7;
    float* outp = g_bias + (size_t)blk * NTP * NTP;
    for (int i = threadIdx.x; i < NTP * NTP; i += 256) {
        int r = i / NTP, c = i % NTP;
        float v;
        if (r < NT && c < NT) {
            int dr = r / 49, hr = (r % 49) / 7, wr = r % 7;
            int dc = c / 49, hc = (c % 49) / 7, wc = c % 7;
            int idx = (dr - dc + 1) * 169 + (hr - hc + 6) * 13 + (wr - wc + 6);
            int rgr = ((cls & 4) ? (dr == 0 ? 1 : 2) : 0) * 9
                    + ((cls & 2) ? (hr < 4 ? 1 : 2) : 0) * 3
                    + ((cls & 1) ? (wr < 4 ? 1 : 2) : 0);
            int rgc = ((cls & 4) ? (dc == 0 ? 1 : 2) : 0) * 9
                    + ((cls & 2) ? (hc < 4 ? 1 : 2) : 0) * 3
                    + ((cls & 1) ? (wc < 4 ? 1 : 2) : 0);
            v = rpb[idx * HEADS + head] + (rgr != rgc ? -100.f : 0.f);
        } else {
            v = -30000.f;
        }
        outp[i] = v;
    }
}

// ---------------- 1: transpose in (B,D,C,W,H) -> (B,D,H,W,C) ----------------
__global__ void k_transpose_in(const float* __restrict__ x) {
    __shared__ float tile[32][33];
    int bz = blockIdx.z;
    int bd = bz / Wz, w = bz % Wz;
    int h0 = blockIdx.x * 32, c0 = blockIdx.y * 32;
    #pragma unroll
    for (int j = 0; j < 32; j += 8) {
        int c = c0 + threadIdx.y + j;
        int h = h0 + threadIdx.x;
        if (h < Hz)
            tile[threadIdx.y + j][threadIdx.x] =
                x[(((size_t)bd * Cz + c) * Wz + w) * Hz + h];
    }
    __syncthreads();
    #pragma unroll
    for (int j = 0; j < 32; j += 8) {
        int c = c0 + threadIdx.x;
        int h = h0 + threadIdx.y + j;
        if (h < Hz)
            g_xp[(((size_t)bd * Hz + h) * Wz + w) * Cz + c] =
                tile[threadIdx.x][threadIdx.y + j];
    }
}

__device__ __forceinline__ int map_token(int t) {
    int b   = t / (NW * NT);
    int rem = t % (NW * NT);
    int wi = rem / NT, n = rem % NT;
    int d2 = wi / 144, h2 = (wi / 12) % 12, w2 = wi % 12;
    int dd = n / 49, r = n % 49, hh = r / 7, ww = r % 7;
    int d = d2 * 2 + dd, h = h2 * 7 + hh, w = w2 * 7 + ww;
    int ds = (d + 1) & 7;
    int hs = h + 3; if (hs >= Hz) hs -= Hz;
    int ws = w + 3; if (ws >= Wz) ws -= Wz;
    return ((b * Dz + ds) * Hz + hs) * Wz + ws;
}

// warp-level mean/invstd over 8 regs/thread (256 channels per warp)
__device__ __forceinline__ void warpMeanVar8(const float* v, float& mean, float& invstd) {
    float s1 = 0.f, s2 = 0.f;
    #pragma unroll
    for (int i = 0; i < 8; i++) { s1 += v[i]; s2 += v[i] * v[i]; }
    #pragma unroll
    for (int o = 16; o; o >>= 1) {
        s1 += __shfl_xor_sync(0xffffffffu, s1, o);
        s2 += __shfl_xor_sync(0xffffffffu, s2, o);
    }
    float m = s1 * (1.f / Cz);
    float q = s2 * (1.f / Cz) - m * m;
    mean = m;
    invstd = rsqrtf(q + 1e-5f);
}

// ---------------- 2: LN1 + shift + partition (warp per token) -------------
__global__ __launch_bounds__(256) void k_ln_part(
    const float* __restrict__ g, const float* __restrict__ bta) {
    int t = blockIdx.x * 8 + (threadIdx.x >> 5);
    int lane = threadIdx.x & 31;
    int srct = map_token(t);
    const float4* src = (const float4*)(g_xp + (size_t)srct * Cz);
    float4 a = src[lane], b4 = src[lane + 32];
    float v[8] = { a.x, a.y, a.z, a.w, b4.x, b4.y, b4.z, b4.w };
    float m, inv;
    warpMeanVar8(v, m, inv);
    float4 g0 = ((const float4*)g)[lane],   g1 = ((const float4*)g)[lane + 32];
    float4 b0 = ((const float4*)bta)[lane], b1 = ((const float4*)bta)[lane + 32];
    float gg[8] = { g0.x, g0.y, g0.z, g0.w, g1.x, g1.y, g1.z, g1.w };
    float bb[8] = { b0.x, b0.y, b0.z, b0.w, b1.x, b1.y, b1.z, b1.w };
    float o[8];
    #pragma unroll
    for (int i = 0; i < 8; i++) o[i] = (v[i] - m) * inv * gg[i] + bb[i];
    size_t base = (size_t)t * Cz;
    *(uint2*)(g_xwh + base + lane * 4) =
        make_uint2(pack2h(o[0], o[1]), pack2h(o[2], o[3]));
    *(uint2*)(g_xwh + base + 128 + lane * 4) =
        make_uint2(pack2h(o[4], o[5]), pack2h(o[6], o[7]));
}

// ---------------- GEMM (1-pass fp16): out[M,N] = A[M,K] @ Wt[N,K]^T -------
// OSPLIT: 0 = fp32 out, 2 = fp16 plane out.
// QSCALE: scale output columns n < Cz by 1/sqrt(HD).
#define PADK 40
#define PLANE_B (128 * PADK * 2)       // 10240 bytes
template <int ACT, bool HAS_BIAS, bool HAS_RES, int OSPLIT, bool QSCALE>
__global__ __launch_bounds__(256, 2) void k_gemm_h(
    const __half* __restrict__ Ah, const __half* __restrict__ Bh,
    const float* __restrict__ bias, const float* __restrict__ res,
    float* __restrict__ out, __half* __restrict__ outh,
    int M, int N, int K, int ostr) {
    extern __shared__ __align__(16) unsigned char dsm[];
    const uint32_t STB = 2 * PLANE_B;
    uint32_t sbase = smem_u32(dsm);
    int tid = threadIdx.x, lane = tid & 31, wid = tid >> 5;
    int bm = blockIdx.y * 128, bn = blockIdx.x * 128;
    int wm = (wid & 1) * 64, wn = (wid >> 1) * 32;

    int aRow = wm + (lane & 15);
    int aCol = (lane >> 4) * 8;
    int bRow = wn + ((lane >> 4) << 3) + (lane & 7);
    int bCol = ((lane >> 3) & 1) * 8;

    float acc[4][4][4];
    #pragma unroll
    for (int i = 0; i < 4; i++)
        #pragma unroll
        for (int j = 0; j < 4; j++)
            #pragma unroll
            for (int c = 0; c < 4; c++) acc[i][j][c] = 0.f;

    const int nChunks = K >> 5;

    #define ISSUE(ch, s) do {                                                   \
        int k0_ = (ch) << 5;                                                    \
        uint32_t sb_ = sbase + (s) * STB;                                       \
        _Pragma("unroll")                                                       \
        for (int q_ = 0; q_ < 2; q_++) {                                        \
            int j_ = q_ * 256 + tid;                                            \
            int row_ = j_ >> 2, c8_ = (j_ & 3) * 8;                             \
            uint32_t so_ = (uint32_t)((row_ * PADK + c8_) * 2);                 \
            cpasync16(sb_ + so_, Ah + (size_t)(bm + row_) * K + k0_ + c8_);     \
            cpasync16(sb_ + PLANE_B + so_,                                      \
                      Bh + (size_t)(bn + row_) * K + k0_ + c8_);                \
        }                                                                       \
        asm volatile("cp.async.commit_group;");                                 \
    } while (0)

    ISSUE(0, 0);
    for (int ch = 0; ch < nChunks; ch++) {
        int s = ch & 1;
        if (ch + 1 < nChunks) {
            ISSUE(ch + 1, (ch + 1) & 1);
            asm volatile("cp.async.wait_group 1;");
        } else {
            asm volatile("cp.async.wait_group 0;");
        }
        __syncthreads();

        uint32_t baseA = sbase + s * STB;
        uint32_t baseB = baseA + PLANE_B;

        #pragma unroll
        for (int kk = 0; kk < 2; kk++) {
            int k0 = kk * 16;
            uint32_t aH[4][4], bb[8];
            #pragma unroll
            for (int mi = 0; mi < 4; mi++) {
                uint32_t off = (uint32_t)(((aRow + mi * 16) * PADK + k0 + aCol) * 2);
                ldsm4(baseA + off, aH[mi][0], aH[mi][1], aH[mi][2], aH[mi][3]);
            }
            #pragma unroll
            for (int p = 0; p < 2; p++) {
                uint32_t off = (uint32_t)(((bRow + p * 16) * PADK + k0 + bCol) * 2);
                ldsm4(baseB + off, bb[p * 4 + 0], bb[p * 4 + 1], bb[p * 4 + 2], bb[p * 4 + 3]);
            }
            #pragma unroll
            for (int mi = 0; mi < 4; mi++)
                #pragma unroll
                for (int ni = 0; ni < 4; ni++)
                    mma_f16(acc[mi][ni], aH[mi], &bb[ni * 2]);
        }
        __syncthreads();
    }
    #undef ISSUE

    int orow = lane >> 2, ocol = (lane & 3) * 2;
    #pragma unroll
    for (int mi = 0; mi < 4; mi++) {
        int m0 = bm + wm + mi * 16;
        #pragma unroll
        for (int ni = 0; ni < 4; ni++) {
            int n = bn + wn + ni * 8 + ocol;
            float bi0 = 0.f, bi1 = 0.f;
            if (HAS_BIAS) { bi0 = bias[n]; bi1 = bias[n + 1]; }
            float sc = (QSCALE && n < Cz) ? 0.17677669529663687f : 1.f;
            #pragma unroll
            for (int half = 0; half < 2; half++) {
                int m = m0 + orow + half * 8;
                float v0 = acc[mi][ni][half * 2 + 0] + bi0;
                float v1 = acc[mi][ni][half * 2 + 1] + bi1;
                if (QSCALE) { v0 *= sc; v1 *= sc; }
                if (ACT == 1) {
                    v0 = 0.5f * v0 * (1.f + erff(v0 * 0.70710678118654752f));
                    v1 = 0.5f * v1 * (1.f + erff(v1 * 0.70710678118654752f));
                }
                if (HAS_RES) {
                    const float2 r2 = *(const float2*)(res + (size_t)m * ostr + n);
                    v0 += r2.x; v1 += r2.y;
                }
                if (OSPLIT == 2) {
                    *(uint32_t*)(outh + (size_t)m * ostr + n) = pack2h(v0, v1);
                } else {
                    *(float2*)(out + (size_t)m * ostr + n) = make_float2(v0, v1);
                }
            }
        }
    }
}

// ---------------- 4: fp16 tensor-core attention per (head, window) --------
#define APL (NTP * 40)                 // 4480 halves per plane
#define ATTN_SMEM_TC (3 * APL * 2)     // 26880 bytes
__global__ __launch_bounds__(224, 2) void k_attn_tc() {
    extern __shared__ __half asm_[];
    int head = blockIdx.x, bwin = blockIdx.y;
    int tid = threadIdx.x, lane = tid & 31, wid = tid >> 5;
    uint32_t sbase = smem_u32(asm_);

    // zero pad rows 98..111 of all 3 planes
    for (int i = tid; i < 3 * 280; i += 224) {
        int p = i / 280, r = i % 280;
        ((uint32_t*)(asm_ + p * APL + NT * 40))[r] = 0u;
    }

    // fill: 98 tokens x {q,k,v} x 4 x 16B cp.async copies
    for (int i = tid; i < 98 * 3 * 4; i += 224) {
        int chunk = i & 3;
        int idx = i >> 2;
        int n = idx / 3, sel = idx % 3;
        const __half* src = g_qkvh
            + (size_t)(bwin * NT + n) * (3 * Cz) + sel * Cz + head * HD + chunk * 8;
        uint32_t dst = sbase + (uint32_t)((sel * APL + n * 40 + chunk * 8) * 2);
        cpasync16(dst, src);
    }
    asm volatile("cp.async.commit_group;");
    asm volatile("cp.async.wait_group 0;");
    __syncthreads();

    // window boundary class -> precomputed bias+mask slab
    int wi = bwin % NW;
    int cls = ((wi / 144) == 3 ? 4 : 0) | (((wi / 12) % 12) == 11 ? 2 : 0)
            | ((wi % 12) == 11 ? 1 : 0);
    const float* Bm = g_bias + (size_t)(cls * HEADS + head) * NTP * NTP;

    uint32_t bQ = sbase, bK = sbase + APL * 2, bV = sbase + 2 * APL * 2;

    int wm = wid * 16;
    int aRow = wm + (lane & 15);
    int aCol = (lane >> 4) * 8;
    int bR = ((lane >> 4) << 3) + (lane & 7);
    int bCol = ((lane >> 3) & 1) * 8;
    int vR = ((lane >> 3) & 1) * 8 + (lane & 7);
    int vCol = (lane >> 4) * 8;

    float sacc[14][4];
    #pragma unroll
    for (int t = 0; t < 14; t++)
        #pragma unroll
        for (int e = 0; e < 4; e++) sacc[t][e] = 0.f;

    #pragma unroll
    for (int kk = 0; kk < 2; kk++) {
        int k0 = kk * 16;
        uint32_t aQ[4], bb[4];
        uint32_t aoff = (uint32_t)((aRow * 40 + k0 + aCol) * 2);
        ldsm4(bQ + aoff, aQ[0], aQ[1], aQ[2], aQ[3]);
        #pragma unroll
        for (int nt = 0; nt < 7; nt++) {
            uint32_t boff = (uint32_t)(((nt * 16 + bR) * 40 + k0 + bCol) * 2);
            ldsm4(bK + boff, bb[0], bb[1], bb[2], bb[3]);
            mma_f16(sacc[nt * 2 + 0], aQ, &bb[0]);
            mma_f16(sacc[nt * 2 + 1], aQ, &bb[2]);
        }
    }

    // precomputed bias/mask add (Q already scaled in qkv epilogue)
    int r0 = wm + (lane >> 2);
    int cbase = (lane & 3) * 2;
    #pragma unroll
    for (int h = 0; h < 2; h++) {
        int r = r0 + h * 8;
        const float2* brow = (const float2*)(Bm + (size_t)r * NTP);
        #pragma unroll
        for (int t = 0; t < 14; t++) {
            float2 bb = brow[t * 4 + (lane & 3)];
            sacc[t][h * 2 + 0] += bb.x;
            sacc[t][h * 2 + 1] += bb.y;
        }
    }

    // softmax in regs (row = quad of lanes)
    #pragma unroll
    for (int h = 0; h < 2; h++) {
        float mx = -1e30f;
        #pragma unroll
        for (int t = 0; t < 14; t++) {
            mx = fmaxf(mx, sacc[t][h * 2 + 0]);
            mx = fmaxf(mx, sacc[t][h * 2 + 1]);
        }
        mx = fmaxf(mx, __shfl_xor_sync(0xffffffffu, mx, 1));
        mx = fmaxf(mx, __shfl_xor_sync(0xffffffffu, mx, 2));
        float sum = 0.f;
        #pragma unroll
        for (int t = 0; t < 14; t++) {
            #pragma unroll
            for (int e = 0; e < 2; e++) {
                float v = __expf(sacc[t][h * 2 + e] - mx);
                sacc[t][h * 2 + e] = v;
                sum += v;
            }
        }
        sum += __shfl_xor_sync(0xffffffffu, sum, 1);
        sum += __shfl_xor_sync(0xffffffffu, sum, 2);
        float inv = 1.f / sum;
        #pragma unroll
        for (int t = 0; t < 14; t++) {
            sacc[t][h * 2 + 0] *= inv;
            sacc[t][h * 2 + 1] *= inv;
        }
    }

    // P @ V (fp16, 1 pass; V via trans-ldmatrix)
    float oacc[4][4];
    #pragma unroll
    for (int i = 0; i < 4; i++)
        #pragma unroll
        for (int e = 0; e < 4; e++) oacc[i][e] = 0.f;

    #pragma unroll
    for (int j = 0; j < 7; j++) {
        uint32_t aP[4];
        #pragma unroll
        for (int q = 0; q < 2; q++) {
            aP[q * 2 + 0] = pack2h(sacc[2 * j + q][0], sacc[2 * j + q][1]);
            aP[q * 2 + 1] = pack2h(sacc[2 * j + q][2], sacc[2 * j + q][3]);
        }
        #pragma unroll
        for (int dg = 0; dg < 2; dg++) {
            uint32_t bb[4];
            uint32_t boff = (uint32_t)(((j * 16 + vR) * 40 + vCol + dg * 16) * 2);
            ldsm4t(bV + boff, bb[0], bb[1], bb[2], bb[3]);
            mma_f16(oacc[dg * 2 + 0], aP, &bb[0]);
            mma_f16(oacc[dg * 2 + 1], aP, &bb[2]);
        }
    }

    #pragma unroll
    for (int h = 0; h < 2; h++) {
        int r = r0 + h * 8;
        if (r < NT) {
            size_t ob = ((size_t)bwin * NT + r) * Cz + head * HD;
            #pragma unroll
            for (int nt = 0; nt < 4; nt++) {
                int c = nt * 8 + cbase;
                *(uint32_t*)(g_aoh + ob + c) =
                    pack2h(oacc[nt][h * 2 + 0], oacc[nt][h * 2 + 1]);
            }
        }
    }
}

// ---------------- 6: reverse + residual + LN2 (warp per token) ------------
__global__ __launch_bounds__(256) void k_rev_res_ln2(
    const float* __restrict__ g2, const float* __restrict__ b2) {
    int t = blockIdx.x * 8 + (threadIdx.x >> 5);
    int lane = threadIdx.x & 31;
    int ft = map_token(t);
    const float4* posrc = (const float4*)(g_po + (size_t)t * Cz);
    const float4* xpsrc = (const float4*)(g_xp + (size_t)ft * Cz);
    float4 p0 = posrc[lane], p1 = posrc[lane + 32];
    float4 x0 = xpsrc[lane], x1 = xpsrc[lane + 32];
    float v[8] = { p0.x + x0.x, p0.y + x0.y, p0.z + x0.z, p0.w + x0.w,
                   p1.x + x1.x, p1.y + x1.y, p1.z + x1.z, p1.w + x1.w };
    float4* xrd = (float4*)(g_xres + (size_t)ft * Cz);
    xrd[lane]      = make_float4(v[0], v[1], v[2], v[3]);
    xrd[lane + 32] = make_float4(v[4], v[5], v[6], v[7]);
    float m, inv;
    warpMeanVar8(v, m, inv);
    float4 g0 = ((const float4*)g2)[lane], g1 = ((const float4*)g2)[lane + 32];
    float4 b0 = ((const float4*)b2)[lane], b1 = ((const float4*)b2)[lane + 32];
    float gg[8] = { g0.x, g0.y, g0.z, g0.w, g1.x, g1.y, g1.z, g1.w };
    float bb[8] = { b0.x, b0.y, b0.z, b0.w, b1.x, b1.y, b1.z, b1.w };
    float o[8];
    #pragma unroll
    for (int i = 0; i < 8; i++) o[i] = (v[i] - m) * inv * gg[i] + bb[i];
    size_t base = (size_t)ft * Cz;
    *(uint2*)(g_l2h + base + lane * 4) =
        make_uint2(pack2h(o[0], o[1]), pack2h(o[2], o[3]));
    *(uint2*)(g_l2h + base + 128 + lane * 4) =
        make_uint2(pack2h(o[4], o[5]), pack2h(o[6], o[7]));
}

// ---------------- 9: transpose out (B,D,H,W,C) -> (B,D,C,W,H) ----------------
__global__ void k_transpose_out(float* __restrict__ out) {
    __shared__ float tile[32][33];
    int bz = blockIdx.z;
    int bd = bz / Wz, w = bz % Wz;
    int h0 = blockIdx.x * 32, c0 = blockIdx.y * 32;
    #pragma unroll
    for (int j = 0; j < 32; j += 8) {
        int c = c0 + threadIdx.x;
        int h = h0 + threadIdx.y + j;
        if (h < Hz)
            tile[threadIdx.y + j][threadIdx.x] =
                g_y[(((size_t)bd * Hz + h) * Wz + w) * Cz + c];
    }
    __syncthreads();
    #pragma unroll
    for (int j = 0; j < 32; j += 8) {
        int h = h0 + threadIdx.x;
        int c = c0 + threadIdx.y + j;
        if (h < Hz)
            out[(((size_t)bd * Cz + c) * Wz + w) * Hz + h] =
                tile[threadIdx.x][threadIdx.y + j];
    }
}

// ---------------- launch ----------------
extern "C" void kernel_launch(void* const* d_in, const int* in_sizes, int n_in,
                              void* d_out, int out_size) {
    const float* x      = (const float*)d_in[0];
    const float* n1g    = (const float*)d_in[1];
    const float* n1b    = (const float*)d_in[2];
    const float* qkv_w  = (const float*)d_in[3];
    const float* rpb    = (const float*)d_in[4];
    const float* proj_w = (const float*)d_in[5];
    const float* proj_b = (const float*)d_in[6];
    const float* n2g    = (const float*)d_in[7];
    const float* n2b    = (const float*)d_in[8];
    const float* fc1_w  = (const float*)d_in[9];
    const float* fc1_b  = (const float*)d_in[10];
    const float* fc2_w  = (const float*)d_in[11];
    const float* fc2_b  = (const float*)d_in[12];
    float* out = (float*)d_out;

    void* p;
    cudaGetSymbolAddress(&p, g_po);   float* po   = (float*)p;
    cudaGetSymbolAddress(&p, g_xres); float* xres = (float*)p;
    cudaGetSymbolAddress(&p, g_y);    float* y    = (float*)p;
    cudaGetSymbolAddress(&p, g_xwh);  __half* xwh = (__half*)p;
    cudaGetSymbolAddress(&p, g_qkvh); __half* qkvh = (__half*)p;
    cudaGetSymbolAddress(&p, g_aoh);  __half* aoh = (__half*)p;
    cudaGetSymbolAddress(&p, g_l2h);  __half* l2h = (__half*)p;
    cudaGetSymbolAddress(&p, g_hih);  __half* hih = (__half*)p;
    cudaGetSymbolAddress(&p, g_wqh);  __half* wqh = (__half*)p;
    cudaGetSymbolAddress(&p, g_wph);  __half* wph = (__half*)p;
    cudaGetSymbolAddress(&p, g_w1h);  __half* w1h = (__half*)p;
    cudaGetSymbolAddress(&p, g_w2h);  __half* w2h = (__half*)p;

    cudaFuncSetAttribute(k_attn_tc, cudaFuncAttributeMaxDynamicSharedMemorySize, ATTN_SMEM_TC);
    cudaFuncSetAttribute(k_gemm_h<0, false, false, 2, true>, cudaFuncAttributeMaxDynamicSharedMemorySize, 4 * PLANE_B);
    cudaFuncSetAttribute(k_gemm_h<0, true, false, 0, false>, cudaFuncAttributeMaxDynamicSharedMemorySize, 4 * PLANE_B);
    cudaFuncSetAttribute(k_gemm_h<1, true, false, 2, false>, cudaFuncAttributeMaxDynamicSharedMemorySize, 4 * PLANE_B);
    cudaFuncSetAttribute(k_gemm_h<0, true, true, 0, false>,  cudaFuncAttributeMaxDynamicSharedMemorySize, 4 * PLANE_B);

    dim3 tb(32, 8);
    dim3 tg(3, 8, Bz * Dz * Wz);

    // 0. weight converts + bias table (tiny)
    k_wcvt<<<(3 * Cz * Cz + 255) / 256, 256>>>(qkv_w, wqh, 3 * Cz * Cz);
    k_wcvt<<<(Cz * Cz + 255) / 256, 256>>>(proj_w, wph, Cz * Cz);
    k_wcvt<<<(HID * Cz + 255) / 256, 256>>>(fc1_w, w1h, HID * Cz);
    k_wcvt<<<(Cz * HID + 255) / 256, 256>>>(fc2_w, w2h, Cz * HID);
    k_bias<<<64, 256>>>(rpb);
    // 1. transpose in
    k_transpose_in<<<tg, tb>>>(x);
    // 2. LN1 + shift + partition (warp per token, fp16 out)
    k_ln_part<<<TOK / 8, 256>>>(n1g, n1b);
    // 3. qkv GEMM (1-pass fp16, N=768, Q pre-scaled)
    k_gemm_h<0, false, false, 2, true><<<dim3(6, TOK / 128), 256, 4 * PLANE_B>>>(
        xwh, wqh, nullptr, nullptr, nullptr, qkvh, TOK, 3 * Cz, Cz, 3 * Cz);
    // 4. attention (fp16 tensor cores, precomputed bias)
    k_attn_tc<<<dim3(HEADS, BW), 224, ATTN_SMEM_TC>>>();
    // 5. proj GEMM -> g_po fp32
    k_gemm_h<0, true, false, 0, false><<<dim3(Cz / 128, TOK / 128), 256, 4 * PLANE_B>>>(
        aoh, wph, proj_b, nullptr, po, nullptr, TOK, Cz, Cz, Cz);
    // 6. reverse + residual + LN2 (warp per token)
    k_rev_res_ln2<<<TOK / 8, 256>>>(n2g, n2b);
    // 7. fc1 GEMM + GELU -> fp16 plane
    k_gemm_h<1, true, false, 2, false><<<dim3(HID / 128, TOK / 128), 256, 4 * PLANE_B>>>(
        l2h, w1h, fc1_b, nullptr, nullptr, hih, TOK, HID, Cz, HID);
    // 8. fc2 GEMM + bias + residual -> y fp32
    k_gemm_h<0, true, true, 0, false><<<dim3(Cz / 128, TOK / 128), 256, 4 * PLANE_B>>>(
        hih, w2h, fc2_b, xres, y, nullptr, TOK, Cz, HID, Cz);
    // 9. transpose out
    k_transpose_out<<<tg, tb>>>(out);
}

// round 14
// speedup vs baseline: 1.6772x; 1.0969x over previous
#include <cuda_runtime.h>
#include <cuda_fp16.h>
#include <math.h>
#include <stdint.h>

// ---------------- problem constants ----------------
#define Bz 2
#define Dz 8
#define Cz 256
#define Wz 84
#define Hz 84
#define HEADS 8
#define HD 32
#define NT 98            // tokens per window (2*7*7)
#define NTP 112          // padded to 7 x 16
#define NW 576           // windows per batch (4*12*12)
#define BW (Bz*NW)       // 1152 window-batches
#define TOK (BW*NT)      // 112896 tokens
#define HID 1024

// ---------------- scratch (device globals; allocation-free) ----------------
__device__ __align__(256) float g_xp  [(size_t)TOK*Cz];   // shortcut (B,D,H,W,C)
__device__ __align__(256) float g_xres[(size_t)TOK*Cz];   // (B,D,H,W,C)
__device__ __align__(256) float g_y   [(size_t)TOK*Cz];
__device__ __align__(256) float g_bias[8 * HEADS * NTP * NTP];  // [cls][head][r][c]
// fp16 activation planes
__device__ __align__(256) __half g_xwh[(size_t)TOK*Cz];
__device__ __align__(256) __half g_qkvh[(size_t)TOK*3*Cz];
__device__ __align__(256) __half g_aoh[(size_t)TOK*Cz];
__device__ __align__(256) __half g_poh[(size_t)TOK*Cz];   // proj out (windowed order)
__device__ __align__(256) __half g_l2h[(size_t)TOK*Cz];
__device__ __align__(256) __half g_hih[(size_t)TOK*HID];
// fp16 weights (contiguous pool: qkv | proj | fc1 | fc2)
__device__ __align__(256) __half g_wqh[3*Cz*Cz];
__device__ __align__(256) __half g_wph[Cz*Cz];
__device__ __align__(256) __half g_w1h[HID*Cz];
__device__ __align__(256) __half g_w2h[Cz*HID];

// ---------------- helpers ----------------
__device__ __forceinline__ uint32_t smem_u32(const void* p) {
    uint32_t a;
    asm("{ .reg .u64 t; cvta.to.shared.u64 t, %1; cvt.u32.u64 %0, t; }" : "=r"(a) : "l"(p));
    return a;
}
__device__ __forceinline__ uint32_t pack2h(float x, float y) {
    __half2 t = __floats2half2_rn(x, y);
    return *(uint32_t*)&t;
}
__device__ __forceinline__ void ldsm4(uint32_t addr, uint32_t& r0, uint32_t& r1,
                                      uint32_t& r2, uint32_t& r3) {
    asm volatile("ldmatrix.sync.aligned.m8n8.x4.shared.b16 {%0,%1,%2,%3}, [%4];"
                 : "=r"(r0), "=r"(r1), "=r"(r2), "=r"(r3) : "r"(addr));
}
__device__ __forceinline__ void ldsm4t(uint32_t addr, uint32_t& r0, uint32_t& r1,
                                       uint32_t& r2, uint32_t& r3) {
    asm volatile("ldmatrix.sync.aligned.m8n8.x4.trans.shared.b16 {%0,%1,%2,%3}, [%4];"
                 : "=r"(r0), "=r"(r1), "=r"(r2), "=r"(r3) : "r"(addr));
}
__device__ __forceinline__ void mma_f16(float* d, const uint32_t* a, const uint32_t* b) {
    asm volatile(
        "mma.sync.aligned.m16n8k16.row.col.f32.f16.f16.f32 "
        "{%0,%1,%2,%3}, {%4,%5,%6,%7}, {%8,%9}, {%0,%1,%2,%3};"
        : "+f"(d[0]), "+f"(d[1]), "+f"(d[2]), "+f"(d[3])
        : "r"(a[0]), "r"(a[1]), "r"(a[2]), "r"(a[3]), "r"(b[0]), "r"(b[1]));
}
__device__ __forceinline__ void cpasync16(uint32_t dst, const void* src) {
    asm volatile("cp.async.cg.shared.global [%0], [%1], 16;" :: "r"(dst), "l"(src));
}

// ---------------- 0a: fused weight convert fp32 -> fp16 (all 4 weights) ---
#define NWQ (3*Cz*Cz)
#define NWP (Cz*Cz)
#define NW1 (HID*Cz)
#define NW2 (Cz*HID)
__global__ void k_wcvt_all(const float* __restrict__ wq, const float* __restrict__ wp,
                           const float* __restrict__ w1, const float* __restrict__ w2) {
    int i = blockIdx.x * 256 + threadIdx.x;
    if (i < NWQ) { g_wqh[i] = __float2half(wq[i]); return; }
    i -= NWQ;
    if (i < NWP) { g_wph[i] = __float2half(wp[i]); return; }
    i -= NWP;
    if (i < NW1) { g_w1h[i] = __float2half(w1[i]); return; }
    i -= NW1;
    if (i < NW2) { g_w2h[i] = __float2half(w2[i]); }
}

// ---------------- 0b: precompute bias+mask per (class, head) ----------------
__global__ void k_bias(const float* __restrict__ rpb) {
    int blk = blockIdx.x;          // cls*8 + head
    int cls = blk >> 3, head = blk & 7;
    float* outp = g_bias + (size_t)blk * NTP * NTP;
    for (int i = threadIdx.x; i < NTP * NTP; i += 256) {
        int r = i / NTP, c = i % NTP;
        float v;
        if (r < NT && c < NT) {
            int dr = r / 49, hr = (r % 49) / 7, wr = r % 7;
            int dc = c / 49, hc = (c % 49) / 7, wc = c % 7;
            int idx = (dr - dc + 1) * 169 + (hr - hc + 6) * 13 + (wr - wc + 6);
            int rgr = ((cls & 4) ? (dr == 0 ? 1 : 2) : 0) * 9
                    + ((cls & 2) ? (hr < 4 ? 1 : 2) : 0) * 3
                    + ((cls & 1) ? (wr < 4 ? 1 : 2) : 0);
            int rgc = ((cls & 4) ? (dc == 0 ? 1 : 2) : 0) * 9
                    + ((cls & 2) ? (hc < 4 ? 1 : 2) : 0) * 3
                    + ((cls & 1) ? (wc < 4 ? 1 : 2) : 0);
            v = rpb[idx * HEADS + head] + (rgr != rgc ? -100.f : 0.f);
        } else {
            v = -30000.f;
        }
        outp[i] = v;
    }
}

// ---------------- 1: transpose in (B,D,C,W,H) -> (B,D,H,W,C) ----------------
__global__ void k_transpose_in(const float* __restrict__ x) {
    __shared__ float tile[32][33];
    int bz = blockIdx.z;
    int bd = bz / Wz, w = bz % Wz;
    int h0 = blockIdx.x * 32, c0 = blockIdx.y * 32;
    #pragma unroll
    for (int j = 0; j < 32; j += 8) {
        int c = c0 + threadIdx.y + j;
        int h = h0 + threadIdx.x;
        if (h < Hz)
            tile[threadIdx.y + j][threadIdx.x] =
                x[(((size_t)bd * Cz + c) * Wz + w) * Hz + h];
    }
    __syncthreads();
    #pragma unroll
    for (int j = 0; j < 32; j += 8) {
        int c = c0 + threadIdx.x;
        int h = h0 + threadIdx.y + j;
        if (h < Hz)
            g_xp[(((size_t)bd * Hz + h) * Wz + w) * Cz + c] =
                tile[threadIdx.x][threadIdx.y + j];
    }
}

__device__ __forceinline__ int map_token(int t) {
    int b   = t / (NW * NT);
    int rem = t % (NW * NT);
    int wi = rem / NT, n = rem % NT;
    int d2 = wi / 144, h2 = (wi / 12) % 12, w2 = wi % 12;
    int dd = n / 49, r = n % 49, hh = r / 7, ww = r % 7;
    int d = d2 * 2 + dd, h = h2 * 7 + hh, w = w2 * 7 + ww;
    int ds = (d + 1) & 7;
    int hs = h + 3; if (hs >= Hz) hs -= Hz;
    int ws = w + 3; if (ws >= Wz) ws -= Wz;
    return ((b * Dz + ds) * Hz + hs) * Wz + ws;
}

// warp-level mean/invstd over 8 regs/thread (256 channels per warp)
__device__ __forceinline__ void warpMeanVar8(const float* v, float& mean, float& invstd) {
    float s1 = 0.f, s2 = 0.f;
    #pragma unroll
    for (int i = 0; i < 8; i++) { s1 += v[i]; s2 += v[i] * v[i]; }
    #pragma unroll
    for (int o = 16; o; o >>= 1) {
        s1 += __shfl_xor_sync(0xffffffffu, s1, o);
        s2 += __shfl_xor_sync(0xffffffffu, s2, o);
    }
    float m = s1 * (1.f / Cz);
    float q = s2 * (1.f / Cz) - m * m;
    mean = m;
    invstd = rsqrtf(q + 1e-5f);
}

// ---------------- 2: LN1 + shift + partition (warp per token) -------------
__global__ __launch_bounds__(256) void k_ln_part(
    const float* __restrict__ g, const float* __restrict__ bta) {
    int t = blockIdx.x * 8 + (threadIdx.x >> 5);
    int lane = threadIdx.x & 31;
    int srct = map_token(t);
    const float4* src = (const float4*)(g_xp + (size_t)srct * Cz);
    float4 a = src[lane], b4 = src[lane + 32];
    float v[8] = { a.x, a.y, a.z, a.w, b4.x, b4.y, b4.z, b4.w };
    float m, inv;
    warpMeanVar8(v, m, inv);
    float4 g0 = ((const float4*)g)[lane],   g1 = ((const float4*)g)[lane + 32];
    float4 b0 = ((const float4*)bta)[lane], b1 = ((const float4*)bta)[lane + 32];
    float gg[8] = { g0.x, g0.y, g0.z, g0.w, g1.x, g1.y, g1.z, g1.w };
    float bb[8] = { b0.x, b0.y, b0.z, b0.w, b1.x, b1.y, b1.z, b1.w };
    float o[8];
    #pragma unroll
    for (int i = 0; i < 8; i++) o[i] = (v[i] - m) * inv * gg[i] + bb[i];
    size_t base = (size_t)t * Cz;
    *(uint2*)(g_xwh + base + lane * 4) =
        make_uint2(pack2h(o[0], o[1]), pack2h(o[2], o[3]));
    *(uint2*)(g_xwh + base + 128 + lane * 4) =
        make_uint2(pack2h(o[4], o[5]), pack2h(o[6], o[7]));
}

// ---------------- GEMM (1-pass fp16, BK=64): out = A[M,K] @ Wt[N,K]^T -----
// OSPLIT: 0 = fp32 out, 2 = fp16 plane out.
// QSCALE: scale output columns n < Cz by 1/sqrt(HD).
#define PADK 72                          // 64 + 8 pad; 144B row stride, conflict-free
#define PLANE_B (128 * PADK * 2)         // 18432 bytes
template <int ACT, bool HAS_BIAS, bool HAS_RES, int OSPLIT, bool QSCALE>
__global__ __launch_bounds__(256, 2) void k_gemm_h(
    const __half* __restrict__ Ah, const __half* __restrict__ Bh,
    const float* __restrict__ bias, const float* __restrict__ res,
    float* __restrict__ out, __half* __restrict__ outh,
    int M, int N, int K, int ostr) {
    extern __shared__ __align__(16) unsigned char dsm[];
    const uint32_t STB = 2 * PLANE_B;
    uint32_t sbase = smem_u32(dsm);
    int tid = threadIdx.x, lane = tid & 31, wid = tid >> 5;
    int bm = blockIdx.y * 128, bn = blockIdx.x * 128;
    int wm = (wid & 1) * 64, wn = (wid >> 1) * 32;

    int aRow = wm + (lane & 15);
    int aCol = (lane >> 4) * 8;
    int bRow = wn + ((lane >> 4) << 3) + (lane & 7);
    int bCol = ((lane >> 3) & 1) * 8;

    float acc[4][4][4];
    #pragma unroll
    for (int i = 0; i < 4; i++)
        #pragma unroll
        for (int j = 0; j < 4; j++)
            #pragma unroll
            for (int c = 0; c < 4; c++) acc[i][j][c] = 0.f;

    const int nChunks = K >> 6;

    // fill: 128 rows x 64 cols per plane -> 1024 x 16B per plane, 8/thread total
    #define ISSUE(ch, s) do {                                                   \
        int k0_ = (ch) << 6;                                                    \
        uint32_t sb_ = sbase + (s) * STB;                                       \
        _Pragma("unroll")                                                       \
        for (int q_ = 0; q_ < 4; q_++) {                                        \
            int j_ = q_ * 256 + tid;                                            \
            int row_ = j_ >> 3, c8_ = (j_ & 7) * 8;                             \
            uint32_t so_ = (uint32_t)((row_ * PADK + c8_) * 2);                 \
            cpasync16(sb_ + so_, Ah + (size_t)(bm + row_) * K + k0_ + c8_);     \
            cpasync16(sb_ + PLANE_B + so_,                                      \
                      Bh + (size_t)(bn + row_) * K + k0_ + c8_);                \
        }                                                                       \
        asm volatile("cp.async.commit_group;");                                 \
    } while (0)

    ISSUE(0, 0);
    for (int ch = 0; ch < nChunks; ch++) {
        int s = ch & 1;
        if (ch + 1 < nChunks) {
            ISSUE(ch + 1, (ch + 1) & 1);
            asm volatile("cp.async.wait_group 1;");
        } else {
            asm volatile("cp.async.wait_group 0;");
        }
        __syncthreads();

        uint32_t baseA = sbase + s * STB;
        uint32_t baseB = baseA + PLANE_B;

        #pragma unroll
        for (int kk = 0; kk < 4; kk++) {
            int k0 = kk * 16;
            uint32_t aH[4][4], bb[8];
            #pragma unroll
            for (int mi = 0; mi < 4; mi++) {
                uint32_t off = (uint32_t)(((aRow + mi * 16) * PADK + k0 + aCol) * 2);
                ldsm4(baseA + off, aH[mi][0], aH[mi][1], aH[mi][2], aH[mi][3]);
            }
            #pragma unroll
            for (int p = 0; p < 2; p++) {
                uint32_t off = (uint32_t)(((bRow + p * 16) * PADK + k0 + bCol) * 2);
                ldsm4(baseB + off, bb[p * 4 + 0], bb[p * 4 + 1], bb[p * 4 + 2], bb[p * 4 + 3]);
            }
            #pragma unroll
            for (int mi = 0; mi < 4; mi++)
                #pragma unroll
                for (int ni = 0; ni < 4; ni++)
                    mma_f16(acc[mi][ni], aH[mi], &bb[ni * 2]);
        }
        __syncthreads();
    }
    #undef ISSUE

    int orow = lane >> 2, ocol = (lane & 3) * 2;
    #pragma unroll
    for (int mi = 0; mi < 4; mi++) {
        int m0 = bm + wm + mi * 16;
        #pragma unroll
        for (int ni = 0; ni < 4; ni++) {
            int n = bn + wn + ni * 8 + ocol;
            float bi0 = 0.f, bi1 = 0.f;
            if (HAS_BIAS) { bi0 = bias[n]; bi1 = bias[n + 1]; }
            float sc = (QSCALE && n < Cz) ? 0.17677669529663687f : 1.f;
            #pragma unroll
            for (int half = 0; half < 2; half++) {
                int m = m0 + orow + half * 8;
                float v0 = acc[mi][ni][half * 2 + 0] + bi0;
                float v1 = acc[mi][ni][half * 2 + 1] + bi1;
                if (QSCALE) { v0 *= sc; v1 *= sc; }
                if (ACT == 1) {
                    v0 = 0.5f * v0 * (1.f + erff(v0 * 0.70710678118654752f));
                    v1 = 0.5f * v1 * (1.f + erff(v1 * 0.70710678118654752f));
                }
                if (HAS_RES) {
                    const float2 r2 = *(const float2*)(res + (size_t)m * ostr + n);
                    v0 += r2.x; v1 += r2.y;
                }
                if (OSPLIT == 2) {
                    *(uint32_t*)(outh + (size_t)m * ostr + n) = pack2h(v0, v1);
                } else {
                    *(float2*)(out + (size_t)m * ostr + n) = make_float2(v0, v1);
                }
            }
        }
    }
}

// ---------------- 4: fp16 tensor-core attention per (head, window) --------
#define APL (NTP * 40)                 // 4480 halves per plane
#define ATTN_SMEM_TC (3 * APL * 2)     // 26880 bytes
__global__ __launch_bounds__(224, 2) void k_attn_tc() {
    extern __shared__ __half asm_[];
    int head = blockIdx.x, bwin = blockIdx.y;
    int tid = threadIdx.x, lane = tid & 31, wid = tid >> 5;
    uint32_t sbase = smem_u32(asm_);

    // zero pad rows 98..111 of all 3 planes
    for (int i = tid; i < 3 * 280; i += 224) {
        int p = i / 280, r = i % 280;
        ((uint32_t*)(asm_ + p * APL + NT * 40))[r] = 0u;
    }

    // fill: 98 tokens x {q,k,v} x 4 x 16B cp.async copies
    for (int i = tid; i < 98 * 3 * 4; i += 224) {
        int chunk = i & 3;
        int idx = i >> 2;
        int n = idx / 3, sel = idx % 3;
        const __half* src = g_qkvh
            + (size_t)(bwin * NT + n) * (3 * Cz) + sel * Cz + head * HD + chunk * 8;
        uint32_t dst = sbase + (uint32_t)((sel * APL + n * 40 + chunk * 8) * 2);
        cpasync16(dst, src);
    }
    asm volatile("cp.async.commit_group;");
    asm volatile("cp.async.wait_group 0;");
    __syncthreads();

    // window boundary class -> precomputed bias+mask slab
    int wi = bwin % NW;
    int cls = ((wi / 144) == 3 ? 4 : 0) | (((wi / 12) % 12) == 11 ? 2 : 0)
            | ((wi % 12) == 11 ? 1 : 0);
    const float* Bm = g_bias + (size_t)(cls * HEADS + head) * NTP * NTP;

    uint32_t bQ = sbase, bK = sbase + APL * 2, bV = sbase + 2 * APL * 2;

    int wm = wid * 16;
    int aRow = wm + (lane & 15);
    int aCol = (lane >> 4) * 8;
    int bR = ((lane >> 4) << 3) + (lane & 7);
    int bCol = ((lane >> 3) & 1) * 8;
    int vR = ((lane >> 3) & 1) * 8 + (lane & 7);
    int vCol = (lane >> 4) * 8;

    float sacc[14][4];
    #pragma unroll
    for (int t = 0; t < 14; t++)
        #pragma unroll
        for (int e = 0; e < 4; e++) sacc[t][e] = 0.f;

    #pragma unroll
    for (int kk = 0; kk < 2; kk++) {
        int k0 = kk * 16;
        uint32_t aQ[4], bb[4];
        uint32_t aoff = (uint32_t)((aRow * 40 + k0 + aCol) * 2);
        ldsm4(bQ + aoff, aQ[0], aQ[1], aQ[2], aQ[3]);
        #pragma unroll
        for (int nt = 0; nt < 7; nt++) {
            uint32_t boff = (uint32_t)(((nt * 16 + bR) * 40 + k0 + bCol) * 2);
            ldsm4(bK + boff, bb[0], bb[1], bb[2], bb[3]);
            mma_f16(sacc[nt * 2 + 0], aQ, &bb[0]);
            mma_f16(sacc[nt * 2 + 1], aQ, &bb[2]);
        }
    }

    // precomputed bias/mask add (Q already scaled in qkv epilogue)
    int r0 = wm + (lane >> 2);
    int cbase = (lane & 3) * 2;
    #pragma unroll
    for (int h = 0; h < 2; h++) {
        int r = r0 + h * 8;
        const float2* brow = (const float2*)(Bm + (size_t)r * NTP);
        #pragma unroll
        for (int t = 0; t < 14; t++) {
            float2 bb = brow[t * 4 + (lane & 3)];
            sacc[t][h * 2 + 0] += bb.x;
            sacc[t][h * 2 + 1] += bb.y;
        }
    }

    // softmax in regs (row = quad of lanes)
    #pragma unroll
    for (int h = 0; h < 2; h++) {
        float mx = -1e30f;
        #pragma unroll
        for (int t = 0; t < 14; t++) {
            mx = fmaxf(mx, sacc[t][h * 2 + 0]);
            mx = fmaxf(mx, sacc[t][h * 2 + 1]);
        }
        mx = fmaxf(mx, __shfl_xor_sync(0xffffffffu, mx, 1));
        mx = fmaxf(mx, __shfl_xor_sync(0xffffffffu, mx, 2));
        float sum = 0.f;
        #pragma unroll
        for (int t = 0; t < 14; t++) {
            #pragma unroll
            for (int e = 0; e < 2; e++) {
                float v = __expf(sacc[t][h * 2 + e] - mx);
                sacc[t][h * 2 + e] = v;
                sum += v;
            }
        }
        sum += __shfl_xor_sync(0xffffffffu, sum, 1);
        sum += __shfl_xor_sync(0xffffffffu, sum, 2);
        float inv = 1.f / sum;
        #pragma unroll
        for (int t = 0; t < 14; t++) {
            sacc[t][h * 2 + 0] *= inv;
            sacc[t][h * 2 + 1] *= inv;
        }
    }

    // P @ V (fp16, 1 pass; V via trans-ldmatrix)
    float oacc[4][4];
    #pragma unroll
    for (int i = 0; i < 4; i++)
        #pragma unroll
        for (int e = 0; e < 4; e++) oacc[i][e] = 0.f;

    #pragma unroll
    for (int j = 0; j < 7; j++) {
        uint32_t aP[4];
        #pragma unroll
        for (int q = 0; q < 2; q++) {
            aP[q * 2 + 0] = pack2h(sacc[2 * j + q][0], sacc[2 * j + q][1]);
            aP[q * 2 + 1] = pack2h(sacc[2 * j + q][2], sacc[2 * j + q][3]);
        }
        #pragma unroll
        for (int dg = 0; dg < 2; dg++) {
            uint32_t bb[4];
            uint32_t boff = (uint32_t)(((j * 16 + vR) * 40 + vCol + dg * 16) * 2);
            ldsm4t(bV + boff, bb[0], bb[1], bb[2], bb[3]);
            mma_f16(oacc[dg * 2 + 0], aP, &bb[0]);
            mma_f16(oacc[dg * 2 + 1], aP, &bb[2]);
        }
    }

    #pragma unroll
    for (int h = 0; h < 2; h++) {
        int r = r0 + h * 8;
        if (r < NT) {
            size_t ob = ((size_t)bwin * NT + r) * Cz + head * HD;
            #pragma unroll
            for (int nt = 0; nt < 4; nt++) {
                int c = nt * 8 + cbase;
                *(uint32_t*)(g_aoh + ob + c) =
                    pack2h(oacc[nt][h * 2 + 0], oacc[nt][h * 2 + 1]);
            }
        }
    }
}

// ---------------- 6: reverse + residual + LN2 (warp per token) ------------
__global__ __launch_bounds__(256) void k_rev_res_ln2(
    const float* __restrict__ g2, const float* __restrict__ b2) {
    int t = blockIdx.x * 8 + (threadIdx.x >> 5);
    int lane = threadIdx.x & 31;
    int ft = map_token(t);
    // proj out (fp16) 8 halves per lane
    const uint2* posrc = (const uint2*)(g_poh + (size_t)t * Cz);
    uint2 ph0 = posrc[lane], ph1 = posrc[lane + 32];
    __half2 p01 = *(__half2*)&ph0.x, p23 = *(__half2*)&ph0.y;
    __half2 p45 = *(__half2*)&ph1.x, p67 = *(__half2*)&ph1.y;
    float2 f01 = __half22float2(p01), f23 = __half22float2(p23);
    float2 f45 = __half22float2(p45), f67 = __half22float2(p67);
    const float4* xpsrc = (const float4*)(g_xp + (size_t)ft * Cz);
    float4 x0 = xpsrc[lane], x1 = xpsrc[lane + 32];
    float v[8] = { f01.x + x0.x, f01.y + x0.y, f23.x + x0.z, f23.y + x0.w,
                   f45.x + x1.x, f45.y + x1.y, f67.x + x1.z, f67.y + x1.w };
    float4* xrd = (float4*)(g_xres + (size_t)ft * Cz);
    xrd[lane]      = make_float4(v[0], v[1], v[2], v[3]);
    xrd[lane + 32] = make_float4(v[4], v[5], v[6], v[7]);
    float m, inv;
    warpMeanVar8(v, m, inv);
    float4 g0 = ((const float4*)g2)[lane], g1 = ((const float4*)g2)[lane + 32];
    float4 b0 = ((const float4*)b2)[lane], b1 = ((const float4*)b2)[lane + 32];
    float gg[8] = { g0.x, g0.y, g0.z, g0.w, g1.x, g1.y, g1.z, g1.w };
    float bb[8] = { b0.x, b0.y, b0.z, b0.w, b1.x, b1.y, b1.z, b1.w };
    float o[8];
    #pragma unroll
    for (int i = 0; i < 8; i++) o[i] = (v[i] - m) * inv * gg[i] + bb[i];
    size_t base = (size_t)ft * Cz;
    *(uint2*)(g_l2h + base + lane * 4) =
        make_uint2(pack2h(o[0], o[1]), pack2h(o[2], o[3]));
    *(uint2*)(g_l2h + base + 128 + lane * 4) =
        make_uint2(pack2h(o[4], o[5]), pack2h(o[6], o[7]));
}

// ---------------- 9: transpose out (B,D,H,W,C) -> (B,D,C,W,H) ----------------
__global__ void k_transpose_out(float* __restrict__ out) {
    __shared__ float tile[32][33];
    int bz = blockIdx.z;
    int bd = bz / Wz, w = bz % Wz;
    int h0 = blockIdx.x * 32, c0 = blockIdx.y * 32;
    #pragma unroll
    for (int j = 0; j < 32; j += 8) {
        int c = c0 + threadIdx.x;
        int h = h0 + threadIdx.y + j;
        if (h < Hz)
            tile[threadIdx.y + j][threadIdx.x] =
                g_y[(((size_t)bd * Hz + h) * Wz + w) * Cz + c];
    }
    __syncthreads();
    #pragma unroll
    for (int j = 0; j < 32; j += 8) {
        int h = h0 + threadIdx.x;
        int c = c0 + threadIdx.y + j;
        if (h < Hz)
            out[(((size_t)bd * Cz + c) * Wz + w) * Hz + h] =
                tile[threadIdx.x][threadIdx.y + j];
    }
}

// ---------------- launch ----------------
extern "C" void kernel_launch(void* const* d_in, const int* in_sizes, int n_in,
                              void* d_out, int out_size) {
    const float* x      = (const float*)d_in[0];
    const float* n1g    = (const float*)d_in[1];
    const float* n1b    = (const float*)d_in[2];
    const float* qkv_w  = (const float*)d_in[3];
    const float* rpb    = (const float*)d_in[4];
    const float* proj_w = (const float*)d_in[5];
    const float* proj_b = (const float*)d_in[6];
    const float* n2g    = (const float*)d_in[7];
    const float* n2b    = (const float*)d_in[8];
    const float* fc1_w  = (const float*)d_in[9];
    const float* fc1_b  = (const float*)d_in[10];
    const float* fc2_w  = (const float*)d_in[11];
    const float* fc2_b  = (const float*)d_in[12];
    float* out = (float*)d_out;

    void* p;
    cudaGetSymbolAddress(&p, g_xres); float* xres = (float*)p;
    cudaGetSymbolAddress(&p, g_y);    float* y    = (float*)p;
    cudaGetSymbolAddress(&p, g_xwh);  __half* xwh = (__half*)p;
    cudaGetSymbolAddress(&p, g_qkvh); __half* qkvh = (__half*)p;
    cudaGetSymbolAddress(&p, g_aoh);  __half* aoh = (__half*)p;
    cudaGetSymbolAddress(&p, g_poh);  __half* poh = (__half*)p;
    cudaGetSymbolAddress(&p, g_l2h);  __half* l2h = (__half*)p;
    cudaGetSymbolAddress(&p, g_hih);  __half* hih = (__half*)p;
    cudaGetSymbolAddress(&p, g_wqh);  __half* wqh = (__half*)p;
    cudaGetSymbolAddress(&p, g_wph);  __half* wph = (__half*)p;
    cudaGetSymbolAddress(&p, g_w1h);  __half* w1h = (__half*)p;
    cudaGetSymbolAddress(&p, g_w2h);  __half* w2h = (__half*)p;

    cudaFuncSetAttribute(k_attn_tc, cudaFuncAttributeMaxDynamicSharedMemorySize, ATTN_SMEM_TC);
    cudaFuncSetAttribute(k_gemm_h<0, false, false, 2, true>, cudaFuncAttributeMaxDynamicSharedMemorySize, 4 * PLANE_B);
    cudaFuncSetAttribute(k_gemm_h<0, true, false, 2, false>, cudaFuncAttributeMaxDynamicSharedMemorySize, 4 * PLANE_B);
    cudaFuncSetAttribute(k_gemm_h<1, true, false, 2, false>, cudaFuncAttributeMaxDynamicSharedMemorySize, 4 * PLANE_B);
    cudaFuncSetAttribute(k_gemm_h<0, true, true, 0, false>,  cudaFuncAttributeMaxDynamicSharedMemorySize, 4 * PLANE_B);

    dim3 tb(32, 8);
    dim3 tg(3, 8, Bz * Dz * Wz);

    // 0. fused weight convert + bias table (tiny)
    k_wcvt_all<<<(NWQ + NWP + NW1 + NW2 + 255) / 256, 256>>>(qkv_w, proj_w, fc1_w, fc2_w);
    k_bias<<<64, 256>>>(rpb);
    // 1. transpose in
    k_transpose_in<<<tg, tb>>>(x);
    // 2. LN1 + shift + partition (warp per token, fp16 out)
    k_ln_part<<<TOK / 8, 256>>>(n1g, n1b);
    // 3. qkv GEMM (1-pass fp16, N=768, Q pre-scaled)
    k_gemm_h<0, false, false, 2, true><<<dim3(6, TOK / 128), 256, 4 * PLANE_B>>>(
        xwh, wqh, nullptr, nullptr, nullptr, qkvh, TOK, 3 * Cz, Cz, 3 * Cz);
    // 4. attention (fp16 tensor cores, precomputed bias)
    k_attn_tc<<<dim3(HEADS, BW), 224, ATTN_SMEM_TC>>>();
    // 5. proj GEMM -> fp16 plane
    k_gemm_h<0, true, false, 2, false><<<dim3(Cz / 128, TOK / 128), 256, 4 * PLANE_B>>>(
        aoh, wph, proj_b, nullptr, nullptr, poh, TOK, Cz, Cz, Cz);
    // 6. reverse + residual + LN2 (warp per token)
    k_rev_res_ln2<<<TOK / 8, 256>>>(n2g, n2b);
    // 7. fc1 GEMM + GELU -> fp16 plane
    k_gemm_h<1, true, false, 2, false><<<dim3(HID / 128, TOK / 128), 256, 4 * PLANE_B>>>(
        l2h, w1h, fc1_b, nullptr, nullptr, hih, TOK, HID, Cz, HID);
    // 8. fc2 GEMM + bias + residual -> y fp32
    k_gemm_h<0, true, true, 0, false><<<dim3(Cz / 128, TOK / 128), 256, 4 * PLANE_B>>>(
        hih, w2h, fc2_b, xres, y, nullptr, TOK, Cz, HID, Cz);
    // 9. transpose out
    k_transpose_out<<<tg, tb>>>(out);
}

// round 15
// speedup vs baseline: 1.7057x; 1.0170x over previous
#include <cuda_runtime.h>
#include <cuda_fp16.h>
#include <math.h>
#include <stdint.h>

// ---------------- problem constants ----------------
#define Bz 2
#define Dz 8
#define Cz 256
#define Wz 84
#define Hz 84
#define HEADS 8
#define HD 32
#define NT 98            // tokens per window (2*7*7)
#define NTP 112          // padded to 7 x 16
#define NW 576           // windows per batch (4*12*12)
#define BW (Bz*NW)       // 1152 window-batches
#define TOK (BW*NT)      // 112896 tokens
#define HID 1024

// ---------------- scratch (device globals; allocation-free) ----------------
__device__ __align__(256) float g_xp  [(size_t)TOK*Cz];   // shortcut (B,D,H,W,C), fp32
__device__ __align__(256) float g_bias[8 * HEADS * NTP * NTP];  // [cls][head][r][c]
// fp16 activation planes
__device__ __align__(256) __half g_xwh[(size_t)TOK*Cz];
__device__ __align__(256) __half g_qkvh[(size_t)TOK*3*Cz];
__device__ __align__(256) __half g_aoh[(size_t)TOK*Cz];
__device__ __align__(256) __half g_poh[(size_t)TOK*Cz];   // proj out (windowed order)
__device__ __align__(256) __half g_xrh[(size_t)TOK*Cz];   // residual trunk (B,D,H,W,C)
__device__ __align__(256) __half g_l2h[(size_t)TOK*Cz];
__device__ __align__(256) __half g_hih[(size_t)TOK*HID];
__device__ __align__(256) __half g_yh [(size_t)TOK*Cz];   // final trunk (B,D,H,W,C)
// fp16 weights
__device__ __align__(256) __half g_wqh[3*Cz*Cz];
__device__ __align__(256) __half g_wph[Cz*Cz];
__device__ __align__(256) __half g_w1h[HID*Cz];
__device__ __align__(256) __half g_w2h[Cz*HID];

// ---------------- helpers ----------------
__device__ __forceinline__ uint32_t smem_u32(const void* p) {
    uint32_t a;
    asm("{ .reg .u64 t; cvta.to.shared.u64 t, %1; cvt.u32.u64 %0, t; }" : "=r"(a) : "l"(p));
    return a;
}
__device__ __forceinline__ uint32_t pack2h(float x, float y) {
    __half2 t = __floats2half2_rn(x, y);
    return *(uint32_t*)&t;
}
__device__ __forceinline__ void ldsm4(uint32_t addr, uint32_t& r0, uint32_t& r1,
                                      uint32_t& r2, uint32_t& r3) {
    asm volatile("ldmatrix.sync.aligned.m8n8.x4.shared.b16 {%0,%1,%2,%3}, [%4];"
                 : "=r"(r0), "=r"(r1), "=r"(r2), "=r"(r3) : "r"(addr));
}
__device__ __forceinline__ void ldsm4t(uint32_t addr, uint32_t& r0, uint32_t& r1,
                                       uint32_t& r2, uint32_t& r3) {
    asm volatile("ldmatrix.sync.aligned.m8n8.x4.trans.shared.b16 {%0,%1,%2,%3}, [%4];"
                 : "=r"(r0), "=r"(r1), "=r"(r2), "=r"(r3) : "r"(addr));
}
__device__ __forceinline__ void mma_f16(float* d, const uint32_t* a, const uint32_t* b) {
    asm volatile(
        "mma.sync.aligned.m16n8k16.row.col.f32.f16.f16.f32 "
        "{%0,%1,%2,%3}, {%4,%5,%6,%7}, {%8,%9}, {%0,%1,%2,%3};"
        : "+f"(d[0]), "+f"(d[1]), "+f"(d[2]), "+f"(d[3])
        : "r"(a[0]), "r"(a[1]), "r"(a[2]), "r"(a[3]), "r"(b[0]), "r"(b[1]));
}
__device__ __forceinline__ void cpasync16(uint32_t dst, const void* src) {
    asm volatile("cp.async.cg.shared.global [%0], [%1], 16;" :: "r"(dst), "l"(src));
}

// ---------------- 0a: fused weight convert fp32 -> fp16 (all 4 weights) ---
#define NWQ (3*Cz*Cz)
#define NWP (Cz*Cz)
#define NW1 (HID*Cz)
#define NW2 (Cz*HID)
__global__ void k_wcvt_all(const float* __restrict__ wq, const float* __restrict__ wp,
                           const float* __restrict__ w1, const float* __restrict__ w2) {
    int i = blockIdx.x * 256 + threadIdx.x;
    if (i < NWQ) { g_wqh[i] = __float2half(wq[i]); return; }
    i -= NWQ;
    if (i < NWP) { g_wph[i] = __float2half(wp[i]); return; }
    i -= NWP;
    if (i < NW1) { g_w1h[i] = __float2half(w1[i]); return; }
    i -= NW1;
    if (i < NW2) { g_w2h[i] = __float2half(w2[i]); }
}

// ---------------- 0b: precompute bias+mask per (class, head) ----------------
__global__ void k_bias(const float* __restrict__ rpb) {
    int blk = blockIdx.x;          // cls*8 + head
    int cls = blk >> 3, head = blk & 7;
    float* outp = g_bias + (size_t)blk * NTP * NTP;
    for (int i = threadIdx.x; i < NTP * NTP; i += 256) {
        int r = i / NTP, c = i % NTP;
        float v;
        if (r < NT && c < NT) {
            int dr = r / 49, hr = (r % 49) / 7, wr = r % 7;
            int dc = c / 49, hc = (c % 49) / 7, wc = c % 7;
            int idx = (dr - dc + 1) * 169 + (hr - hc + 6) * 13 + (wr - wc + 6);
            int rgr = ((cls & 4) ? (dr == 0 ? 1 : 2) : 0) * 9
                    + ((cls & 2) ? (hr < 4 ? 1 : 2) : 0) * 3
                    + ((cls & 1) ? (wr < 4 ? 1 : 2) : 0);
            int rgc = ((cls & 4) ? (dc == 0 ? 1 : 2) : 0) * 9
                    + ((cls & 2) ? (hc < 4 ? 1 : 2) : 0) * 3
                    + ((cls & 1) ? (wc < 4 ? 1 : 2) : 0);
            v = rpb[idx * HEADS + head] + (rgr != rgc ? -100.f : 0.f);
        } else {
            v = -30000.f;
        }
        outp[i] = v;
    }
}

// ---------------- 1: transpose in (B,D,C,W,H) -> (B,D,H,W,C) ----------------
__global__ void k_transpose_in(const float* __restrict__ x) {
    __shared__ float tile[32][33];
    int bz = blockIdx.z;
    int bd = bz / Wz, w = bz % Wz;
    int h0 = blockIdx.x * 32, c0 = blockIdx.y * 32;
    #pragma unroll
    for (int j = 0; j < 32; j += 8) {
        int c = c0 + threadIdx.y + j;
        int h = h0 + threadIdx.x;
        if (h < Hz)
            tile[threadIdx.y + j][threadIdx.x] =
                x[(((size_t)bd * Cz + c) * Wz + w) * Hz + h];
    }
    __syncthreads();
    #pragma unroll
    for (int j = 0; j < 32; j += 8) {
        int c = c0 + threadIdx.x;
        int h = h0 + threadIdx.y + j;
        if (h < Hz)
            g_xp[(((size_t)bd * Hz + h) * Wz + w) * Cz + c] =
                tile[threadIdx.x][threadIdx.y + j];
    }
}

__device__ __forceinline__ int map_token(int t) {
    int b   = t / (NW * NT);
    int rem = t % (NW * NT);
    int wi = rem / NT, n = rem % NT;
    int d2 = wi / 144, h2 = (wi / 12) % 12, w2 = wi % 12;
    int dd = n / 49, r = n % 49, hh = r / 7, ww = r % 7;
    int d = d2 * 2 + dd, h = h2 * 7 + hh, w = w2 * 7 + ww;
    int ds = (d + 1) & 7;
    int hs = h + 3; if (hs >= Hz) hs -= Hz;
    int ws = w + 3; if (ws >= Wz) ws -= Wz;
    return ((b * Dz + ds) * Hz + hs) * Wz + ws;
}

// warp-level mean/invstd over 8 regs/thread (256 channels per warp)
__device__ __forceinline__ void warpMeanVar8(const float* v, float& mean, float& invstd) {
    float s1 = 0.f, s2 = 0.f;
    #pragma unroll
    for (int i = 0; i < 8; i++) { s1 += v[i]; s2 += v[i] * v[i]; }
    #pragma unroll
    for (int o = 16; o; o >>= 1) {
        s1 += __shfl_xor_sync(0xffffffffu, s1, o);
        s2 += __shfl_xor_sync(0xffffffffu, s2, o);
    }
    float m = s1 * (1.f / Cz);
    float q = s2 * (1.f / Cz) - m * m;
    mean = m;
    invstd = rsqrtf(q + 1e-5f);
}

// ---------------- 2: LN1 + shift + partition (warp per token) -------------
__global__ __launch_bounds__(256) void k_ln_part(
    const float* __restrict__ g, const float* __restrict__ bta) {
    int t = blockIdx.x * 8 + (threadIdx.x >> 5);
    int lane = threadIdx.x & 31;
    int srct = map_token(t);
    const float4* src = (const float4*)(g_xp + (size_t)srct * Cz);
    float4 a = src[lane], b4 = src[lane + 32];
    float v[8] = { a.x, a.y, a.z, a.w, b4.x, b4.y, b4.z, b4.w };
    float m, inv;
    warpMeanVar8(v, m, inv);
    float4 g0 = ((const float4*)g)[lane],   g1 = ((const float4*)g)[lane + 32];
    float4 b0 = ((const float4*)bta)[lane], b1 = ((const float4*)bta)[lane + 32];
    float gg[8] = { g0.x, g0.y, g0.z, g0.w, g1.x, g1.y, g1.z, g1.w };
    float bb[8] = { b0.x, b0.y, b0.z, b0.w, b1.x, b1.y, b1.z, b1.w };
    float o[8];
    #pragma unroll
    for (int i = 0; i < 8; i++) o[i] = (v[i] - m) * inv * gg[i] + bb[i];
    size_t base = (size_t)t * Cz;
    *(uint2*)(g_xwh + base + lane * 4) =
        make_uint2(pack2h(o[0], o[1]), pack2h(o[2], o[3]));
    *(uint2*)(g_xwh + base + 128 + lane * 4) =
        make_uint2(pack2h(o[4], o[5]), pack2h(o[6], o[7]));
}

// ---------------- GEMM (1-pass fp16, BK=64): out = A[M,K] @ Wt[N,K]^T -----
// Output always fp16 plane. Optional fp16 residual. QSCALE scales n < Cz.
#define PADK 72                          // 64 + 8 pad; 144B row stride, conflict-free
#define PLANE_B (128 * PADK * 2)         // 18432 bytes
template <int ACT, bool HAS_BIAS, bool HAS_RES, bool QSCALE>
__global__ __launch_bounds__(256, 2) void k_gemm_h(
    const __half* __restrict__ Ah, const __half* __restrict__ Bh,
    const float* __restrict__ bias, const __half* __restrict__ res,
    __half* __restrict__ outh,
    int M, int N, int K, int ostr) {
    extern __shared__ __align__(16) unsigned char dsm[];
    const uint32_t STB = 2 * PLANE_B;
    uint32_t sbase = smem_u32(dsm);
    int tid = threadIdx.x, lane = tid & 31, wid = tid >> 5;
    int bm = blockIdx.y * 128, bn = blockIdx.x * 128;
    int wm = (wid & 1) * 64, wn = (wid >> 1) * 32;

    int aRow = wm + (lane & 15);
    int aCol = (lane >> 4) * 8;
    int bRow = wn + ((lane >> 4) << 3) + (lane & 7);
    int bCol = ((lane >> 3) & 1) * 8;

    float acc[4][4][4];
    #pragma unroll
    for (int i = 0; i < 4; i++)
        #pragma unroll
        for (int j = 0; j < 4; j++)
            #pragma unroll
            for (int c = 0; c < 4; c++) acc[i][j][c] = 0.f;

    const int nChunks = K >> 6;

    #define ISSUE(ch, s) do {                                                   \
        int k0_ = (ch) << 6;                                                    \
        uint32_t sb_ = sbase + (s) * STB;                                       \
        _Pragma("unroll")                                                       \
        for (int q_ = 0; q_ < 4; q_++) {                                        \
            int j_ = q_ * 256 + tid;                                            \
            int row_ = j_ >> 3, c8_ = (j_ & 7) * 8;                             \
            uint32_t so_ = (uint32_t)((row_ * PADK + c8_) * 2);                 \
            cpasync16(sb_ + so_, Ah + (size_t)(bm + row_) * K + k0_ + c8_);     \
            cpasync16(sb_ + PLANE_B + so_,                                      \
                      Bh + (size_t)(bn + row_) * K + k0_ + c8_);                \
        }                                                                       \
        asm volatile("cp.async.commit_group;");                                 \
    } while (0)

    ISSUE(0, 0);
    for (int ch = 0; ch < nChunks; ch++) {
        int s = ch & 1;
        if (ch + 1 < nChunks) {
            ISSUE(ch + 1, (ch + 1) & 1);
            asm volatile("cp.async.wait_group 1;");
        } else {
            asm volatile("cp.async.wait_group 0;");
        }
        __syncthreads();

        uint32_t baseA = sbase + s * STB;
        uint32_t baseB = baseA + PLANE_B;

        #pragma unroll
        for (int kk = 0; kk < 4; kk++) {
            int k0 = kk * 16;
            uint32_t aH[4][4], bb[8];
            #pragma unroll
            for (int mi = 0; mi < 4; mi++) {
                uint32_t off = (uint32_t)(((aRow + mi * 16) * PADK + k0 + aCol) * 2);
                ldsm4(baseA + off, aH[mi][0], aH[mi][1], aH[mi][2], aH[mi][3]);
            }
            #pragma unroll
            for (int p = 0; p < 2; p++) {
                uint32_t off = (uint32_t)(((bRow + p * 16) * PADK + k0 + bCol) * 2);
                ldsm4(baseB + off, bb[p * 4 + 0], bb[p * 4 + 1], bb[p * 4 + 2], bb[p * 4 + 3]);
            }
            #pragma unroll
            for (int mi = 0; mi < 4; mi++)
                #pragma unroll
                for (int ni = 0; ni < 4; ni++)
                    mma_f16(acc[mi][ni], aH[mi], &bb[ni * 2]);
        }
        __syncthreads();
    }
    #undef ISSUE

    int orow = lane >> 2, ocol = (lane & 3) * 2;
    #pragma unroll
    for (int mi = 0; mi < 4; mi++) {
        int m0 = bm + wm + mi * 16;
        #pragma unroll
        for (int ni = 0; ni < 4; ni++) {
            int n = bn + wn + ni * 8 + ocol;
            float bi0 = 0.f, bi1 = 0.f;
            if (HAS_BIAS) { bi0 = bias[n]; bi1 = bias[n + 1]; }
            float sc = (QSCALE && n < Cz) ? 0.17677669529663687f : 1.f;
            #pragma unroll
            for (int half = 0; half < 2; half++) {
                int m = m0 + orow + half * 8;
                float v0 = acc[mi][ni][half * 2 + 0] + bi0;
                float v1 = acc[mi][ni][half * 2 + 1] + bi1;
                if (QSCALE) { v0 *= sc; v1 *= sc; }
                if (ACT == 1) {
                    v0 = 0.5f * v0 * (1.f + erff(v0 * 0.70710678118654752f));
                    v1 = 0.5f * v1 * (1.f + erff(v1 * 0.70710678118654752f));
                }
                if (HAS_RES) {
                    uint32_t rr = *(const uint32_t*)(res + (size_t)m * ostr + n);
                    float2 rf = __half22float2(*(__half2*)&rr);
                    v0 += rf.x; v1 += rf.y;
                }
                *(uint32_t*)(outh + (size_t)m * ostr + n) = pack2h(v0, v1);
            }
        }
    }
}

// ---------------- 4: fp16 tensor-core attention per (head, window) --------
#define APL (NTP * 40)                 // 4480 halves per plane
#define ATTN_SMEM_TC (3 * APL * 2)     // 26880 bytes
__global__ __launch_bounds__(224, 2) void k_attn_tc() {
    extern __shared__ __half asm_[];
    int head = blockIdx.x, bwin = blockIdx.y;
    int tid = threadIdx.x, lane = tid & 31, wid = tid >> 5;
    uint32_t sbase = smem_u32(asm_);

    // zero pad rows 98..111 of all 3 planes
    for (int i = tid; i < 3 * 280; i += 224) {
        int p = i / 280, r = i % 280;
        ((uint32_t*)(asm_ + p * APL + NT * 40))[r] = 0u;
    }

    // fill: 98 tokens x {q,k,v} x 4 x 16B cp.async copies
    for (int i = tid; i < 98 * 3 * 4; i += 224) {
        int chunk = i & 3;
        int idx = i >> 2;
        int n = idx / 3, sel = idx % 3;
        const __half* src = g_qkvh
            + (size_t)(bwin * NT + n) * (3 * Cz) + sel * Cz + head * HD + chunk * 8;
        uint32_t dst = sbase + (uint32_t)((sel * APL + n * 40 + chunk * 8) * 2);
        cpasync16(dst, src);
    }
    asm volatile("cp.async.commit_group;");
    asm volatile("cp.async.wait_group 0;");
    __syncthreads();

    // window boundary class -> precomputed bias+mask slab
    int wi = bwin % NW;
    int cls = ((wi / 144) == 3 ? 4 : 0) | (((wi / 12) % 12) == 11 ? 2 : 0)
            | ((wi % 12) == 11 ? 1 : 0);
    const float* Bm = g_bias + (size_t)(cls * HEADS + head) * NTP * NTP;

    uint32_t bQ = sbase, bK = sbase + APL * 2, bV = sbase + 2 * APL * 2;

    int wm = wid * 16;
    int aRow = wm + (lane & 15);
    int aCol = (lane >> 4) * 8;
    int bR = ((lane >> 4) << 3) + (lane & 7);
    int bCol = ((lane >> 3) & 1) * 8;
    int vR = ((lane >> 3) & 1) * 8 + (lane & 7);
    int vCol = (lane >> 4) * 8;

    float sacc[14][4];
    #pragma unroll
    for (int t = 0; t < 14; t++)
        #pragma unroll
        for (int e = 0; e < 4; e++) sacc[t][e] = 0.f;

    #pragma unroll
    for (int kk = 0; kk < 2; kk++) {
        int k0 = kk * 16;
        uint32_t aQ[4], bb[4];
        uint32_t aoff = (uint32_t)((aRow * 40 + k0 + aCol) * 2);
        ldsm4(bQ + aoff, aQ[0], aQ[1], aQ[2], aQ[3]);
        #pragma unroll
        for (int nt = 0; nt < 7; nt++) {
            uint32_t boff = (uint32_t)(((nt * 16 + bR) * 40 + k0 + bCol) * 2);
            ldsm4(bK + boff, bb[0], bb[1], bb[2], bb[3]);
            mma_f16(sacc[nt * 2 + 0], aQ, &bb[0]);
            mma_f16(sacc[nt * 2 + 1], aQ, &bb[2]);
        }
    }

    // precomputed bias/mask add (Q already scaled in qkv epilogue)
    int r0 = wm + (lane >> 2);
    int cbase = (lane & 3) * 2;
    #pragma unroll
    for (int h = 0; h < 2; h++) {
        int r = r0 + h * 8;
        const float2* brow = (const float2*)(Bm + (size_t)r * NTP);
        #pragma unroll
        for (int t = 0; t < 14; t++) {
            float2 bb = brow[t * 4 + (lane & 3)];
            sacc[t][h * 2 + 0] += bb.x;
            sacc[t][h * 2 + 1] += bb.y;
        }
    }

    // softmax in regs (row = quad of lanes)
    #pragma unroll
    for (int h = 0; h < 2; h++) {
        float mx = -1e30f;
        #pragma unroll
        for (int t = 0; t < 14; t++) {
            mx = fmaxf(mx, sacc[t][h * 2 + 0]);
            mx = fmaxf(mx, sacc[t][h * 2 + 1]);
        }
        mx = fmaxf(mx, __shfl_xor_sync(0xffffffffu, mx, 1));
        mx = fmaxf(mx, __shfl_xor_sync(0xffffffffu, mx, 2));
        float sum = 0.f;
        #pragma unroll
        for (int t = 0; t < 14; t++) {
            #pragma unroll
            for (int e = 0; e < 2; e++) {
                float v = __expf(sacc[t][h * 2 + e] - mx);
                sacc[t][h * 2 + e] = v;
                sum += v;
            }
        }
        sum += __shfl_xor_sync(0xffffffffu, sum, 1);
        sum += __shfl_xor_sync(0xffffffffu, sum, 2);
        float inv = 1.f / sum;
        #pragma unroll
        for (int t = 0; t < 14; t++) {
            sacc[t][h * 2 + 0] *= inv;
            sacc[t][h * 2 + 1] *= inv;
        }
    }

    // P @ V (fp16, 1 pass; V via trans-ldmatrix)
    float oacc[4][4];
    #pragma unroll
    for (int i = 0; i < 4; i++)
        #pragma unroll
        for (int e = 0; e < 4; e++) oacc[i][e] = 0.f;

    #pragma unroll
    for (int j = 0; j < 7; j++) {
        uint32_t aP[4];
        #pragma unroll
        for (int q = 0; q < 2; q++) {
            aP[q * 2 + 0] = pack2h(sacc[2 * j + q][0], sacc[2 * j + q][1]);
            aP[q * 2 + 1] = pack2h(sacc[2 * j + q][2], sacc[2 * j + q][3]);
        }
        #pragma unroll
        for (int dg = 0; dg < 2; dg++) {
            uint32_t bb[4];
            uint32_t boff = (uint32_t)(((j * 16 + vR) * 40 + vCol + dg * 16) * 2);
            ldsm4t(bV + boff, bb[0], bb[1], bb[2], bb[3]);
            mma_f16(oacc[dg * 2 + 0], aP, &bb[0]);
            mma_f16(oacc[dg * 2 + 1], aP, &bb[2]);
        }
    }

    #pragma unroll
    for (int h = 0; h < 2; h++) {
        int r = r0 + h * 8;
        if (r < NT) {
            size_t ob = ((size_t)bwin * NT + r) * Cz + head * HD;
            #pragma unroll
            for (int nt = 0; nt < 4; nt++) {
                int c = nt * 8 + cbase;
                *(uint32_t*)(g_aoh + ob + c) =
                    pack2h(oacc[nt][h * 2 + 0], oacc[nt][h * 2 + 1]);
            }
        }
    }
}

// ---------------- 6: reverse + residual + LN2 (warp per token) ------------
__global__ __launch_bounds__(256) void k_rev_res_ln2(
    const float* __restrict__ g2, const float* __restrict__ b2) {
    int t = blockIdx.x * 8 + (threadIdx.x >> 5);
    int lane = threadIdx.x & 31;
    int ft = map_token(t);
    const uint2* posrc = (const uint2*)(g_poh + (size_t)t * Cz);
    uint2 ph0 = posrc[lane], ph1 = posrc[lane + 32];
    float2 f01 = __half22float2(*(__half2*)&ph0.x), f23 = __half22float2(*(__half2*)&ph0.y);
    float2 f45 = __half22float2(*(__half2*)&ph1.x), f67 = __half22float2(*(__half2*)&ph1.y);
    const float4* xpsrc = (const float4*)(g_xp + (size_t)ft * Cz);
    float4 x0 = xpsrc[lane], x1 = xpsrc[lane + 32];
    float v[8] = { f01.x + x0.x, f01.y + x0.y, f23.x + x0.z, f23.y + x0.w,
                   f45.x + x1.x, f45.y + x1.y, f67.x + x1.z, f67.y + x1.w };
    // store trunk fp16
    size_t fbase = (size_t)ft * Cz;
    *(uint2*)(g_xrh + fbase + lane * 4) =
        make_uint2(pack2h(v[0], v[1]), pack2h(v[2], v[3]));
    *(uint2*)(g_xrh + fbase + 128 + lane * 4) =
        make_uint2(pack2h(v[4], v[5]), pack2h(v[6], v[7]));
    float m, inv;
    warpMeanVar8(v, m, inv);
    float4 g0 = ((const float4*)g2)[lane], g1 = ((const float4*)g2)[lane + 32];
    float4 b0 = ((const float4*)b2)[lane], b1 = ((const float4*)b2)[lane + 32];
    float gg[8] = { g0.x, g0.y, g0.z, g0.w, g1.x, g1.y, g1.z, g1.w };
    float bb[8] = { b0.x, b0.y, b0.z, b0.w, b1.x, b1.y, b1.z, b1.w };
    float o[8];
    #pragma unroll
    for (int i = 0; i < 8; i++) o[i] = (v[i] - m) * inv * gg[i] + bb[i];
    *(uint2*)(g_l2h + fbase + lane * 4) =
        make_uint2(pack2h(o[0], o[1]), pack2h(o[2], o[3]));
    *(uint2*)(g_l2h + fbase + 128 + lane * 4) =
        make_uint2(pack2h(o[4], o[5]), pack2h(o[6], o[7]));
}

// ---------------- 9: transpose out fp16 (B,D,H,W,C) -> fp32 (B,D,C,W,H) ----
__global__ void k_transpose_out(float* __restrict__ out) {
    __shared__ unsigned short tile[32][34];
    int bz = blockIdx.z;
    int bd = bz / Wz, w = bz % Wz;
    int h0 = blockIdx.x * 32, c0 = blockIdx.y * 32;
    #pragma unroll
    for (int j = 0; j < 32; j += 8) {
        int c = c0 + threadIdx.x;
        int h = h0 + threadIdx.y + j;
        if (h < Hz)
            tile[threadIdx.y + j][threadIdx.x] =
                *(const unsigned short*)(g_yh + (((size_t)bd * Hz + h) * Wz + w) * Cz + c);
    }
    __syncthreads();
    #pragma unroll
    for (int j = 0; j < 32; j += 8) {
        int h = h0 + threadIdx.x;
        int c = c0 + threadIdx.y + j;
        if (h < Hz) {
            unsigned short u = tile[threadIdx.x][threadIdx.y + j];
            out[(((size_t)bd * Cz + c) * Wz + w) * Hz + h] = __half2float(*(__half*)&u);
        }
    }
}

// ---------------- launch ----------------
extern "C" void kernel_launch(void* const* d_in, const int* in_sizes, int n_in,
                              void* d_out, int out_size) {
    const float* x      = (const float*)d_in[0];
    const float* n1g    = (const float*)d_in[1];
    const float* n1b    = (const float*)d_in[2];
    const float* qkv_w  = (const float*)d_in[3];
    const float* rpb    = (const float*)d_in[4];
    const float* proj_w = (const float*)d_in[5];
    const float* proj_b = (const float*)d_in[6];
    const float* n2g    = (const float*)d_in[7];
    const float* n2b    = (const float*)d_in[8];
    const float* fc1_w  = (const float*)d_in[9];
    const float* fc1_b  = (const float*)d_in[10];
    const float* fc2_w  = (const float*)d_in[11];
    const float* fc2_b  = (const float*)d_in[12];
    float* out = (float*)d_out;

    void* p;
    cudaGetSymbolAddress(&p, g_xwh);  __half* xwh = (__half*)p;
    cudaGetSymbolAddress(&p, g_qkvh); __half* qkvh = (__half*)p;
    cudaGetSymbolAddress(&p, g_aoh);  __half* aoh = (__half*)p;
    cudaGetSymbolAddress(&p, g_poh);  __half* poh = (__half*)p;
    cudaGetSymbolAddress(&p, g_xrh);  __half* xrh = (__half*)p;
    cudaGetSymbolAddress(&p, g_l2h);  __half* l2h = (__half*)p;
    cudaGetSymbolAddress(&p, g_hih);  __half* hih = (__half*)p;
    cudaGetSymbolAddress(&p, g_yh);   __half* yh  = (__half*)p;
    cudaGetSymbolAddress(&p, g_wqh);  __half* wqh = (__half*)p;
    cudaGetSymbolAddress(&p, g_wph);  __half* wph = (__half*)p;
    cudaGetSymbolAddress(&p, g_w1h);  __half* w1h = (__half*)p;
    cudaGetSymbolAddress(&p, g_w2h);  __half* w2h = (__half*)p;

    cudaFuncSetAttribute(k_attn_tc, cudaFuncAttributeMaxDynamicSharedMemorySize, ATTN_SMEM_TC);
    cudaFuncSetAttribute(k_gemm_h<0, false, false, true>, cudaFuncAttributeMaxDynamicSharedMemorySize, 4 * PLANE_B);
    cudaFuncSetAttribute(k_gemm_h<0, true, false, false>, cudaFuncAttributeMaxDynamicSharedMemorySize, 4 * PLANE_B);
    cudaFuncSetAttribute(k_gemm_h<1, true, false, false>, cudaFuncAttributeMaxDynamicSharedMemorySize, 4 * PLANE_B);
    cudaFuncSetAttribute(k_gemm_h<0, true, true, false>,  cudaFuncAttributeMaxDynamicSharedMemorySize, 4 * PLANE_B);

    dim3 tb(32, 8);
    dim3 tg(3, 8, Bz * Dz * Wz);

    // 0. fused weight convert + bias table (tiny)
    k_wcvt_all<<<(NWQ + NWP + NW1 + NW2 + 255) / 256, 256>>>(qkv_w, proj_w, fc1_w, fc2_w);
    k_bias<<<64, 256>>>(rpb);
    // 1. transpose in
    k_transpose_in<<<tg, tb>>>(x);
    // 2. LN1 + shift + partition (warp per token, fp16 out)
    k_ln_part<<<TOK / 8, 256>>>(n1g, n1b);
    // 3. qkv GEMM (1-pass fp16, N=768, Q pre-scaled)
    k_gemm_h<0, false, false, true><<<dim3(6, TOK / 128), 256, 4 * PLANE_B>>>(
        xwh, wqh, nullptr, nullptr, qkvh, TOK, 3 * Cz, Cz, 3 * Cz);
    // 4. attention (fp16 tensor cores, precomputed bias)
    k_attn_tc<<<dim3(HEADS, BW), 224, ATTN_SMEM_TC>>>();
    // 5. proj GEMM -> fp16 plane
    k_gemm_h<0, true, false, false><<<dim3(Cz / 128, TOK / 128), 256, 4 * PLANE_B>>>(
        aoh, wph, proj_b, nullptr, poh, TOK, Cz, Cz, Cz);
    // 6. reverse + residual + LN2 (warp per token; fp16 trunk out)
    k_rev_res_ln2<<<TOK / 8, 256>>>(n2g, n2b);
    // 7. fc1 GEMM + GELU -> fp16 plane
    k_gemm_h<1, true, false, false><<<dim3(HID / 128, TOK / 128), 256, 4 * PLANE_B>>>(
        l2h, w1h, fc1_b, nullptr, hih, TOK, HID, Cz, HID);
    // 8. fc2 GEMM + bias + fp16 residual -> fp16 y
    k_gemm_h<0, true, true, false><<<dim3(Cz / 128, TOK / 128), 256, 4 * PLANE_B>>>(
        hih, w2h, fc2_b, xrh, yh, TOK, Cz, HID, Cz);
    // 9. transpose out (fp16 -> fp32)
    k_transpose_out<<<tg, tb>>>(out);
}

// round 16
// speedup vs baseline: 1.7280x; 1.0131x over previous
#include <cuda_runtime.h>
#include <cuda_fp16.h>
#include <math.h>
#include <stdint.h>

// ---------------- problem constants ----------------
#define Bz 2
#define Dz 8
#define Cz 256
#define Wz 84
#define Hz 84
#define HEADS 8
#define HD 32
#define NT 98            // tokens per window (2*7*7)
#define NTP 112          // padded to 7 x 16
#define NW 576           // windows per batch (4*12*12)
#define BW (Bz*NW)       // 1152 window-batches
#define TOK (BW*NT)      // 112896 tokens
#define HID 1024

// ---------------- scratch (device globals; allocation-free) ----------------
__device__ __align__(256) float g_bias[8 * HEADS * NTP * NTP];  // [cls][head][r][c]
// fp16 activation planes
__device__ __align__(256) __half g_xph[(size_t)TOK*Cz];   // shortcut (B,D,H,W,C)
__device__ __align__(256) __half g_xwh[(size_t)TOK*Cz];
__device__ __align__(256) __half g_qkvh[(size_t)TOK*3*Cz];
__device__ __align__(256) __half g_aoh[(size_t)TOK*Cz];
__device__ __align__(256) __half g_poh[(size_t)TOK*Cz];   // proj out (windowed order)
__device__ __align__(256) __half g_xrh[(size_t)TOK*Cz];   // residual trunk (B,D,H,W,C)
__device__ __align__(256) __half g_l2h[(size_t)TOK*Cz];
__device__ __align__(256) __half g_hih[(size_t)TOK*HID];
__device__ __align__(256) __half g_yh [(size_t)TOK*Cz];   // final trunk (B,D,H,W,C)
// fp16 weights
__device__ __align__(256) __half g_wqh[3*Cz*Cz];
__device__ __align__(256) __half g_wph[Cz*Cz];
__device__ __align__(256) __half g_w1h[HID*Cz];
__device__ __align__(256) __half g_w2h[Cz*HID];

// ---------------- helpers ----------------
__device__ __forceinline__ uint32_t smem_u32(const void* p) {
    uint32_t a;
    asm("{ .reg .u64 t; cvta.to.shared.u64 t, %1; cvt.u32.u64 %0, t; }" : "=r"(a) : "l"(p));
    return a;
}
__device__ __forceinline__ uint32_t pack2h(float x, float y) {
    __half2 t = __floats2half2_rn(x, y);
    return *(uint32_t*)&t;
}
__device__ __forceinline__ void ldsm4(uint32_t addr, uint32_t& r0, uint32_t& r1,
                                      uint32_t& r2, uint32_t& r3) {
    asm volatile("ldmatrix.sync.aligned.m8n8.x4.shared.b16 {%0,%1,%2,%3}, [%4];"
                 : "=r"(r0), "=r"(r1), "=r"(r2), "=r"(r3) : "r"(addr));
}
__device__ __forceinline__ void ldsm4t(uint32_t addr, uint32_t& r0, uint32_t& r1,
                                       uint32_t& r2, uint32_t& r3) {
    asm volatile("ldmatrix.sync.aligned.m8n8.x4.trans.shared.b16 {%0,%1,%2,%3}, [%4];"
                 : "=r"(r0), "=r"(r1), "=r"(r2), "=r"(r3) : "r"(addr));
}
__device__ __forceinline__ void mma_f16(float* d, const uint32_t* a, const uint32_t* b) {
    asm volatile(
        "mma.sync.aligned.m16n8k16.row.col.f32.f16.f16.f32 "
        "{%0,%1,%2,%3}, {%4,%5,%6,%7}, {%8,%9}, {%0,%1,%2,%3};"
        : "+f"(d[0]), "+f"(d[1]), "+f"(d[2]), "+f"(d[3])
        : "r"(a[0]), "r"(a[1]), "r"(a[2]), "r"(a[3]), "r"(b[0]), "r"(b[1]));
}
__device__ __forceinline__ void cpasync16(uint32_t dst, const void* src) {
    asm volatile("cp.async.cg.shared.global [%0], [%1], 16;" :: "r"(dst), "l"(src));
}

// ---------------- 0a: fused weight convert fp32 -> fp16 (all 4 weights) ---
#define NWQ (3*Cz*Cz)
#define NWP (Cz*Cz)
#define NW1 (HID*Cz)
#define NW2 (Cz*HID)
__global__ void k_wcvt_all(const float* __restrict__ wq, const float* __restrict__ wp,
                           const float* __restrict__ w1, const float* __restrict__ w2) {
    int i = blockIdx.x * 256 + threadIdx.x;
    if (i < NWQ) { g_wqh[i] = __float2half(wq[i]); return; }
    i -= NWQ;
    if (i < NWP) { g_wph[i] = __float2half(wp[i]); return; }
    i -= NWP;
    if (i < NW1) { g_w1h[i] = __float2half(w1[i]); return; }
    i -= NW1;
    if (i < NW2) { g_w2h[i] = __float2half(w2[i]); }
}

// ---------------- 0b: precompute bias+mask per (class, head) ----------------
__global__ void k_bias(const float* __restrict__ rpb) {
    int blk = blockIdx.x;          // cls*8 + head
    int cls = blk >> 3, head = blk & 7;
    float* outp = g_bias + (size_t)blk * NTP * NTP;
    for (int i = threadIdx.x; i < NTP * NTP; i += 256) {
        int r = i / NTP, c = i % NTP;
        float v;
        if (r < NT && c < NT) {
            int dr = r / 49, hr = (r % 49) / 7, wr = r % 7;
            int dc = c / 49, hc = (c % 49) / 7, wc = c % 7;
            int idx = (dr - dc + 1) * 169 + (hr - hc + 6) * 13 + (wr - wc + 6);
            int rgr = ((cls & 4) ? (dr == 0 ? 1 : 2) : 0) * 9
                    + ((cls & 2) ? (hr < 4 ? 1 : 2) : 0) * 3
                    + ((cls & 1) ? (wr < 4 ? 1 : 2) : 0);
            int rgc = ((cls & 4) ? (dc == 0 ? 1 : 2) : 0) * 9
                    + ((cls & 2) ? (hc < 4 ? 1 : 2) : 0) * 3
                    + ((cls & 1) ? (wc < 4 ? 1 : 2) : 0);
            v = rpb[idx * HEADS + head] + (rgr != rgc ? -100.f : 0.f);
        } else {
            v = -30000.f;
        }
        outp[i] = v;
    }
}

// ---------------- 1: transpose in fp32 (B,D,C,W,H) -> fp16 (B,D,H,W,C) -----
__global__ void k_transpose_in(const float* __restrict__ x) {
    __shared__ unsigned short tile[32][34];
    int bz = blockIdx.z;
    int bd = bz / Wz, w = bz % Wz;
    int h0 = blockIdx.x * 32, c0 = blockIdx.y * 32;
    #pragma unroll
    for (int j = 0; j < 32; j += 8) {
        int c = c0 + threadIdx.y + j;
        int h = h0 + threadIdx.x;
        if (h < Hz) {
            __half hv = __float2half(x[(((size_t)bd * Cz + c) * Wz + w) * Hz + h]);
            tile[threadIdx.y + j][threadIdx.x] = *(unsigned short*)&hv;
        }
    }
    __syncthreads();
    #pragma unroll
    for (int j = 0; j < 32; j += 8) {
        int c = c0 + threadIdx.x;
        int h = h0 + threadIdx.y + j;
        if (h < Hz)
            *(unsigned short*)(g_xph + (((size_t)bd * Hz + h) * Wz + w) * Cz + c) =
                tile[threadIdx.x][threadIdx.y + j];
    }
}

__device__ __forceinline__ int map_token(int t) {
    int b   = t / (NW * NT);
    int rem = t % (NW * NT);
    int wi = rem / NT, n = rem % NT;
    int d2 = wi / 144, h2 = (wi / 12) % 12, w2 = wi % 12;
    int dd = n / 49, r = n % 49, hh = r / 7, ww = r % 7;
    int d = d2 * 2 + dd, h = h2 * 7 + hh, w = w2 * 7 + ww;
    int ds = (d + 1) & 7;
    int hs = h + 3; if (hs >= Hz) hs -= Hz;
    int ws = w + 3; if (ws >= Wz) ws -= Wz;
    return ((b * Dz + ds) * Hz + hs) * Wz + ws;
}

// warp-level mean/invstd over 8 regs/thread (256 channels per warp)
__device__ __forceinline__ void warpMeanVar8(const float* v, float& mean, float& invstd) {
    float s1 = 0.f, s2 = 0.f;
    #pragma unroll
    for (int i = 0; i < 8; i++) { s1 += v[i]; s2 += v[i] * v[i]; }
    #pragma unroll
    for (int o = 16; o; o >>= 1) {
        s1 += __shfl_xor_sync(0xffffffffu, s1, o);
        s2 += __shfl_xor_sync(0xffffffffu, s2, o);
    }
    float m = s1 * (1.f / Cz);
    float q = s2 * (1.f / Cz) - m * m;
    mean = m;
    invstd = rsqrtf(q + 1e-5f);
}

__device__ __forceinline__ void load8h(const __half* base, int lane, float* v) {
    const uint2* p = (const uint2*)base;
    uint2 h0 = p[lane], h1 = p[lane + 32];
    float2 a = __half22float2(*(__half2*)&h0.x), b = __half22float2(*(__half2*)&h0.y);
    float2 c = __half22float2(*(__half2*)&h1.x), d = __half22float2(*(__half2*)&h1.y);
    v[0] = a.x; v[1] = a.y; v[2] = b.x; v[3] = b.y;
    v[4] = c.x; v[5] = c.y; v[6] = d.x; v[7] = d.y;
}

// ---------------- 2: LN1 + shift + partition (warp per token) -------------
__global__ __launch_bounds__(256) void k_ln_part(
    const float* __restrict__ g, const float* __restrict__ bta) {
    int t = blockIdx.x * 8 + (threadIdx.x >> 5);
    int lane = threadIdx.x & 31;
    int srct = map_token(t);
    float v[8];
    load8h(g_xph + (size_t)srct * Cz, lane, v);
    float m, inv;
    warpMeanVar8(v, m, inv);
    float4 g0 = ((const float4*)g)[lane],   g1 = ((const float4*)g)[lane + 32];
    float4 b0 = ((const float4*)bta)[lane], b1 = ((const float4*)bta)[lane + 32];
    float gg[8] = { g0.x, g0.y, g0.z, g0.w, g1.x, g1.y, g1.z, g1.w };
    float bb[8] = { b0.x, b0.y, b0.z, b0.w, b1.x, b1.y, b1.z, b1.w };
    float o[8];
    #pragma unroll
    for (int i = 0; i < 8; i++) o[i] = (v[i] - m) * inv * gg[i] + bb[i];
    size_t base = (size_t)t * Cz;
    *(uint2*)(g_xwh + base + lane * 4) =
        make_uint2(pack2h(o[0], o[1]), pack2h(o[2], o[3]));
    *(uint2*)(g_xwh + base + 128 + lane * 4) =
        make_uint2(pack2h(o[4], o[5]), pack2h(o[6], o[7]));
}

// ---------------- GEMM (1-pass fp16, BK=64): out = A[M,K] @ Wt[N,K]^T -----
// Output always fp16 plane. Optional fp16 residual. QSCALE scales n < Cz.
#define PADK 72                          // 64 + 8 pad; 144B row stride, conflict-free
#define PLANE_B (128 * PADK * 2)         // 18432 bytes
template <int ACT, bool HAS_BIAS, bool HAS_RES, bool QSCALE>
__global__ __launch_bounds__(256, 2) void k_gemm_h(
    const __half* __restrict__ Ah, const __half* __restrict__ Bh,
    const float* __restrict__ bias, const __half* __restrict__ res,
    __half* __restrict__ outh,
    int M, int N, int K, int ostr) {
    extern __shared__ __align__(16) unsigned char dsm[];
    const uint32_t STB = 2 * PLANE_B;
    uint32_t sbase = smem_u32(dsm);
    int tid = threadIdx.x, lane = tid & 31, wid = tid >> 5;
    int bm = blockIdx.y * 128, bn = blockIdx.x * 128;
    int wm = (wid & 1) * 64, wn = (wid >> 1) * 32;

    int aRow = wm + (lane & 15);
    int aCol = (lane >> 4) * 8;
    int bRow = wn + ((lane >> 4) << 3) + (lane & 7);
    int bCol = ((lane >> 3) & 1) * 8;

    float acc[4][4][4];
    #pragma unroll
    for (int i = 0; i < 4; i++)
        #pragma unroll
        for (int j = 0; j < 4; j++)
            #pragma unroll
            for (int c = 0; c < 4; c++) acc[i][j][c] = 0.f;

    const int nChunks = K >> 6;

    #define ISSUE(ch, s) do {                                                   \
        int k0_ = (ch) << 6;                                                    \
        uint32_t sb_ = sbase + (s) * STB;                                       \
        _Pragma("unroll")                                                       \
        for (int q_ = 0; q_ < 4; q_++) {                                        \
            int j_ = q_ * 256 + tid;                                            \
            int row_ = j_ >> 3, c8_ = (j_ & 7) * 8;                             \
            uint32_t so_ = (uint32_t)((row_ * PADK + c8_) * 2);                 \
            cpasync16(sb_ + so_, Ah + (size_t)(bm + row_) * K + k0_ + c8_);     \
            cpasync16(sb_ + PLANE_B + so_,                                      \
                      Bh + (size_t)(bn + row_) * K + k0_ + c8_);                \
        }                                                                       \
        asm volatile("cp.async.commit_group;");                                 \
    } while (0)

    ISSUE(0, 0);
    for (int ch = 0; ch < nChunks; ch++) {
        int s = ch & 1;
        if (ch + 1 < nChunks) {
            ISSUE(ch + 1, (ch + 1) & 1);
            asm volatile("cp.async.wait_group 1;");
        } else {
            asm volatile("cp.async.wait_group 0;");
        }
        __syncthreads();

        uint32_t baseA = sbase + s * STB;
        uint32_t baseB = baseA + PLANE_B;

        #pragma unroll
        for (int kk = 0; kk < 4; kk++) {
            int k0 = kk * 16;
            uint32_t aH[4][4], bb[8];
            #pragma unroll
            for (int mi = 0; mi < 4; mi++) {
                uint32_t off = (uint32_t)(((aRow + mi * 16) * PADK + k0 + aCol) * 2);
                ldsm4(baseA + off, aH[mi][0], aH[mi][1], aH[mi][2], aH[mi][3]);
            }
            #pragma unroll
            for (int p = 0; p < 2; p++) {
                uint32_t off = (uint32_t)(((bRow + p * 16) * PADK + k0 + bCol) * 2);
                ldsm4(baseB + off, bb[p * 4 + 0], bb[p * 4 + 1], bb[p * 4 + 2], bb[p * 4 + 3]);
            }
            #pragma unroll
            for (int mi = 0; mi < 4; mi++)
                #pragma unroll
                for (int ni = 0; ni < 4; ni++)
                    mma_f16(acc[mi][ni], aH[mi], &bb[ni * 2]);
        }
        __syncthreads();
    }
    #undef ISSUE

    int orow = lane >> 2, ocol = (lane & 3) * 2;
    #pragma unroll
    for (int mi = 0; mi < 4; mi++) {
        int m0 = bm + wm + mi * 16;
        #pragma unroll
        for (int ni = 0; ni < 4; ni++) {
            int n = bn + wn + ni * 8 + ocol;
            float bi0 = 0.f, bi1 = 0.f;
            if (HAS_BIAS) { bi0 = bias[n]; bi1 = bias[n + 1]; }
            float sc = (QSCALE && n < Cz) ? 0.17677669529663687f : 1.f;
            #pragma unroll
            for (int half = 0; half < 2; half++) {
                int m = m0 + orow + half * 8;
                float v0 = acc[mi][ni][half * 2 + 0] + bi0;
                float v1 = acc[mi][ni][half * 2 + 1] + bi1;
                if (QSCALE) { v0 *= sc; v1 *= sc; }
                if (ACT == 1) {
                    v0 = 0.5f * v0 * (1.f + erff(v0 * 0.70710678118654752f));
                    v1 = 0.5f * v1 * (1.f + erff(v1 * 0.70710678118654752f));
                }
                if (HAS_RES) {
                    uint32_t rr = *(const uint32_t*)(res + (size_t)m * ostr + n);
                    float2 rf = __half22float2(*(__half2*)&rr);
                    v0 += rf.x; v1 += rf.y;
                }
                *(uint32_t*)(outh + (size_t)m * ostr + n) = pack2h(v0, v1);
            }
        }
    }
}

// ---------------- 4: fp16 tensor-core attention per (head, window) --------
#define APL (NTP * 40)                 // 4480 halves per plane
#define ATTN_SMEM_TC (3 * APL * 2)     // 26880 bytes
__global__ __launch_bounds__(224, 2) void k_attn_tc() {
    extern __shared__ __half asm_[];
    int head = blockIdx.x, bwin = blockIdx.y;
    int tid = threadIdx.x, lane = tid & 31, wid = tid >> 5;
    uint32_t sbase = smem_u32(asm_);

    // zero pad rows 98..111 of all 3 planes
    for (int i = tid; i < 3 * 280; i += 224) {
        int p = i / 280, r = i % 280;
        ((uint32_t*)(asm_ + p * APL + NT * 40))[r] = 0u;
    }

    // fill: 98 tokens x {q,k,v} x 4 x 16B cp.async copies
    for (int i = tid; i < 98 * 3 * 4; i += 224) {
        int chunk = i & 3;
        int idx = i >> 2;
        int n = idx / 3, sel = idx % 3;
        const __half* src = g_qkvh
            + (size_t)(bwin * NT + n) * (3 * Cz) + sel * Cz + head * HD + chunk * 8;
        uint32_t dst = sbase + (uint32_t)((sel * APL + n * 40 + chunk * 8) * 2);
        cpasync16(dst, src);
    }
    asm volatile("cp.async.commit_group;");
    asm volatile("cp.async.wait_group 0;");
    __syncthreads();

    // window boundary class -> precomputed bias+mask slab
    int wi = bwin % NW;
    int cls = ((wi / 144) == 3 ? 4 : 0) | (((wi / 12) % 12) == 11 ? 2 : 0)
            | ((wi % 12) == 11 ? 1 : 0);
    const float* Bm = g_bias + (size_t)(cls * HEADS + head) * NTP * NTP;

    uint32_t bQ = sbase, bK = sbase + APL * 2, bV = sbase + 2 * APL * 2;

    int wm = wid * 16;
    int aRow = wm + (lane & 15);
    int aCol = (lane >> 4) * 8;
    int bR = ((lane >> 4) << 3) + (lane & 7);
    int bCol = ((lane >> 3) & 1) * 8;
    int vR = ((lane >> 3) & 1) * 8 + (lane & 7);
    int vCol = (lane >> 4) * 8;

    float sacc[14][4];
    #pragma unroll
    for (int t = 0; t < 14; t++)
        #pragma unroll
        for (int e = 0; e < 4; e++) sacc[t][e] = 0.f;

    #pragma unroll
    for (int kk = 0; kk < 2; kk++) {
        int k0 = kk * 16;
        uint32_t aQ[4], bb[4];
        uint32_t aoff = (uint32_t)((aRow * 40 + k0 + aCol) * 2);
        ldsm4(bQ + aoff, aQ[0], aQ[1], aQ[2], aQ[3]);
        #pragma unroll
        for (int nt = 0; nt < 7; nt++) {
            uint32_t boff = (uint32_t)(((nt * 16 + bR) * 40 + k0 + bCol) * 2);
            ldsm4(bK + boff, bb[0], bb[1], bb[2], bb[3]);
            mma_f16(sacc[nt * 2 + 0], aQ, &bb[0]);
            mma_f16(sacc[nt * 2 + 1], aQ, &bb[2]);
        }
    }

    // precomputed bias/mask add (Q already scaled in qkv epilogue)
    int r0 = wm + (lane >> 2);
    int cbase = (lane & 3) * 2;
    #pragma unroll
    for (int h = 0; h < 2; h++) {
        int r = r0 + h * 8;
        const float2* brow = (const float2*)(Bm + (size_t)r * NTP);
        #pragma unroll
        for (int t = 0; t < 14; t++) {
            float2 bb = brow[t * 4 + (lane & 3)];
            sacc[t][h * 2 + 0] += bb.x;
            sacc[t][h * 2 + 1] += bb.y;
        }
    }

    // softmax in regs (row = quad of lanes)
    #pragma unroll
    for (int h = 0; h < 2; h++) {
        float mx = -1e30f;
        #pragma unroll
        for (int t = 0; t < 14; t++) {
            mx = fmaxf(mx, sacc[t][h * 2 + 0]);
            mx = fmaxf(mx, sacc[t][h * 2 + 1]);
        }
        mx = fmaxf(mx, __shfl_xor_sync(0xffffffffu, mx, 1));
        mx = fmaxf(mx, __shfl_xor_sync(0xffffffffu, mx, 2));
        float sum = 0.f;
        #pragma unroll
        for (int t = 0; t < 14; t++) {
            #pragma unroll
            for (int e = 0; e < 2; e++) {
                float v = __expf(sacc[t][h * 2 + e] - mx);
                sacc[t][h * 2 + e] = v;
                sum += v;
            }
        }
        sum += __shfl_xor_sync(0xffffffffu, sum, 1);
        sum += __shfl_xor_sync(0xffffffffu, sum, 2);
        float inv = 1.f / sum;
        #pragma unroll
        for (int t = 0; t < 14; t++) {
            sacc[t][h * 2 + 0] *= inv;
            sacc[t][h * 2 + 1] *= inv;
        }
    }

    // P @ V (fp16, 1 pass; V via trans-ldmatrix)
    float oacc[4][4];
    #pragma unroll
    for (int i = 0; i < 4; i++)
        #pragma unroll
        for (int e = 0; e < 4; e++) oacc[i][e] = 0.f;

    #pragma unroll
    for (int j = 0; j < 7; j++) {
        uint32_t aP[4];
        #pragma unroll
        for (int q = 0; q < 2; q++) {
            aP[q * 2 + 0] = pack2h(sacc[2 * j + q][0], sacc[2 * j + q][1]);
            aP[q * 2 + 1] = pack2h(sacc[2 * j + q][2], sacc[2 * j + q][3]);
        }
        #pragma unroll
        for (int dg = 0; dg < 2; dg++) {
            uint32_t bb[4];
            uint32_t boff = (uint32_t)(((j * 16 + vR) * 40 + vCol + dg * 16) * 2);
            ldsm4t(bV + boff, bb[0], bb[1], bb[2], bb[3]);
            mma_f16(oacc[dg * 2 + 0], aP, &bb[0]);
            mma_f16(oacc[dg * 2 + 1], aP, &bb[2]);
        }
    }

    #pragma unroll
    for (int h = 0; h < 2; h++) {
        int r = r0 + h * 8;
        if (r < NT) {
            size_t ob = ((size_t)bwin * NT + r) * Cz + head * HD;
            #pragma unroll
            for (int nt = 0; nt < 4; nt++) {
                int c = nt * 8 + cbase;
                *(uint32_t*)(g_aoh + ob + c) =
                    pack2h(oacc[nt][h * 2 + 0], oacc[nt][h * 2 + 1]);
            }
        }
    }
}

// ---------------- 6: reverse + residual + LN2 (warp per token) ------------
__global__ __launch_bounds__(256) void k_rev_res_ln2(
    const float* __restrict__ g2, const float* __restrict__ b2) {
    int t = blockIdx.x * 8 + (threadIdx.x >> 5);
    int lane = threadIdx.x & 31;
    int ft = map_token(t);
    float pv[8], xv[8];
    load8h(g_poh + (size_t)t * Cz, lane, pv);
    load8h(g_xph + (size_t)ft * Cz, lane, xv);
    float v[8];
    #pragma unroll
    for (int i = 0; i < 8; i++) v[i] = pv[i] + xv[i];
    size_t fbase = (size_t)ft * Cz;
    *(uint2*)(g_xrh + fbase + lane * 4) =
        make_uint2(pack2h(v[0], v[1]), pack2h(v[2], v[3]));
    *(uint2*)(g_xrh + fbase + 128 + lane * 4) =
        make_uint2(pack2h(v[4], v[5]), pack2h(v[6], v[7]));
    float m, inv;
    warpMeanVar8(v, m, inv);
    float4 g0 = ((const float4*)g2)[lane], g1 = ((const float4*)g2)[lane + 32];
    float4 b0 = ((const float4*)b2)[lane], b1 = ((const float4*)b2)[lane + 32];
    float gg[8] = { g0.x, g0.y, g0.z, g0.w, g1.x, g1.y, g1.z, g1.w };
    float bb[8] = { b0.x, b0.y, b0.z, b0.w, b1.x, b1.y, b1.z, b1.w };
    float o[8];
    #pragma unroll
    for (int i = 0; i < 8; i++) o[i] = (v[i] - m) * inv * gg[i] + bb[i];
    *(uint2*)(g_l2h + fbase + lane * 4) =
        make_uint2(pack2h(o[0], o[1]), pack2h(o[2], o[3]));
    *(uint2*)(g_l2h + fbase + 128 + lane * 4) =
        make_uint2(pack2h(o[4], o[5]), pack2h(o[6], o[7]));
}

// ---------------- 9: transpose out fp16 (B,D,H,W,C) -> fp32 (B,D,C,W,H) ----
__global__ void k_transpose_out(float* __restrict__ out) {
    __shared__ unsigned short tile[32][34];
    int bz = blockIdx.z;
    int bd = bz / Wz, w = bz % Wz;
    int h0 = blockIdx.x * 32, c0 = blockIdx.y * 32;
    #pragma unroll
    for (int j = 0; j < 32; j += 8) {
        int c = c0 + threadIdx.x;
        int h = h0 + threadIdx.y + j;
        if (h < Hz)
            tile[threadIdx.y + j][threadIdx.x] =
                *(const unsigned short*)(g_yh + (((size_t)bd * Hz + h) * Wz + w) * Cz + c);
    }
    __syncthreads();
    #pragma unroll
    for (int j = 0; j < 32; j += 8) {
        int h = h0 + threadIdx.x;
        int c = c0 + threadIdx.y + j;
        if (h < Hz) {
            unsigned short u = tile[threadIdx.x][threadIdx.y + j];
            out[(((size_t)bd * Cz + c) * Wz + w) * Hz + h] = __half2float(*(__half*)&u);
        }
    }
}

// ---------------- launch ----------------
extern "C" void kernel_launch(void* const* d_in, const int* in_sizes, int n_in,
                              void* d_out, int out_size) {
    const float* x      = (const float*)d_in[0];
    const float* n1g    = (const float*)d_in[1];
    const float* n1b    = (const float*)d_in[2];
    const float* qkv_w  = (const float*)d_in[3];
    const float* rpb    = (const float*)d_in[4];
    const float* proj_w = (const float*)d_in[5];
    const float* proj_b = (const float*)d_in[6];
    const float* n2g    = (const float*)d_in[7];
    const float* n2b    = (const float*)d_in[8];
    const float* fc1_w  = (const float*)d_in[9];
    const float* fc1_b  = (const float*)d_in[10];
    const float* fc2_w  = (const float*)d_in[11];
    const float* fc2_b  = (const float*)d_in[12];
    float* out = (float*)d_out;

    void* p;
    cudaGetSymbolAddress(&p, g_xwh);  __half* xwh = (__half*)p;
    cudaGetSymbolAddress(&p, g_qkvh); __half* qkvh = (__half*)p;
    cudaGetSymbolAddress(&p, g_aoh);  __half* aoh = (__half*)p;
    cudaGetSymbolAddress(&p, g_poh);  __half* poh = (__half*)p;
    cudaGetSymbolAddress(&p, g_xrh);  __half* xrh = (__half*)p;
    cudaGetSymbolAddress(&p, g_l2h);  __half* l2h = (__half*)p;
    cudaGetSymbolAddress(&p, g_hih);  __half* hih = (__half*)p;
    cudaGetSymbolAddress(&p, g_yh);   __half* yh  = (__half*)p;
    cudaGetSymbolAddress(&p, g_wqh);  __half* wqh = (__half*)p;
    cudaGetSymbolAddress(&p, g_wph);  __half* wph = (__half*)p;
    cudaGetSymbolAddress(&p, g_w1h);  __half* w1h = (__half*)p;
    cudaGetSymbolAddress(&p, g_w2h);  __half* w2h = (__half*)p;

    cudaFuncSetAttribute(k_attn_tc, cudaFuncAttributeMaxDynamicSharedMemorySize, ATTN_SMEM_TC);
    cudaFuncSetAttribute(k_gemm_h<0, false, false, true>, cudaFuncAttributeMaxDynamicSharedMemorySize, 4 * PLANE_B);
    cudaFuncSetAttribute(k_gemm_h<0, true, false, false>, cudaFuncAttributeMaxDynamicSharedMemorySize, 4 * PLANE_B);
    cudaFuncSetAttribute(k_gemm_h<1, true, false, false>, cudaFuncAttributeMaxDynamicSharedMemorySize, 4 * PLANE_B);
    cudaFuncSetAttribute(k_gemm_h<0, true, true, false>,  cudaFuncAttributeMaxDynamicSharedMemorySize, 4 * PLANE_B);

    dim3 tb(32, 8);
    dim3 tg(3, 8, Bz * Dz * Wz);

    // 0. fused weight convert + bias table (tiny)
    k_wcvt_all<<<(NWQ + NWP + NW1 + NW2 + 255) / 256, 256>>>(qkv_w, proj_w, fc1_w, fc2_w);
    k_bias<<<64, 256>>>(rpb);
    // 1. transpose in (fp32 -> fp16 shortcut plane)
    k_transpose_in<<<tg, tb>>>(x);
    // 2. LN1 + shift + partition (warp per token, fp16 out)
    k_ln_part<<<TOK / 8, 256>>>(n1g, n1b);
    // 3. qkv GEMM (1-pass fp16, N=768, Q pre-scaled)
    k_gemm_h<0, false, false, true><<<dim3(6, TOK / 128), 256, 4 * PLANE_B>>>(
        xwh, wqh, nullptr, nullptr, qkvh, TOK, 3 * Cz, Cz, 3 * Cz);
    // 4. attention (fp16 tensor cores, precomputed bias)
    k_attn_tc<<<dim3(HEADS, BW), 224, ATTN_SMEM_TC>>>();
    // 5. proj GEMM -> fp16 plane
    k_gemm_h<0, true, false, false><<<dim3(Cz / 128, TOK / 128), 256, 4 * PLANE_B>>>(
        aoh, wph, proj_b, nullptr, poh, TOK, Cz, Cz, Cz);
    // 6. reverse + residual + LN2 (warp per token; fp16 trunk out)
    k_rev_res_ln2<<<TOK / 8, 256>>>(n2g, n2b);
    // 7. fc1 GEMM + GELU -> fp16 plane
    k_gemm_h<1, true, false, false><<<dim3(HID / 128, TOK / 128), 256, 4 * PLANE_B>>>(
        l2h, w1h, fc1_b, nullptr, hih, TOK, HID, Cz, HID);
    // 8. fc2 GEMM + bias + fp16 residual -> fp16 y
    k_gemm_h<0, true, true, false><<<dim3(Cz / 128, TOK / 128), 256, 4 * PLANE_B>>>(
        hih, w2h, fc2_b, xrh, yh, TOK, Cz, HID, Cz);
    // 9. transpose out (fp16 -> fp32)
    k_transpose_out<<<tg, tb>>>(out);
}